// round 13
// baseline (speedup 1.0000x reference)
#include <cuda_runtime.h>
#include <cuda_fp16.h>
#include <cstdint>

#define Nn 100000
#define Ee 600000
#define EPSBN 1e-5f
#define SLOPE 0.2f

// ---------------- scratch ----------------
__device__ float g_HC[(size_t)Nn * 640];
__device__ float g_z[(size_t)Nn * 128];
__device__ float g_t[(size_t)Nn * 256];   // used as __half[Nn*256] for FF hidden
__device__ float g_y[(size_t)Nn * 128];
__device__ float g_el[(size_t)Nn * 16];
__device__ float g_er[(size_t)Nn * 16];
__device__ float g_bnsum[8 * 256];
__device__ int   g_deg[Nn];
__device__ int   g_scan[Nn];
__device__ int   g_bsum[128];
__device__ int   g_rowptr[Nn + 1];
__device__ int   g_cursor[Nn];
__device__ int   g_srcs[Ee];
__device__ float g_W[425984];

__device__ __forceinline__ float to_tf32(float x) {
    float r;
    asm("cvt.rna.tf32.f32 %0, %1;" : "=f"(r) : "f"(x));
    return r;
}
__device__ __forceinline__ uint32_t smem_to_u32(const void* p) {
    uint32_t a;
    asm("{ .reg .u64 t; cvta.to.shared.u64 t, %1; cvt.u32.u64 %0, t; }" : "=r"(a) : "l"(p));
    return a;
}
__device__ __forceinline__ void cp16(uint32_t dst, const void* src, bool ok) {
    int sz = ok ? 16 : 0;
    asm volatile("cp.async.cg.shared.global [%0], [%1], 16, %2;"
                 :: "r"(dst), "l"(src), "r"(sz) : "memory");
}
#define CP_COMMIT() asm volatile("cp.async.commit_group;" ::: "memory")
#define CP_WAIT2() asm volatile("cp.async.wait_group 2;" ::: "memory")

#define MMA_TF32(d, av, bv)                                               \
    asm volatile(                                                         \
        "mma.sync.aligned.m16n8k8.row.col.f32.tf32.tf32.f32 "             \
        "{%0,%1,%2,%3},{%4,%5,%6,%7},{%8,%9},{%0,%1,%2,%3};"              \
        : "+f"((d)[0]), "+f"((d)[1]), "+f"((d)[2]), "+f"((d)[3])          \
        : "r"((av)[0]), "r"((av)[1]), "r"((av)[2]), "r"((av)[3]),         \
          "r"((bv)[0]), "r"((bv)[1]))

// ---------------- CSR build ----------------
__global__ void k_count(const int* __restrict__ dst) {
    int e = blockIdx.x * blockDim.x + threadIdx.x;
    if (e < Ee) atomicAdd(&g_deg[dst[e]], 1);
}
__global__ void k_scan1() {
    __shared__ int s[1024];
    int i = blockIdx.x * 1024 + threadIdx.x;
    int v = (i < Nn) ? g_deg[i] : 0;
    s[threadIdx.x] = v;
    __syncthreads();
    for (int off = 1; off < 1024; off <<= 1) {
        int t = (threadIdx.x >= off) ? s[threadIdx.x - off] : 0;
        __syncthreads();
        s[threadIdx.x] += t;
        __syncthreads();
    }
    if (i < Nn) g_scan[i] = s[threadIdx.x];
    if (threadIdx.x == 1023) g_bsum[blockIdx.x] = s[1023];
}
__global__ void k_scan2(int nb) {
    __shared__ int s[128];
    int v = (threadIdx.x < nb) ? g_bsum[threadIdx.x] : 0;
    s[threadIdx.x] = v;
    __syncthreads();
    for (int off = 1; off < 128; off <<= 1) {
        int t = (threadIdx.x >= off) ? s[threadIdx.x - off] : 0;
        __syncthreads();
        s[threadIdx.x] += t;
        __syncthreads();
    }
    g_bsum[threadIdx.x] = (threadIdx.x == 0) ? 0 : s[threadIdx.x - 1];
}
__global__ void k_finalize() {
    int i = blockIdx.x * blockDim.x + threadIdx.x;
    if (i >= Nn) return;
    int incl = g_scan[i] + g_bsum[i >> 10];
    g_rowptr[i + 1] = incl;
    g_cursor[i] = incl - g_deg[i];
    if (i == 0) g_rowptr[0] = 0;
}
__global__ void k_fill(const int* __restrict__ dst, const int* __restrict__ src) {
    int e = blockIdx.x * blockDim.x + threadIdx.x;
    if (e < Ee) {
        int d = dst[e];
        int p = atomicAdd(&g_cursor[d], 1);
        g_srcs[p] = src[e];
    }
}

// ---------------- all-weight cvt ----------------
__global__ void k_cvt_all(const float* __restrict__ gat_W, const float* __restrict__ ff_W1,
                          const float* __restrict__ ff_W2, const float* __restrict__ dec_W1,
                          const float* __restrict__ emb_W2) {
    int i = blockIdx.x * blockDim.x + threadIdx.x;
    if (i >= 425984) return;
    float v;
    if (i < 65536) v = gat_W[i];
    else if (i < 196608) v = ff_W1[i - 65536];
    else if (i < 327680) v = ff_W2[i - 196608];
    else if (i < 409600) v = dec_W1[i - 327680];
    else v = emb_W2[i - 409600];
    g_W[i] = to_tf32(v);
}

// ---------------- embed stage 1 ----------------
__global__ void k_embed1(const float* __restrict__ x,
                         const float* __restrict__ W1, const float* __restrict__ b1,
                         const float* __restrict__ b2,
                         const float* __restrict__ Ws, const float* __restrict__ bs) {
    int idx = blockIdx.x * blockDim.x + threadIdx.x;
    if (idx >= Nn * 128) return;
    int n = idx >> 7, c = idx & 127;
    float x0 = x[n * 2], x1 = x[n * 2 + 1];
    float tv = fmaf(x0, W1[c], fmaf(x1, W1[128 + c], b1[c]));
    g_t[idx] = tv > 0.f ? tv : 0.f;
    g_y[idx] = fmaf(x0, Ws[c], fmaf(x1, Ws[128 + c], bs[c] + b2[c]));
}

// ---------------- generic fused tf32 tensor GEMM (512 thr, 2 CTAs/SM) ----------------
// AHALF: A is __half (lda in halfs). CHALF: C stored as __half (ldc in halfs).
template <int RELU, int BIAS, int RES, int BN, int ELER, int AAFF, int RAFF, int DEC,
          int AHALF, int CHALF>
__global__ void __launch_bounds__(512, 2) k_tgemm(
    const float* __restrict__ A, int lda,
    const float* __restrict__ B,
    const float* __restrict__ bias,
    const float* __restrict__ Res, int ldres,
    float* __restrict__ C, int ldc,
    int Nrows, int Mred, int Kcols, float* bnslot,
    const float* affA, const float* affAg, const float* affAb,
    const float* affR, const float* affRg, const float* affRb,
    const float* al, const float* ar) {
    constexpr int S = 4;
    constexpr int ASTG = 128 * 20;  // floats per A stage (half layout fits inside: 128*24 halfs)
    constexpr int BSTG = 16 * 136;
    constexpr int STGF = S * ASTG + S * BSTG;
    constexpr int SCA = STGF, SHA = SCA + 640, SCR = SHA + 640, SHR = SCR + 128;
    constexpr int ALO = SHR + 128, ARO = ALO + 128;
    extern __shared__ float sm[];
    float* AsF = sm;
    float* BsF = sm + S * ASTG;

    const int tid = threadIdx.x;
    const int lane = tid & 31;
    const int wid = tid >> 5;
    const int bm = blockIdx.x * 128;
    const int bn = blockIdx.y * 128;

    const int m0 = (wid & 3) * 32;
    const int n0 = (wid >> 2) * 32;
    const int qrow = lane >> 2;
    const int qk = lane & 3;

    // fp32 A loader: 512 threads, 16B each, K=16 chunk
    const int arowF = tid >> 2;
    const int asegF = (tid & 3) * 4;
    // fp16 A loader: 256 threads, 16B (8 halfs) each, K=16 chunk
    const int arowH = tid >> 1;
    const int asegH = (tid & 1) * 8;

    const int brow = tid >> 5;
    const int bcol = (tid & 31) * 4;

    const bool aokF = (bm + arowF) < Nrows;
    const bool aokH = (tid < 256) && ((bm + arowH) < Nrows);
    const float* AsrcF = A + (size_t)(bm + arowF) * lda + asegF;
    const __half* AsrcH = (const __half*)A + (size_t)(bm + arowH) * lda + asegH;
    const float* Bsrc = B + (size_t)brow * Kcols + bn + bcol;
    const uint32_t asmb = smem_to_u32(AsF);
    const uint32_t bdst = smem_to_u32(BsF) + (uint32_t)(brow * 136 + bcol) * 4u;

    const int nIter = Mred >> 4;

#pragma unroll
    for (int s = 0; s < S - 1; s++) {
        if (s < nIter) {
            int kt = s << 4;
            if (AHALF) {
                if (tid < 256)
                    cp16(asmb + (uint32_t)s * (ASTG * 4u) + (uint32_t)(arowH * 24 + asegH) * 2u,
                         AsrcH + kt, aokH);
            } else {
                cp16(asmb + (uint32_t)s * (ASTG * 4u) + (uint32_t)(arowF * 20 + asegF) * 4u,
                     AsrcF + kt, aokF);
            }
            cp16(bdst + (uint32_t)(s * BSTG) * 4u, Bsrc + (size_t)kt * Kcols, true);
        }
        CP_COMMIT();
    }

    const float invN = 1.f / (float)Nn;
    if (AAFF) {
        for (int k = tid; k < Mred; k += 512) {
            float scv = 1.f, shv = 0.f;
            const float *slot = nullptr, *gg = nullptr, *bb = nullptr;
            int c = k;
            if (AAFF == 1) { slot = affA; gg = affAg; bb = affAb; }
            else {
                int blk = k >> 7;
                c = k & 127;
                if (blk > 0) {
                    slot = g_bnsum + (size_t)(2 * (blk - 1) + 1) * 256;
                    gg = affAg + (blk - 1) * 128;
                    bb = affAb + (blk - 1) * 128;
                }
            }
            if (slot) {
                float mu = slot[c] * invN;
                float var = slot[c + 128] * invN - mu * mu;
                float rs = rsqrtf(var + EPSBN);
                scv = gg[c] * rs;
                shv = bb[c] - mu * scv;
            }
            sm[SCA + k] = scv;
            sm[SHA + k] = shv;
        }
    }
    if (RAFF) {
        if (tid < 128) {
            float mu = affR[tid] * invN;
            float var = affR[tid + 128] * invN - mu * mu;
            float rs = rsqrtf(var + EPSBN);
            float scv = affRg[tid] * rs;
            sm[SCR + tid] = scv;
            sm[SHR + tid] = affRb[tid] - mu * scv;
        }
    }
    if (ELER) {
        if (tid < 128) sm[ALO + tid] = al[tid];
        else if (tid < 256) sm[ARO + tid - 128] = ar[tid - 128];
    }
    if (DEC) {
        if (tid < 128) sm[ALO + tid] = al[tid];
    }

    float acc[2][4][4];
#pragma unroll
    for (int mi = 0; mi < 2; mi++)
#pragma unroll
        for (int ni = 0; ni < 4; ni++)
#pragma unroll
            for (int j = 0; j < 4; j++) acc[mi][ni][j] = 0.f;

    for (int it = 0; it < nIter; it++) {
        CP_WAIT2();
        __syncthreads();

        const int stg = it & (S - 1);
        const float* as = AsF + stg * ASTG;
        const float* bs = BsF + stg * BSTG;
#pragma unroll
        for (int ks = 0; ks < 2; ks++) {
            const int kbase = ks * 8;
            float sc0 = 1.f, sc1 = 1.f, sh0 = 0.f, sh1 = 0.f;
            if (AAFF) {
                int kg = (it << 4) + kbase + qk;
                sc0 = sm[SCA + kg]; sh0 = sm[SHA + kg];
                sc1 = sm[SCA + kg + 4]; sh1 = sm[SHA + kg + 4];
            }
            uint32_t a[2][4];
#pragma unroll
            for (int mi = 0; mi < 2; mi++) {
                if (AHALF) {
                    const __half* ap = (const __half*)as + (m0 + mi * 16 + qrow) * 24 + kbase + qk;
                    a[mi][0] = __float_as_uint(__half2float(ap[0]));
                    a[mi][1] = __float_as_uint(__half2float(ap[8 * 24]));
                    a[mi][2] = __float_as_uint(__half2float(ap[4]));
                    a[mi][3] = __float_as_uint(__half2float(ap[8 * 24 + 4]));
                } else {
                    const float* ap = as + (m0 + mi * 16 + qrow) * 20 + kbase + qk;
                    if (AAFF) {
                        a[mi][0] = __float_as_uint(to_tf32(fmaf(ap[0], sc0, sh0)));
                        a[mi][1] = __float_as_uint(to_tf32(fmaf(ap[8 * 20], sc0, sh0)));
                        a[mi][2] = __float_as_uint(to_tf32(fmaf(ap[4], sc1, sh1)));
                        a[mi][3] = __float_as_uint(to_tf32(fmaf(ap[8 * 20 + 4], sc1, sh1)));
                    } else {
                        a[mi][0] = __float_as_uint(to_tf32(ap[0]));
                        a[mi][1] = __float_as_uint(to_tf32(ap[8 * 20]));
                        a[mi][2] = __float_as_uint(to_tf32(ap[4]));
                        a[mi][3] = __float_as_uint(to_tf32(ap[8 * 20 + 4]));
                    }
                }
            }
            uint32_t b[4][2];
#pragma unroll
            for (int ni = 0; ni < 4; ni++) {
                const float* bp = bs + (kbase + qk) * 136 + n0 + ni * 8 + qrow;
                b[ni][0] = __float_as_uint(bp[0]);
                b[ni][1] = __float_as_uint(bp[4 * 136]);
            }
#pragma unroll
            for (int mi = 0; mi < 2; mi++)
#pragma unroll
                for (int ni = 0; ni < 4; ni++) MMA_TF32(acc[mi][ni], a[mi], b[ni]);
        }

        const int nx = it + S - 1;
        if (nx < nIter) {
            const int s = nx & (S - 1);
            const int kt = nx << 4;
            if (AHALF) {
                if (tid < 256)
                    cp16(asmb + (uint32_t)s * (ASTG * 4u) + (uint32_t)(arowH * 24 + asegH) * 2u,
                         AsrcH + kt, aokH);
            } else {
                cp16(asmb + (uint32_t)s * (ASTG * 4u) + (uint32_t)(arowF * 20 + asegF) * 4u,
                     AsrcF + kt, aokF);
            }
            cp16(bdst + (uint32_t)(s * BSTG) * 4u, Bsrc + (size_t)kt * Kcols, true);
        }
        CP_COMMIT();
    }

    // epilogue
    float s0[4], s1[4], q0[4], q1[4];
    if (BN) {
#pragma unroll
        for (int ni = 0; ni < 4; ni++) { s0[ni] = 0.f; s1[ni] = 0.f; q0[ni] = 0.f; q1[ni] = 0.f; }
    }
#pragma unroll
    for (int mi = 0; mi < 2; mi++) {
#pragma unroll
        for (int half = 0; half < 2; half++) {
            int r = bm + m0 + mi * 16 + qrow + half * 8;
            bool rok = r < Nrows;
            float pd = 0.f;
#pragma unroll
            for (int ni = 0; ni < 4; ni++) {
                int gcl = n0 + ni * 8 + qk * 2;
                int gc = bn + gcl;
                float v0 = acc[mi][ni][half * 2 + 0];
                float v1 = acc[mi][ni][half * 2 + 1];
                if (BIAS) {
                    v0 += bias[gc];
                    v1 += bias[gc + 1];
                }
                if (RELU) {
                    v0 = fmaxf(v0, 0.f);
                    v1 = fmaxf(v1, 0.f);
                }
                if (RES && rok) {
                    const float* rp = Res + (size_t)r * ldres + gc;
                    float rv0 = rp[0], rv1 = rp[1];
                    if (RAFF) {
                        rv0 = fmaf(rv0, sm[SCR + gc], sm[SHR + gc]);
                        rv1 = fmaf(rv1, sm[SCR + gc + 1], sm[SHR + gc + 1]);
                    }
                    v0 += rv0;
                    v1 += rv1;
                }
                if (!DEC && rok) {
                    if (CHALF) {
                        *(__half2*)((__half*)C + (size_t)r * ldc + gc) = __floats2half2_rn(v0, v1);
                    } else {
                        *(float2*)(C + (size_t)r * ldc + gc) = make_float2(v0, v1);
                    }
                }
                if (BN && rok) {
                    s0[ni] += v0; q0[ni] += v0 * v0;
                    s1[ni] += v1; q1[ni] += v1 * v1;
                }
                if (DEC) pd = fmaf(v0, sm[ALO + gcl], fmaf(v1, sm[ALO + gcl + 1], pd));
                if (ELER) {
                    int h = (n0 >> 3) + ni;
                    float p = fmaf(v0, sm[ALO + h * 8 + qk * 2], v1 * sm[ALO + h * 8 + qk * 2 + 1]);
                    float q = fmaf(v0, sm[ARO + h * 8 + qk * 2], v1 * sm[ARO + h * 8 + qk * 2 + 1]);
                    p += __shfl_xor_sync(0xffffffffu, p, 1);
                    p += __shfl_xor_sync(0xffffffffu, p, 2);
                    q += __shfl_xor_sync(0xffffffffu, q, 1);
                    q += __shfl_xor_sync(0xffffffffu, q, 2);
                    if ((lane & 3) == 0 && rok) {
                        g_el[r * 16 + h] = p;
                        g_er[r * 16 + h] = q;
                    }
                }
            }
            if (DEC) {
                pd += __shfl_xor_sync(0xffffffffu, pd, 1);
                pd += __shfl_xor_sync(0xffffffffu, pd, 2);
                if ((lane & 3) == 0 && rok)
                    atomicAdd(C + r, pd + 0.25f * ar[0]);
            }
        }
    }

    if (BN) {
#pragma unroll
        for (int ni = 0; ni < 4; ni++) {
            s0[ni] += __shfl_xor_sync(0xffffffffu, s0[ni], 4);
            s0[ni] += __shfl_xor_sync(0xffffffffu, s0[ni], 8);
            s0[ni] += __shfl_xor_sync(0xffffffffu, s0[ni], 16);
            s1[ni] += __shfl_xor_sync(0xffffffffu, s1[ni], 4);
            s1[ni] += __shfl_xor_sync(0xffffffffu, s1[ni], 8);
            s1[ni] += __shfl_xor_sync(0xffffffffu, s1[ni], 16);
            q0[ni] += __shfl_xor_sync(0xffffffffu, q0[ni], 4);
            q0[ni] += __shfl_xor_sync(0xffffffffu, q0[ni], 8);
            q0[ni] += __shfl_xor_sync(0xffffffffu, q0[ni], 16);
            q1[ni] += __shfl_xor_sync(0xffffffffu, q1[ni], 4);
            q1[ni] += __shfl_xor_sync(0xffffffffu, q1[ni], 8);
            q1[ni] += __shfl_xor_sync(0xffffffffu, q1[ni], 16);
        }
        __syncthreads();
        if (lane < 4) {
            int mg = wid & 3;
#pragma unroll
            for (int ni = 0; ni < 4; ni++) {
                int c = n0 + ni * 8 + lane * 2;
                sm[mg * 128 + c] = s0[ni];
                sm[mg * 128 + c + 1] = s1[ni];
                sm[512 + mg * 128 + c] = q0[ni];
                sm[512 + mg * 128 + c + 1] = q1[ni];
            }
        }
        __syncthreads();
        if (tid < 256) {
            int c = tid & 127, st = tid >> 7;
            float v = sm[st * 512 + c] + sm[st * 512 + 128 + c] +
                      sm[st * 512 + 256 + c] + sm[st * 512 + 384 + c];
            atomicAdd(bnslot + st * 128 + c, v);
        }
    }
}

// ---------------- GAT aggregate: single-pass softmax, 2-way edge unroll, fused BN1 stats ----------------
__global__ void k_gat(const float* __restrict__ z,
                      const float* __restrict__ hres, int ldh,
                      const float* __restrict__ bias, float* __restrict__ y,
                      float* __restrict__ bnslot,
                      const float* __restrict__ slotPrev,
                      const float* __restrict__ gPrev, const float* __restrict__ bPrev) {
    __shared__ float sbn[2][8][128];
    int gw = (blockIdx.x * blockDim.x + threadIdx.x) >> 5;
    int lane = threadIdx.x & 31;
    int wid = threadIdx.x >> 5;
    float4 o = make_float4(0.f, 0.f, 0.f, 0.f);
    if (gw < Nn) {
        int head = lane >> 1;
        int beg = g_rowptr[gw], end = g_rowptr[gw + 1];
        float er_h = g_er[gw * 16 + head];
        const float4* z4 = (const float4*)z;

        float den = 0.f;
        float4 acc = make_float4(0.f, 0.f, 0.f, 0.f);
        int i = beg;
        for (; i + 1 < end; i += 2) {
            int sA = g_srcs[i];
            int sB = g_srcs[i + 1];
            float eA = g_el[sA * 16 + head];
            float eB = g_el[sB * 16 + head];
            float4 zA = z4[(size_t)sA * 32 + lane];
            float4 zB = z4[(size_t)sB * 32 + lane];
            eA += er_h;
            eB += er_h;
            eA = eA > 0.f ? eA : SLOPE * eA;
            eB = eB > 0.f ? eB : SLOPE * eB;
            float wA = __expf(eA);
            float wB = __expf(eB);
            den += wA + wB;
            acc.x += wA * zA.x + wB * zB.x;
            acc.y += wA * zA.y + wB * zB.y;
            acc.z += wA * zA.z + wB * zB.z;
            acc.w += wA * zA.w + wB * zB.w;
        }
        if (i < end) {
            int s = g_srcs[i];
            float e = g_el[s * 16 + head] + er_h;
            float4 zc = z4[(size_t)s * 32 + lane];
            e = e > 0.f ? e : SLOPE * e;
            float w = __expf(e);
            den += w;
            acc.x += w * zc.x; acc.y += w * zc.y; acc.z += w * zc.z; acc.w += w * zc.w;
        }
        float dinv = den > 0.f ? 1.f / den : 1.f;
        float4 b4 = ((const float4*)bias)[lane];
        float4 h4 = *(const float4*)(hres + (size_t)gw * ldh + lane * 4);
        if (slotPrev != nullptr) {
            const float invN = 1.f / (float)Nn;
            int c = lane * 4;
#pragma unroll
            for (int j = 0; j < 4; j++) {
                float mu = slotPrev[c + j] * invN;
                float var = slotPrev[128 + c + j] * invN - mu * mu;
                float sc = gPrev[c + j] * rsqrtf(var + EPSBN);
                float sh = bPrev[c + j] - mu * sc;
                float* hp = (&h4.x) + j;
                *hp = fmaf(*hp, sc, sh);
            }
        }
        o.x = acc.x * dinv + b4.x + h4.x;
        o.y = acc.y * dinv + b4.y + h4.y;
        o.z = acc.z * dinv + b4.z + h4.z;
        o.w = acc.w * dinv + b4.w + h4.w;
        ((float4*)y)[(size_t)gw * 32 + lane] = o;
    }
    ((float4*)sbn[0][wid])[lane] = o;
    ((float4*)sbn[1][wid])[lane] = make_float4(o.x * o.x, o.y * o.y, o.z * o.z, o.w * o.w);
    __syncthreads();
    int c = threadIdx.x & 127, st = threadIdx.x >> 7;
    float v = 0.f;
#pragma unroll
    for (int w = 0; w < 8; w++) v += sbn[st][w][c];
    atomicAdd(bnslot + st * 128 + c, v);
}

// ---------------- launch ----------------
extern "C" void kernel_launch(void* const* d_in, const int* in_sizes, int n_in,
                              void* d_out, int out_size) {
    const float* x      = (const float*)d_in[0];
    const int*   src    = (const int*)d_in[1];
    const int*   dst    = (const int*)d_in[2];
    const float* emb_W1 = (const float*)d_in[3];
    const float* emb_b1 = (const float*)d_in[4];
    const float* emb_W2 = (const float*)d_in[5];
    const float* emb_b2 = (const float*)d_in[6];
    const float* emb_Ws = (const float*)d_in[7];
    const float* emb_bs = (const float*)d_in[8];
    const float* gat_W  = (const float*)d_in[9];
    const float* gat_al = (const float*)d_in[10];
    const float* gat_ar = (const float*)d_in[11];
    const float* gat_b  = (const float*)d_in[12];
    const float* bn1_g  = (const float*)d_in[13];
    const float* bn1_b  = (const float*)d_in[14];
    const float* ff_W1  = (const float*)d_in[15];
    const float* ff_b1  = (const float*)d_in[16];
    const float* ff_W2  = (const float*)d_in[17];
    const float* ff_b2  = (const float*)d_in[18];
    const float* bn2_g  = (const float*)d_in[19];
    const float* bn2_b  = (const float*)d_in[20];
    const float* dec_W1 = (const float*)d_in[21];
    const float* dec_b1 = (const float*)d_in[22];
    const float* dec_W2 = (const float*)d_in[23];
    const float* dec_b2 = (const float*)d_in[24];

    void* p;
    float *HC, *zb, *tb, *yb, *bns, *W;
    int* degp;
    cudaGetSymbolAddress(&p, g_HC);    HC = (float*)p;
    cudaGetSymbolAddress(&p, g_z);     zb = (float*)p;
    cudaGetSymbolAddress(&p, g_t);     tb = (float*)p;
    cudaGetSymbolAddress(&p, g_y);     yb = (float*)p;
    cudaGetSymbolAddress(&p, g_bnsum); bns = (float*)p;
    cudaGetSymbolAddress(&p, g_deg);   degp = (int*)p;
    cudaGetSymbolAddress(&p, g_W);     W = (float*)p;

    float* Wg = W;
    float* Wf1 = W + 65536;
    float* Wf2 = W + 196608;
    float* Wd = W + 327680;
    float* We2 = W + 409600;

    const int SMEM = 20736 * 4;  // 82944 B
    static bool attrDone = false;
    if (!attrDone) {
        cudaFuncSetAttribute(k_tgemm<0, 0, 1, 0, 0, 0, 0, 0, 0, 0>, cudaFuncAttributeMaxDynamicSharedMemorySize, SMEM);
        cudaFuncSetAttribute(k_tgemm<0, 0, 0, 0, 1, 0, 0, 0, 0, 0>, cudaFuncAttributeMaxDynamicSharedMemorySize, SMEM);
        cudaFuncSetAttribute(k_tgemm<0, 0, 0, 0, 1, 1, 0, 0, 0, 0>, cudaFuncAttributeMaxDynamicSharedMemorySize, SMEM);
        cudaFuncSetAttribute(k_tgemm<1, 1, 0, 0, 0, 1, 0, 0, 0, 1>, cudaFuncAttributeMaxDynamicSharedMemorySize, SMEM);
        cudaFuncSetAttribute(k_tgemm<0, 1, 1, 1, 0, 0, 1, 0, 1, 0>, cudaFuncAttributeMaxDynamicSharedMemorySize, SMEM);
        cudaFuncSetAttribute(k_tgemm<1, 1, 0, 0, 0, 2, 0, 1, 0, 0>, cudaFuncAttributeMaxDynamicSharedMemorySize, SMEM);
        attrDone = true;
    }

    cudaMemsetAsync(bns, 0, 8 * 256 * sizeof(float));
    cudaMemsetAsync(degp, 0, Nn * sizeof(int));
    cudaMemsetAsync(d_out, 0, (size_t)out_size * sizeof(float));

    k_cvt_all<<<(425984 + 255) / 256, 256>>>(gat_W, ff_W1, ff_W2, dec_W1, emb_W2);
    k_embed1<<<(Nn * 128 + 255) / 256, 256>>>(x, emb_W1, emb_b1, emb_b2, emb_Ws, emb_bs);
    k_count<<<(Ee + 255) / 256, 256>>>(dst);

    const int gx = (Nn + 127) / 128;  // 782
    dim3 grid1(gx, 1), grid2(gx, 2);
    const int warpBlocks = (Nn * 32 + 255) / 256;

    // embed stage 2 GEMM (4th launch -> ncu target)
    k_tgemm<0, 0, 1, 0, 0, 0, 0, 0, 0, 0><<<grid1, 512, SMEM>>>(
        tb, 128, We2, nullptr, yb, 128, HC, 640, Nn, 128, 128, nullptr,
        nullptr, nullptr, nullptr, nullptr, nullptr, nullptr, nullptr, nullptr);

    const int nb = (Nn + 1023) / 1024;
    k_scan1<<<nb, 1024>>>();
    k_scan2<<<1, 128>>>(nb);
    k_finalize<<<(Nn + 255) / 256, 256>>>();
    k_fill<<<(Ee + 255) / 256, 256>>>(dst, src);

    for (int l = 0; l < 4; l++) {
        const float* h = HC + l * 128;
        float* slot1 = bns + (size_t)(2 * l) * 256;
        float* slot2 = bns + (size_t)(2 * l + 1) * 256;
        const float* slotP = (l > 0) ? (bns + (size_t)(2 * (l - 1) + 1) * 256) : nullptr;
        const float* gP = (l > 0) ? (bn2_g + (l - 1) * 128) : nullptr;
        const float* bP = (l > 0) ? (bn2_b + (l - 1) * 128) : nullptr;

        if (l == 0) {
            k_tgemm<0, 0, 0, 0, 1, 0, 0, 0, 0, 0><<<grid1, 512, SMEM>>>(
                h, 640, Wg, nullptr, nullptr, 0, zb, 128, Nn, 128, 128, nullptr,
                nullptr, nullptr, nullptr, nullptr, nullptr, nullptr,
                gat_al, gat_ar);
        } else {
            k_tgemm<0, 0, 0, 0, 1, 1, 0, 0, 0, 0><<<grid1, 512, SMEM>>>(
                h, 640, Wg + (size_t)l * 16384, nullptr, nullptr, 0, zb, 128, Nn, 128, 128, nullptr,
                slotP, gP, bP, nullptr, nullptr, nullptr,
                gat_al + l * 128, gat_ar + l * 128);
        }
        k_gat<<<warpBlocks, 256>>>(zb, h, 640, gat_b + l * 128, yb, slot1, slotP, gP, bP);
        // ff1: t(half) = relu(BN1(y) @ W1 + b1)
        k_tgemm<1, 1, 0, 0, 0, 1, 0, 0, 0, 1><<<grid2, 512, SMEM>>>(
            yb, 128, Wf1 + (size_t)l * 32768, ff_b1 + l * 256, nullptr, 0,
            tb /* as half C */, 256, Nn, 128, 256, nullptr,
            slot1, bn1_g + l * 128, bn1_b + l * 128, nullptr, nullptr, nullptr, nullptr, nullptr);
        // ff2: HC_next = t(half) @ W2 + b2 + BN1(y), BN2 stats fused
        k_tgemm<0, 1, 1, 1, 0, 0, 1, 0, 1, 0><<<grid1, 512, SMEM>>>(
            tb /* as half A */, 256, Wf2 + (size_t)l * 32768, ff_b2 + l * 128, yb, 128,
            HC + (size_t)(l + 1) * 128, 640, Nn, 256, 128, slot2,
            nullptr, nullptr, nullptr, slot1, bn1_g + l * 128, bn1_b + l * 128, nullptr, nullptr);
    }

    // decoder: relu(affine_concat(HC) @ Wd + b1) . W2 + b2 (fused dot, atomic partials)
    k_tgemm<1, 1, 0, 0, 0, 2, 0, 1, 0, 0><<<grid1, 512, SMEM>>>(
        HC, 640, Wd, dec_b1, nullptr, 0, (float*)d_out, 1, Nn, 640, 128, nullptr,
        nullptr, bn2_g, bn2_b, nullptr, nullptr, nullptr, dec_W2, dec_b2);
}

// round 14
// speedup vs baseline: 1.0420x; 1.0420x over previous
#include <cuda_runtime.h>
#include <cuda_fp16.h>
#include <cstdint>

#define Nn 100000
#define Ee 600000
#define EPSBN 1e-5f
#define SLOPE 0.2f

// ---------------- scratch ----------------
__device__ float g_HC[(size_t)Nn * 640];
__device__ float g_z[(size_t)Nn * 128];   // used as __half[Nn*128]
__device__ float g_t[(size_t)Nn * 256];
__device__ float g_y[(size_t)Nn * 128];
__device__ float g_el[(size_t)Nn * 16];
__device__ float g_er[(size_t)Nn * 16];
__device__ float g_bnsum[8 * 256];
__device__ int   g_deg[Nn];
__device__ int   g_scan[Nn];
__device__ int   g_bsum[128];
__device__ int   g_rowptr[Nn + 1];
__device__ int   g_cursor[Nn];
__device__ int   g_srcs[Ee];
__device__ float g_W[425984];

__device__ __forceinline__ float to_tf32(float x) {
    float r;
    asm("cvt.rna.tf32.f32 %0, %1;" : "=f"(r) : "f"(x));
    return r;
}
__device__ __forceinline__ uint32_t smem_to_u32(const void* p) {
    uint32_t a;
    asm("{ .reg .u64 t; cvta.to.shared.u64 t, %1; cvt.u32.u64 %0, t; }" : "=r"(a) : "l"(p));
    return a;
}
__device__ __forceinline__ void cp16(uint32_t dst, const void* src, bool ok) {
    int sz = ok ? 16 : 0;
    asm volatile("cp.async.cg.shared.global [%0], [%1], 16, %2;"
                 :: "r"(dst), "l"(src), "r"(sz) : "memory");
}
#define CP_COMMIT() asm volatile("cp.async.commit_group;" ::: "memory")
#define CP_WAIT2() asm volatile("cp.async.wait_group 2;" ::: "memory")
#define CP_WAIT1() asm volatile("cp.async.wait_group 1;" ::: "memory")
#define CP_WAIT0() asm volatile("cp.async.wait_group 0;" ::: "memory")

#define MMA_TF32(d, av, bv)                                               \
    asm volatile(                                                         \
        "mma.sync.aligned.m16n8k8.row.col.f32.tf32.tf32.f32 "             \
        "{%0,%1,%2,%3},{%4,%5,%6,%7},{%8,%9},{%0,%1,%2,%3};"              \
        : "+f"((d)[0]), "+f"((d)[1]), "+f"((d)[2]), "+f"((d)[3])          \
        : "r"((av)[0]), "r"((av)[1]), "r"((av)[2]), "r"((av)[3]),         \
          "r"((bv)[0]), "r"((bv)[1]))

// ---------------- CSR build ----------------
__global__ void k_count(const int* __restrict__ dst) {
    int e = blockIdx.x * blockDim.x + threadIdx.x;
    if (e < Ee) atomicAdd(&g_deg[dst[e]], 1);
}
__global__ void k_scan1() {
    __shared__ int s[1024];
    int i = blockIdx.x * 1024 + threadIdx.x;
    int v = (i < Nn) ? g_deg[i] : 0;
    s[threadIdx.x] = v;
    __syncthreads();
    for (int off = 1; off < 1024; off <<= 1) {
        int t = (threadIdx.x >= off) ? s[threadIdx.x - off] : 0;
        __syncthreads();
        s[threadIdx.x] += t;
        __syncthreads();
    }
    if (i < Nn) g_scan[i] = s[threadIdx.x];
    if (threadIdx.x == 1023) g_bsum[blockIdx.x] = s[1023];
}
__global__ void k_scan2(int nb) {
    __shared__ int s[128];
    int v = (threadIdx.x < nb) ? g_bsum[threadIdx.x] : 0;
    s[threadIdx.x] = v;
    __syncthreads();
    for (int off = 1; off < 128; off <<= 1) {
        int t = (threadIdx.x >= off) ? s[threadIdx.x - off] : 0;
        __syncthreads();
        s[threadIdx.x] += t;
        __syncthreads();
    }
    g_bsum[threadIdx.x] = (threadIdx.x == 0) ? 0 : s[threadIdx.x - 1];
}
__global__ void k_finalize() {
    int i = blockIdx.x * blockDim.x + threadIdx.x;
    if (i >= Nn) return;
    int incl = g_scan[i] + g_bsum[i >> 10];
    g_rowptr[i + 1] = incl;
    g_cursor[i] = incl - g_deg[i];
    if (i == 0) g_rowptr[0] = 0;
}
__global__ void k_fill(const int* __restrict__ dst, const int* __restrict__ src) {
    int e = blockIdx.x * blockDim.x + threadIdx.x;
    if (e < Ee) {
        int d = dst[e];
        int p = atomicAdd(&g_cursor[d], 1);
        g_srcs[p] = src[e];
    }
}

// ---------------- all-weight cvt ----------------
__global__ void k_cvt_all(const float* __restrict__ gat_W, const float* __restrict__ ff_W1,
                          const float* __restrict__ ff_W2, const float* __restrict__ dec_W1,
                          const float* __restrict__ emb_W2) {
    int i = blockIdx.x * blockDim.x + threadIdx.x;
    if (i >= 425984) return;
    float v;
    if (i < 65536) v = gat_W[i];
    else if (i < 196608) v = ff_W1[i - 65536];
    else if (i < 327680) v = ff_W2[i - 196608];
    else if (i < 409600) v = dec_W1[i - 327680];
    else v = emb_W2[i - 409600];
    g_W[i] = to_tf32(v);
}

// ---------------- embed stage 1 ----------------
__global__ void k_embed1(const float* __restrict__ x,
                         const float* __restrict__ W1, const float* __restrict__ b1,
                         const float* __restrict__ b2,
                         const float* __restrict__ Ws, const float* __restrict__ bs) {
    int idx = blockIdx.x * blockDim.x + threadIdx.x;
    if (idx >= Nn * 128) return;
    int n = idx >> 7, c = idx & 127;
    float x0 = x[n * 2], x1 = x[n * 2 + 1];
    float tv = fmaf(x0, W1[c], fmaf(x1, W1[128 + c], b1[c]));
    g_t[idx] = tv > 0.f ? tv : 0.f;
    g_y[idx] = fmaf(x0, Ws[c], fmaf(x1, Ws[128 + c], bs[c] + b2[c]));
}

// ---------------- generic fused tf32 tensor GEMM (512 thr, 2 CTAs/SM) ----------------
// CHALF: C stored as __half (ldc in halfs).
template <int RELU, int BIAS, int RES, int BN, int ELER, int AAFF, int RAFF, int DEC, int CHALF>
__global__ void __launch_bounds__(512, 2) k_tgemm(
    const float* __restrict__ A, int lda,
    const float* __restrict__ B,
    const float* __restrict__ bias,
    const float* __restrict__ Res, int ldres,
    float* __restrict__ C, int ldc,
    int Nrows, int Mred, int Kcols, float* bnslot,
    const float* affA, const float* affAg, const float* affAb,
    const float* affR, const float* affRg, const float* affRb,
    const float* al, const float* ar) {
    constexpr int S = 4;
    constexpr int ASTG = 128 * 20;
    constexpr int BSTG = 16 * 136;
    constexpr int STGF = S * ASTG + S * BSTG;
    constexpr int SCA = STGF, SHA = SCA + 640, SCR = SHA + 640, SHR = SCR + 128;
    constexpr int ALO = SHR + 128, ARO = ALO + 128;
    extern __shared__ float sm[];
    float* AsF = sm;
    float* BsF = sm + S * ASTG;

    const int tid = threadIdx.x;
    const int lane = tid & 31;
    const int wid = tid >> 5;
    const int bm = blockIdx.x * 128;
    const int bn = blockIdx.y * 128;

    const int m0 = (wid & 3) * 32;
    const int n0 = (wid >> 2) * 32;
    const int qrow = lane >> 2;
    const int qk = lane & 3;

    const int arow = tid >> 2;
    const int aseg = (tid & 3) * 4;
    const int brow = tid >> 5;
    const int bcol = (tid & 31) * 4;

    const int gr = bm + arow;
    const bool aok = gr < Nrows;
    const float* Asrc = A + (size_t)gr * lda + aseg;
    const float* Bsrc = B + (size_t)brow * Kcols + bn + bcol;
    const uint32_t adst = smem_to_u32(AsF) + (uint32_t)(arow * 20 + aseg) * 4u;
    const uint32_t bdst = smem_to_u32(BsF) + (uint32_t)(brow * 136 + bcol) * 4u;

    const int nIter = Mred >> 4;

#pragma unroll
    for (int s = 0; s < S - 1; s++) {
        if (s < nIter) {
            int kt = s << 4;
            cp16(adst + (uint32_t)(s * ASTG) * 4u, Asrc + kt, aok);
            cp16(bdst + (uint32_t)(s * BSTG) * 4u, Bsrc + (size_t)kt * Kcols, true);
        }
        CP_COMMIT();
    }

    const float invN = 1.f / (float)Nn;
    if (AAFF) {
        for (int k = tid; k < Mred; k += 512) {
            float scv = 1.f, shv = 0.f;
            const float *slot = nullptr, *gg = nullptr, *bb = nullptr;
            int c = k;
            if (AAFF == 1) { slot = affA; gg = affAg; bb = affAb; }
            else {
                int blk = k >> 7;
                c = k & 127;
                if (blk > 0) {
                    slot = g_bnsum + (size_t)(2 * (blk - 1) + 1) * 256;
                    gg = affAg + (blk - 1) * 128;
                    bb = affAb + (blk - 1) * 128;
                }
            }
            if (slot) {
                float mu = slot[c] * invN;
                float var = slot[c + 128] * invN - mu * mu;
                float rs = rsqrtf(var + EPSBN);
                scv = gg[c] * rs;
                shv = bb[c] - mu * scv;
            }
            sm[SCA + k] = scv;
            sm[SHA + k] = shv;
        }
    }
    if (RAFF) {
        if (tid < 128) {
            float mu = affR[tid] * invN;
            float var = affR[tid + 128] * invN - mu * mu;
            float rs = rsqrtf(var + EPSBN);
            float scv = affRg[tid] * rs;
            sm[SCR + tid] = scv;
            sm[SHR + tid] = affRb[tid] - mu * scv;
        }
    }
    if (ELER) {
        if (tid < 128) sm[ALO + tid] = al[tid];
        else if (tid < 256) sm[ARO + tid - 128] = ar[tid - 128];
    }
    if (DEC) {
        if (tid < 128) sm[ALO + tid] = al[tid];
    }

    float acc[2][4][4];
#pragma unroll
    for (int mi = 0; mi < 2; mi++)
#pragma unroll
        for (int ni = 0; ni < 4; ni++)
#pragma unroll
            for (int j = 0; j < 4; j++) acc[mi][ni][j] = 0.f;

    for (int it = 0; it < nIter; it++) {
        CP_WAIT2();
        __syncthreads();

        const int stg = it & (S - 1);
        const float* as = AsF + stg * ASTG;
        const float* bs = BsF + stg * BSTG;
#pragma unroll
        for (int ks = 0; ks < 2; ks++) {
            const int kbase = ks * 8;
            float sc0 = 1.f, sc1 = 1.f, sh0 = 0.f, sh1 = 0.f;
            if (AAFF) {
                int kg = (it << 4) + kbase + qk;
                sc0 = sm[SCA + kg]; sh0 = sm[SHA + kg];
                sc1 = sm[SCA + kg + 4]; sh1 = sm[SHA + kg + 4];
            }
            uint32_t a[2][4];
#pragma unroll
            for (int mi = 0; mi < 2; mi++) {
                const float* ap = as + (m0 + mi * 16 + qrow) * 20 + kbase + qk;
                if (AAFF) {
                    a[mi][0] = __float_as_uint(to_tf32(fmaf(ap[0], sc0, sh0)));
                    a[mi][1] = __float_as_uint(to_tf32(fmaf(ap[8 * 20], sc0, sh0)));
                    a[mi][2] = __float_as_uint(to_tf32(fmaf(ap[4], sc1, sh1)));
                    a[mi][3] = __float_as_uint(to_tf32(fmaf(ap[8 * 20 + 4], sc1, sh1)));
                } else {
                    a[mi][0] = __float_as_uint(to_tf32(ap[0]));
                    a[mi][1] = __float_as_uint(to_tf32(ap[8 * 20]));
                    a[mi][2] = __float_as_uint(to_tf32(ap[4]));
                    a[mi][3] = __float_as_uint(to_tf32(ap[8 * 20 + 4]));
                }
            }
            uint32_t b[4][2];
#pragma unroll
            for (int ni = 0; ni < 4; ni++) {
                const float* bp = bs + (kbase + qk) * 136 + n0 + ni * 8 + qrow;
                b[ni][0] = __float_as_uint(bp[0]);
                b[ni][1] = __float_as_uint(bp[4 * 136]);
            }
#pragma unroll
            for (int mi = 0; mi < 2; mi++)
#pragma unroll
                for (int ni = 0; ni < 4; ni++) MMA_TF32(acc[mi][ni], a[mi], b[ni]);
        }

        const int nx = it + S - 1;
        if (nx < nIter) {
            const int s = nx & (S - 1);
            const int kt = nx << 4;
            cp16(adst + (uint32_t)(s * ASTG) * 4u, Asrc + kt, aok);
            cp16(bdst + (uint32_t)(s * BSTG) * 4u, Bsrc + (size_t)kt * Kcols, true);
        }
        CP_COMMIT();
    }

    // epilogue
    float s0[4], s1[4], q0[4], q1[4];
    if (BN) {
#pragma unroll
        for (int ni = 0; ni < 4; ni++) { s0[ni] = 0.f; s1[ni] = 0.f; q0[ni] = 0.f; q1[ni] = 0.f; }
    }
#pragma unroll
    for (int mi = 0; mi < 2; mi++) {
#pragma unroll
        for (int half = 0; half < 2; half++) {
            int r = bm + m0 + mi * 16 + qrow + half * 8;
            bool rok = r < Nrows;
            float pd = 0.f;
#pragma unroll
            for (int ni = 0; ni < 4; ni++) {
                int gcl = n0 + ni * 8 + qk * 2;
                int gc = bn + gcl;
                float v0 = acc[mi][ni][half * 2 + 0];
                float v1 = acc[mi][ni][half * 2 + 1];
                if (BIAS) {
                    v0 += bias[gc];
                    v1 += bias[gc + 1];
                }
                if (RELU) {
                    v0 = fmaxf(v0, 0.f);
                    v1 = fmaxf(v1, 0.f);
                }
                if (RES && rok) {
                    const float* rp = Res + (size_t)r * ldres + gc;
                    float rv0 = rp[0], rv1 = rp[1];
                    if (RAFF) {
                        rv0 = fmaf(rv0, sm[SCR + gc], sm[SHR + gc]);
                        rv1 = fmaf(rv1, sm[SCR + gc + 1], sm[SHR + gc + 1]);
                    }
                    v0 += rv0;
                    v1 += rv1;
                }
                if (!DEC && rok) {
                    if (CHALF) {
                        *(__half2*)((__half*)C + (size_t)r * ldc + gc) = __floats2half2_rn(v0, v1);
                    } else {
                        *(float2*)(C + (size_t)r * ldc + gc) = make_float2(v0, v1);
                    }
                }
                if (BN && rok) {
                    s0[ni] += v0; q0[ni] += v0 * v0;
                    s1[ni] += v1; q1[ni] += v1 * v1;
                }
                if (DEC) pd = fmaf(v0, sm[ALO + gcl], fmaf(v1, sm[ALO + gcl + 1], pd));
                if (ELER) {
                    int h = (n0 >> 3) + ni;
                    float p = fmaf(v0, sm[ALO + h * 8 + qk * 2], v1 * sm[ALO + h * 8 + qk * 2 + 1]);
                    float q = fmaf(v0, sm[ARO + h * 8 + qk * 2], v1 * sm[ARO + h * 8 + qk * 2 + 1]);
                    p += __shfl_xor_sync(0xffffffffu, p, 1);
                    p += __shfl_xor_sync(0xffffffffu, p, 2);
                    q += __shfl_xor_sync(0xffffffffu, q, 1);
                    q += __shfl_xor_sync(0xffffffffu, q, 2);
                    if ((lane & 3) == 0 && rok) {
                        g_el[r * 16 + h] = p;
                        g_er[r * 16 + h] = q;
                    }
                }
            }
            if (DEC) {
                pd += __shfl_xor_sync(0xffffffffu, pd, 1);
                pd += __shfl_xor_sync(0xffffffffu, pd, 2);
                if ((lane & 3) == 0 && rok)
                    atomicAdd(C + r, pd + 0.25f * ar[0]);
            }
        }
    }

    if (BN) {
#pragma unroll
        for (int ni = 0; ni < 4; ni++) {
            s0[ni] += __shfl_xor_sync(0xffffffffu, s0[ni], 4);
            s0[ni] += __shfl_xor_sync(0xffffffffu, s0[ni], 8);
            s0[ni] += __shfl_xor_sync(0xffffffffu, s0[ni], 16);
            s1[ni] += __shfl_xor_sync(0xffffffffu, s1[ni], 4);
            s1[ni] += __shfl_xor_sync(0xffffffffu, s1[ni], 8);
            s1[ni] += __shfl_xor_sync(0xffffffffu, s1[ni], 16);
            q0[ni] += __shfl_xor_sync(0xffffffffu, q0[ni], 4);
            q0[ni] += __shfl_xor_sync(0xffffffffu, q0[ni], 8);
            q0[ni] += __shfl_xor_sync(0xffffffffu, q0[ni], 16);
            q1[ni] += __shfl_xor_sync(0xffffffffu, q1[ni], 4);
            q1[ni] += __shfl_xor_sync(0xffffffffu, q1[ni], 8);
            q1[ni] += __shfl_xor_sync(0xffffffffu, q1[ni], 16);
        }
        __syncthreads();
        if (lane < 4) {
            int mg = wid & 3;
#pragma unroll
            for (int ni = 0; ni < 4; ni++) {
                int c = n0 + ni * 8 + lane * 2;
                sm[mg * 128 + c] = s0[ni];
                sm[mg * 128 + c + 1] = s1[ni];
                sm[512 + mg * 128 + c] = q0[ni];
                sm[512 + mg * 128 + c + 1] = q1[ni];
            }
        }
        __syncthreads();
        if (tid < 256) {
            int c = tid & 127, st = tid >> 7;
            float v = sm[st * 512 + c] + sm[st * 512 + 128 + c] +
                      sm[st * 512 + 256 + c] + sm[st * 512 + 384 + c];
            atomicAdd(bnslot + st * 128 + c, v);
        }
    }
}

// ---------------- fused FF kernel (R10/R12 version: double-buffer, early prefetch) ----------------
__global__ void __launch_bounds__(512, 1) k_ff(
    const float* __restrict__ y,
    const float* __restrict__ W1, const float* __restrict__ b1v,
    const float* __restrict__ W2, const float* __restrict__ b2v,
    float* __restrict__ C, int ldc,
    const float* __restrict__ slot1, const float* __restrict__ g1, const float* __restrict__ bb1,
    float* __restrict__ bnslot) {
    constexpr int YOFF = 0;
    constexpr int TOFF = 16896;
    constexpr int WOFF = TOFF + 33280;
    constexpr int SCA = WOFF + 4352;
    constexpr int SHA = SCA + 128;
    constexpr int SB1 = SHA + 128;
    extern __shared__ float sm[];
    const int tid = threadIdx.x, lane = tid & 31, wid = tid >> 5;
    const int bm = blockIdx.x * 128;
    const int qrow = lane >> 2, qk = lane & 3;
    const uint32_t smb = smem_to_u32(sm);

    {
        int row = tid >> 2, cb = (tid & 3) * 32;
        bool ok = (bm + row) < Nn;
        const float* srcp = y + (size_t)(bm + row) * 128 + cb;
        uint32_t dst = smb + (uint32_t)(YOFF + row * 132 + cb) * 4u;
#pragma unroll
        for (int j = 0; j < 8; j++) cp16(dst + j * 16u, srcp + j * 4, ok);
    }
    {
        int r = tid >> 6, c = (tid & 63) * 4;
        cp16(smb + (uint32_t)(WOFF + r * 264 + c) * 4u, W1 + r * 256 + c, true);
    }
    CP_COMMIT();
    const float invN = 1.f / (float)Nn;
    if (tid < 128) {
        float mu = slot1[tid] * invN;
        float var = slot1[tid + 128] * invN - mu * mu;
        float sc = g1[tid] * rsqrtf(var + EPSBN);
        sm[SCA + tid] = sc;
        sm[SHA + tid] = bb1[tid] - mu * sc;
    } else if (tid < 384) {
        sm[SB1 + tid - 128] = b1v[tid - 128];
    }
    CP_WAIT0();
    __syncthreads();

    const int m0A = (wid & 3) * 32, n0A = (wid >> 2) * 64;
    float accA[2][8][4];
#pragma unroll
    for (int mi = 0; mi < 2; mi++)
#pragma unroll
        for (int ni = 0; ni < 8; ni++)
#pragma unroll
            for (int j = 0; j < 4; j++) accA[mi][ni][j] = 0.f;

    for (int it = 0; it < 16; it++) {
        if (it + 1 < 16) {
            int r = tid >> 6, c = (tid & 63) * 4;
            cp16(smb + (uint32_t)(WOFF + ((it + 1) & 1) * 2112 + r * 264 + c) * 4u,
                 W1 + (size_t)((it + 1) * 8 + r) * 256 + c, true);
        }
        CP_COMMIT();
        CP_WAIT1();
        __syncthreads();
        const float* bs = sm + WOFF + (it & 1) * 2112;
        int kg = it * 8 + qk;
        float sc0 = sm[SCA + kg], sh0 = sm[SHA + kg];
        float sc1 = sm[SCA + kg + 4], sh1 = sm[SHA + kg + 4];
        uint32_t a[2][4];
#pragma unroll
        for (int mi = 0; mi < 2; mi++) {
            const float* ap = sm + YOFF + (m0A + mi * 16 + qrow) * 132 + it * 8 + qk;
            a[mi][0] = __float_as_uint(to_tf32(fmaf(ap[0], sc0, sh0)));
            a[mi][1] = __float_as_uint(to_tf32(fmaf(ap[8 * 132], sc0, sh0)));
            a[mi][2] = __float_as_uint(to_tf32(fmaf(ap[4], sc1, sh1)));
            a[mi][3] = __float_as_uint(to_tf32(fmaf(ap[8 * 132 + 4], sc1, sh1)));
        }
#pragma unroll
        for (int ni = 0; ni < 8; ni++) {
            uint32_t b[2];
            const float* bp = bs + qk * 264 + n0A + ni * 8 + qrow;
            b[0] = __float_as_uint(bp[0]);
            b[1] = __float_as_uint(bp[4 * 264]);
#pragma unroll
            for (int mi = 0; mi < 2; mi++) MMA_TF32(accA[mi][ni], a[mi], b);
        }
        __syncthreads();
    }

#pragma unroll
    for (int mi = 0; mi < 2; mi++) {
#pragma unroll
        for (int half = 0; half < 2; half++) {
            int rl = m0A + mi * 16 + half * 8 + qrow;
#pragma unroll
            for (int ni = 0; ni < 8; ni++) {
                int c = n0A + ni * 8 + qk * 2;
                float v0 = fmaxf(accA[mi][ni][half * 2 + 0] + sm[SB1 + c], 0.f);
                float v1 = fmaxf(accA[mi][ni][half * 2 + 1] + sm[SB1 + c + 1], 0.f);
                *(float2*)&sm[TOFF + rl * 260 + c] = make_float2(v0, v1);
            }
        }
    }
    __syncthreads();

    const int m0B = (wid & 3) * 32, n0B = (wid >> 2) * 32;
    float accB[2][4][4];
#pragma unroll
    for (int mi = 0; mi < 2; mi++)
#pragma unroll
        for (int ni = 0; ni < 4; ni++)
#pragma unroll
            for (int j = 0; j < 4; j++) accB[mi][ni][j] = 0.f;

    {
        int r = tid >> 5, c = (tid & 31) * 4;
        cp16(smb + (uint32_t)(WOFF + r * 136 + c) * 4u, W2 + r * 128 + c, true);
    }
    CP_COMMIT();

    for (int it = 0; it < 16; it++) {
        if (it + 1 < 16) {
            int r = tid >> 5, c = (tid & 31) * 4;
            cp16(smb + (uint32_t)(WOFF + ((it + 1) & 1) * 2176 + r * 136 + c) * 4u,
                 W2 + (size_t)((it + 1) * 16 + r) * 128 + c, true);
        }
        CP_COMMIT();
        CP_WAIT1();
        __syncthreads();
        const float* bs = sm + WOFF + (it & 1) * 2176;
#pragma unroll
        for (int ks = 0; ks < 2; ks++) {
            int kb = it * 16 + ks * 8;
            uint32_t a[2][4];
#pragma unroll
            for (int mi = 0; mi < 2; mi++) {
                const float* ap = sm + TOFF + (m0B + mi * 16 + qrow) * 260 + kb + qk;
                a[mi][0] = __float_as_uint(to_tf32(ap[0]));
                a[mi][1] = __float_as_uint(to_tf32(ap[8 * 260]));
                a[mi][2] = __float_as_uint(to_tf32(ap[4]));
                a[mi][3] = __float_as_uint(to_tf32(ap[8 * 260 + 4]));
            }
#pragma unroll
            for (int ni = 0; ni < 4; ni++) {
                uint32_t b[2];
                const float* bp = bs + (ks * 8 + qk) * 136 + n0B + ni * 8 + qrow;
                b[0] = __float_as_uint(bp[0]);
                b[1] = __float_as_uint(bp[4 * 136]);
#pragma unroll
                for (int mi = 0; mi < 2; mi++) MMA_TF32(accB[mi][ni], a[mi], b);
            }
        }
        __syncthreads();
    }

    float s0[4], s1[4], q0[4], q1[4];
#pragma unroll
    for (int ni = 0; ni < 4; ni++) { s0[ni] = 0.f; s1[ni] = 0.f; q0[ni] = 0.f; q1[ni] = 0.f; }
#pragma unroll
    for (int mi = 0; mi < 2; mi++) {
#pragma unroll
        for (int half = 0; half < 2; half++) {
            int rl = m0B + mi * 16 + half * 8 + qrow;
            int r = bm + rl;
            bool rok = r < Nn;
#pragma unroll
            for (int ni = 0; ni < 4; ni++) {
                int gc = n0B + ni * 8 + qk * 2;
                float yv0 = fmaf(sm[YOFF + rl * 132 + gc], sm[SCA + gc], sm[SHA + gc]);
                float yv1 = fmaf(sm[YOFF + rl * 132 + gc + 1], sm[SCA + gc + 1], sm[SHA + gc + 1]);
                float v0 = accB[mi][ni][half * 2 + 0] + b2v[gc] + yv0;
                float v1 = accB[mi][ni][half * 2 + 1] + b2v[gc + 1] + yv1;
                if (rok) {
                    *(float2*)(C + (size_t)r * ldc + gc) = make_float2(v0, v1);
                    s0[ni] += v0; q0[ni] += v0 * v0;
                    s1[ni] += v1; q1[ni] += v1 * v1;
                }
            }
        }
    }
#pragma unroll
    for (int ni = 0; ni < 4; ni++) {
        s0[ni] += __shfl_xor_sync(0xffffffffu, s0[ni], 4);
        s0[ni] += __shfl_xor_sync(0xffffffffu, s0[ni], 8);
        s0[ni] += __shfl_xor_sync(0xffffffffu, s0[ni], 16);
        s1[ni] += __shfl_xor_sync(0xffffffffu, s1[ni], 4);
        s1[ni] += __shfl_xor_sync(0xffffffffu, s1[ni], 8);
        s1[ni] += __shfl_xor_sync(0xffffffffu, s1[ni], 16);
        q0[ni] += __shfl_xor_sync(0xffffffffu, q0[ni], 4);
        q0[ni] += __shfl_xor_sync(0xffffffffu, q0[ni], 8);
        q0[ni] += __shfl_xor_sync(0xffffffffu, q0[ni], 16);
        q1[ni] += __shfl_xor_sync(0xffffffffu, q1[ni], 4);
        q1[ni] += __shfl_xor_sync(0xffffffffu, q1[ni], 8);
        q1[ni] += __shfl_xor_sync(0xffffffffu, q1[ni], 16);
    }
    __syncthreads();
    if (lane < 4) {
        int mg = wid & 3;
#pragma unroll
        for (int ni = 0; ni < 4; ni++) {
            int c = n0B + ni * 8 + lane * 2;
            sm[mg * 128 + c] = s0[ni];
            sm[mg * 128 + c + 1] = s1[ni];
            sm[512 + mg * 128 + c] = q0[ni];
            sm[512 + mg * 128 + c + 1] = q1[ni];
        }
    }
    __syncthreads();
    if (tid < 256) {
        int c = tid & 127, st = tid >> 7;
        float v = sm[st * 512 + c] + sm[st * 512 + 128 + c] +
                  sm[st * 512 + 256 + c] + sm[st * 512 + 384 + c];
        atomicAdd(bnslot + st * 128 + c, v);
    }
}

// ---------------- GAT aggregate: half z gather, single-pass softmax, fused BN1 stats ----------------
__global__ void k_gat(const __half* __restrict__ z,
                      const float* __restrict__ hres, int ldh,
                      const float* __restrict__ bias, float* __restrict__ y,
                      float* __restrict__ bnslot,
                      const float* __restrict__ slotPrev,
                      const float* __restrict__ gPrev, const float* __restrict__ bPrev) {
    __shared__ float sbn[2][8][128];
    int gw = (blockIdx.x * blockDim.x + threadIdx.x) >> 5;
    int lane = threadIdx.x & 31;
    int wid = threadIdx.x >> 5;
    float4 o = make_float4(0.f, 0.f, 0.f, 0.f);
    if (gw < Nn) {
        int head = lane >> 1;
        int beg = g_rowptr[gw], end = g_rowptr[gw + 1];
        float er_h = g_er[gw * 16 + head];
        const uint2* z2 = (const uint2*)z;  // 4 halfs per lane

        float den = 0.f;
        float4 acc = make_float4(0.f, 0.f, 0.f, 0.f);
        int i = beg;
        for (; i + 1 < end; i += 2) {
            int sA = g_srcs[i];
            int sB = g_srcs[i + 1];
            float eA = g_el[sA * 16 + head];
            float eB = g_el[sB * 16 + head];
            uint2 rA = z2[(size_t)sA * 32 + lane];
            uint2 rB = z2[(size_t)sB * 32 + lane];
            eA += er_h;
            eB += er_h;
            eA = eA > 0.f ? eA : SLOPE * eA;
            eB = eB > 0.f ? eB : SLOPE * eB;
            float wA = __expf(eA);
            float wB = __expf(eB);
            den += wA + wB;
            float2 a0 = __half22float2(*(__half2*)&rA.x);
            float2 a1 = __half22float2(*(__half2*)&rA.y);
            float2 b0 = __half22float2(*(__half2*)&rB.x);
            float2 b1 = __half22float2(*(__half2*)&rB.y);
            acc.x += wA * a0.x + wB * b0.x;
            acc.y += wA * a0.y + wB * b0.y;
            acc.z += wA * a1.x + wB * b1.x;
            acc.w += wA * a1.y + wB * b1.y;
        }
        if (i < end) {
            int s = g_srcs[i];
            float e = g_el[s * 16 + head] + er_h;
            uint2 r = z2[(size_t)s * 32 + lane];
            e = e > 0.f ? e : SLOPE * e;
            float w = __expf(e);
            den += w;
            float2 a0 = __half22float2(*(__half2*)&r.x);
            float2 a1 = __half22float2(*(__half2*)&r.y);
            acc.x += w * a0.x; acc.y += w * a0.y;
            acc.z += w * a1.x; acc.w += w * a1.y;
        }
        float dinv = den > 0.f ? 1.f / den : 1.f;
        float4 b4 = ((const float4*)bias)[lane];
        float4 h4 = *(const float4*)(hres + (size_t)gw * ldh + lane * 4);
        if (slotPrev != nullptr) {
            const float invN = 1.f / (float)Nn;
            int c = lane * 4;
#pragma unroll
            for (int j = 0; j < 4; j++) {
                float mu = slotPrev[c + j] * invN;
                float var = slotPrev[128 + c + j] * invN - mu * mu;
                float sc = gPrev[c + j] * rsqrtf(var + EPSBN);
                float sh = bPrev[c + j] - mu * sc;
                float* hp = (&h4.x) + j;
                *hp = fmaf(*hp, sc, sh);
            }
        }
        o.x = acc.x * dinv + b4.x + h4.x;
        o.y = acc.y * dinv + b4.y + h4.y;
        o.z = acc.z * dinv + b4.z + h4.z;
        o.w = acc.w * dinv + b4.w + h4.w;
        ((float4*)y)[(size_t)gw * 32 + lane] = o;
    }
    ((float4*)sbn[0][wid])[lane] = o;
    ((float4*)sbn[1][wid])[lane] = make_float4(o.x * o.x, o.y * o.y, o.z * o.z, o.w * o.w);
    __syncthreads();
    int c = threadIdx.x & 127, st = threadIdx.x >> 7;
    float v = 0.f;
#pragma unroll
    for (int w = 0; w < 8; w++) v += sbn[st][w][c];
    atomicAdd(bnslot + st * 128 + c, v);
}

// ---------------- launch ----------------
extern "C" void kernel_launch(void* const* d_in, const int* in_sizes, int n_in,
                              void* d_out, int out_size) {
    const float* x      = (const float*)d_in[0];
    const int*   src    = (const int*)d_in[1];
    const int*   dst    = (const int*)d_in[2];
    const float* emb_W1 = (const float*)d_in[3];
    const float* emb_b1 = (const float*)d_in[4];
    const float* emb_W2 = (const float*)d_in[5];
    const float* emb_b2 = (const float*)d_in[6];
    const float* emb_Ws = (const float*)d_in[7];
    const float* emb_bs = (const float*)d_in[8];
    const float* gat_W  = (const float*)d_in[9];
    const float* gat_al = (const float*)d_in[10];
    const float* gat_ar = (const float*)d_in[11];
    const float* gat_b  = (const float*)d_in[12];
    const float* bn1_g  = (const float*)d_in[13];
    const float* bn1_b  = (const float*)d_in[14];
    const float* ff_W1  = (const float*)d_in[15];
    const float* ff_b1  = (const float*)d_in[16];
    const float* ff_W2  = (const float*)d_in[17];
    const float* ff_b2  = (const float*)d_in[18];
    const float* bn2_g  = (const float*)d_in[19];
    const float* bn2_b  = (const float*)d_in[20];
    const float* dec_W1 = (const float*)d_in[21];
    const float* dec_b1 = (const float*)d_in[22];
    const float* dec_W2 = (const float*)d_in[23];
    const float* dec_b2 = (const float*)d_in[24];

    void* p;
    float *HC, *zb, *tb, *yb, *bns, *W;
    int* degp;
    cudaGetSymbolAddress(&p, g_HC);    HC = (float*)p;
    cudaGetSymbolAddress(&p, g_z);     zb = (float*)p;
    cudaGetSymbolAddress(&p, g_t);     tb = (float*)p;
    cudaGetSymbolAddress(&p, g_y);     yb = (float*)p;
    cudaGetSymbolAddress(&p, g_bnsum); bns = (float*)p;
    cudaGetSymbolAddress(&p, g_deg);   degp = (int*)p;
    cudaGetSymbolAddress(&p, g_W);     W = (float*)p;

    float* Wg = W;
    float* Wf1 = W + 65536;
    float* Wf2 = W + 196608;
    float* Wd = W + 327680;
    float* We2 = W + 409600;

    const int SMEM = 20736 * 4;        // 82944 B (generic)
    const int SMEM_FF = 55040 * 4;     // 220160 B (fused FF)
    static bool attrDone = false;
    if (!attrDone) {
        cudaFuncSetAttribute(k_tgemm<0, 0, 1, 0, 0, 0, 0, 0, 0>, cudaFuncAttributeMaxDynamicSharedMemorySize, SMEM);
        cudaFuncSetAttribute(k_tgemm<0, 0, 0, 0, 1, 0, 0, 0, 1>, cudaFuncAttributeMaxDynamicSharedMemorySize, SMEM);
        cudaFuncSetAttribute(k_tgemm<0, 0, 0, 0, 1, 1, 0, 0, 1>, cudaFuncAttributeMaxDynamicSharedMemorySize, SMEM);
        cudaFuncSetAttribute(k_tgemm<1, 1, 0, 0, 0, 2, 0, 1, 0>, cudaFuncAttributeMaxDynamicSharedMemorySize, SMEM);
        cudaFuncSetAttribute(k_ff, cudaFuncAttributeMaxDynamicSharedMemorySize, SMEM_FF);
        attrDone = true;
    }

    cudaMemsetAsync(bns, 0, 8 * 256 * sizeof(float));
    cudaMemsetAsync(degp, 0, Nn * sizeof(int));
    cudaMemsetAsync(d_out, 0, (size_t)out_size * sizeof(float));

    k_cvt_all<<<(425984 + 255) / 256, 256>>>(gat_W, ff_W1, ff_W2, dec_W1, emb_W2);
    k_embed1<<<(Nn * 128 + 255) / 256, 256>>>(x, emb_W1, emb_b1, emb_b2, emb_Ws, emb_bs);
    k_count<<<(Ee + 255) / 256, 256>>>(dst);

    const int gx = (Nn + 127) / 128;  // 782
    dim3 grid1(gx, 1);
    const int warpBlocks = (Nn * 32 + 255) / 256;

    // embed stage 2 GEMM
    k_tgemm<0, 0, 1, 0, 0, 0, 0, 0, 0><<<grid1, 512, SMEM>>>(
        tb, 128, We2, nullptr, yb, 128, HC, 640, Nn, 128, 128, nullptr,
        nullptr, nullptr, nullptr, nullptr, nullptr, nullptr, nullptr, nullptr);

    const int nb = (Nn + 1023) / 1024;
    k_scan1<<<nb, 1024>>>();
    k_scan2<<<1, 128>>>(nb);
    k_finalize<<<(Nn + 255) / 256, 256>>>();
    k_fill<<<(Ee + 255) / 256, 256>>>(dst, src);

    for (int l = 0; l < 4; l++) {
        const float* h = HC + l * 128;
        float* slot1 = bns + (size_t)(2 * l) * 256;
        float* slot2 = bns + (size_t)(2 * l + 1) * 256;
        const float* slotP = (l > 0) ? (bns + (size_t)(2 * (l - 1) + 1) * 256) : nullptr;
        const float* gP = (l > 0) ? (bn2_g + (l - 1) * 128) : nullptr;
        const float* bP = (l > 0) ? (bn2_b + (l - 1) * 128) : nullptr;

        // z(half) = BN2prev(h) @ gat_W[l]  (+ fused el/er from fp32 accumulators)
        if (l == 0) {
            k_tgemm<0, 0, 0, 0, 1, 0, 0, 0, 1><<<grid1, 512, SMEM>>>(
                h, 640, Wg, nullptr, nullptr, 0, zb /* half C */, 128, Nn, 128, 128, nullptr,
                nullptr, nullptr, nullptr, nullptr, nullptr, nullptr,
                gat_al, gat_ar);
        } else {
            k_tgemm<0, 0, 0, 0, 1, 1, 0, 0, 1><<<grid1, 512, SMEM>>>(
                h, 640, Wg + (size_t)l * 16384, nullptr, nullptr, 0, zb /* half C */, 128,
                Nn, 128, 128, nullptr,
                slotP, gP, bP, nullptr, nullptr, nullptr,
                gat_al + l * 128, gat_ar + l * 128);
        }
        k_gat<<<warpBlocks, 256>>>((const __half*)zb, h, 640, gat_b + l * 128, yb, slot1,
                                   slotP, gP, bP);
        k_ff<<<grid1, 512, SMEM_FF>>>(
            yb, Wf1 + (size_t)l * 32768, ff_b1 + l * 256,
            Wf2 + (size_t)l * 32768, ff_b2 + l * 128,
            HC + (size_t)(l + 1) * 128, 640,
            slot1, bn1_g + l * 128, bn1_b + l * 128, slot2);
    }

    // decoder: relu(affine_concat(HC) @ Wd + b1) . W2 + b2 (fused dot, atomic partials)
    k_tgemm<1, 1, 0, 0, 0, 2, 0, 1, 0><<<grid1, 512, SMEM>>>(
        HC, 640, Wd, dec_b1, nullptr, 0, (float*)d_out, 1, Nn, 640, 128, nullptr,
        nullptr, bn2_g, bn2_b, nullptr, nullptr, nullptr, dec_W2, dec_b2);
}

// round 15
// speedup vs baseline: 1.0715x; 1.0283x over previous
#include <cuda_runtime.h>
#include <cuda_fp16.h>
#include <cstdint>

#define Nn 100000
#define Ee 600000
#define EPSBN 1e-5f
#define SLOPE 0.2f

// ---------------- scratch ----------------
__device__ __half g_HC[(size_t)Nn * 640];  // fp16 JumpingKnowledge buffer
__device__ float g_z[(size_t)Nn * 128];    // used as __half[Nn*128]
__device__ float g_y[(size_t)Nn * 128];
__device__ float g_el[(size_t)Nn * 16];
__device__ float g_er[(size_t)Nn * 16];
__device__ float g_bnsum[8 * 256];
__device__ int   g_deg[Nn];
__device__ int   g_scan[Nn];
__device__ int   g_bsum[128];
__device__ int   g_rowptr[Nn + 1];
__device__ int   g_cursor[Nn];
__device__ int   g_srcs[Ee];
__device__ float g_W[425984];

__device__ __forceinline__ float to_tf32(float x) {
    float r;
    asm("cvt.rna.tf32.f32 %0, %1;" : "=f"(r) : "f"(x));
    return r;
}
__device__ __forceinline__ uint32_t smem_to_u32(const void* p) {
    uint32_t a;
    asm("{ .reg .u64 t; cvta.to.shared.u64 t, %1; cvt.u32.u64 %0, t; }" : "=r"(a) : "l"(p));
    return a;
}
__device__ __forceinline__ void cp16(uint32_t dst, const void* src, bool ok) {
    int sz = ok ? 16 : 0;
    asm volatile("cp.async.cg.shared.global [%0], [%1], 16, %2;"
                 :: "r"(dst), "l"(src), "r"(sz) : "memory");
}
#define CP_COMMIT() asm volatile("cp.async.commit_group;" ::: "memory")
#define CP_WAIT2() asm volatile("cp.async.wait_group 2;" ::: "memory")
#define CP_WAIT1() asm volatile("cp.async.wait_group 1;" ::: "memory")
#define CP_WAIT0() asm volatile("cp.async.wait_group 0;" ::: "memory")

#define MMA_TF32(d, av, bv)                                               \
    asm volatile(                                                         \
        "mma.sync.aligned.m16n8k8.row.col.f32.tf32.tf32.f32 "             \
        "{%0,%1,%2,%3},{%4,%5,%6,%7},{%8,%9},{%0,%1,%2,%3};"              \
        : "+f"((d)[0]), "+f"((d)[1]), "+f"((d)[2]), "+f"((d)[3])          \
        : "r"((av)[0]), "r"((av)[1]), "r"((av)[2]), "r"((av)[3]),         \
          "r"((bv)[0]), "r"((bv)[1]))

// ---------------- CSR build ----------------
__global__ void k_count(const int* __restrict__ dst) {
    int e = blockIdx.x * blockDim.x + threadIdx.x;
    if (e < Ee) atomicAdd(&g_deg[dst[e]], 1);
}
__global__ void k_scan1() {
    __shared__ int s[1024];
    int i = blockIdx.x * 1024 + threadIdx.x;
    int v = (i < Nn) ? g_deg[i] : 0;
    s[threadIdx.x] = v;
    __syncthreads();
    for (int off = 1; off < 1024; off <<= 1) {
        int t = (threadIdx.x >= off) ? s[threadIdx.x - off] : 0;
        __syncthreads();
        s[threadIdx.x] += t;
        __syncthreads();
    }
    if (i < Nn) g_scan[i] = s[threadIdx.x];
    if (threadIdx.x == 1023) g_bsum[blockIdx.x] = s[1023];
}
__global__ void k_scan2(int nb) {
    __shared__ int s[128];
    int v = (threadIdx.x < nb) ? g_bsum[threadIdx.x] : 0;
    s[threadIdx.x] = v;
    __syncthreads();
    for (int off = 1; off < 128; off <<= 1) {
        int t = (threadIdx.x >= off) ? s[threadIdx.x - off] : 0;
        __syncthreads();
        s[threadIdx.x] += t;
        __syncthreads();
    }
    g_bsum[threadIdx.x] = (threadIdx.x == 0) ? 0 : s[threadIdx.x - 1];
}
__global__ void k_finalize() {
    int i = blockIdx.x * blockDim.x + threadIdx.x;
    if (i >= Nn) return;
    int incl = g_scan[i] + g_bsum[i >> 10];
    g_rowptr[i + 1] = incl;
    g_cursor[i] = incl - g_deg[i];
    if (i == 0) g_rowptr[0] = 0;
}
__global__ void k_fill(const int* __restrict__ dst, const int* __restrict__ src) {
    int e = blockIdx.x * blockDim.x + threadIdx.x;
    if (e < Ee) {
        int d = dst[e];
        int p = atomicAdd(&g_cursor[d], 1);
        g_srcs[p] = src[e];
    }
}

// ---------------- all-weight cvt ----------------
__global__ void k_cvt_all(const float* __restrict__ gat_W, const float* __restrict__ ff_W1,
                          const float* __restrict__ ff_W2, const float* __restrict__ dec_W1,
                          const float* __restrict__ emb_W2) {
    int i = blockIdx.x * blockDim.x + threadIdx.x;
    if (i >= 425984) return;
    float v;
    if (i < 65536) v = gat_W[i];
    else if (i < 196608) v = ff_W1[i - 65536];
    else if (i < 327680) v = ff_W2[i - 196608];
    else if (i < 409600) v = dec_W1[i - 327680];
    else v = emb_W2[i - 409600];
    g_W[i] = to_tf32(v);
}

// ---------------- fused embed kernel: HC0(half) = relu(x@W1+b1)@We2 + b2 + x@Ws + bs ----------------
__global__ void __launch_bounds__(512, 2) k_emb(
    const float* __restrict__ x, const float* __restrict__ B,  // We2 tf32 [128][128]
    const float* __restrict__ W1, const float* __restrict__ b1,
    const float* __restrict__ Ws, const float* __restrict__ bs,
    const float* __restrict__ b2,
    __half* __restrict__ C, int ldc) {
    constexpr int S = 4;
    constexpr int ASTG = 128 * 20;
    constexpr int BSTG = 16 * 136;
    constexpr int W1O = S * ASTG + S * BSTG;  // 18944
    constexpr int B1O = W1O + 256;
    extern __shared__ float sm[];
    float* AsF = sm;
    float* BsF = sm + S * ASTG;
    const int tid = threadIdx.x, lane = tid & 31, wid = tid >> 5;
    const int bm = blockIdx.x * 128;
    const int m0 = (wid & 3) * 32, n0 = (wid >> 2) * 32;
    const int qrow = lane >> 2, qk = lane & 3;
    const int arow = tid >> 2, aseg = (tid & 3) * 4;
    const int brow = tid >> 5, bcol = (tid & 31) * 4;
    const bool aok = (bm + arow) < Nn;
    float x0 = 0.f, x1 = 0.f;
    if (aok) {
        x0 = x[(size_t)(bm + arow) * 2];
        x1 = x[(size_t)(bm + arow) * 2 + 1];
    }
    if (tid < 256) sm[W1O + tid] = W1[tid];
    else if (tid < 384) sm[B1O + tid - 256] = b1[tid - 256];

    const float* Bsrc = B + (size_t)brow * 128 + bcol;
    const uint32_t bdst = smem_to_u32(BsF) + (uint32_t)(brow * 136 + bcol) * 4u;
#pragma unroll
    for (int s = 0; s < S - 1; s++) {
        cp16(bdst + (uint32_t)(s * BSTG) * 4u, Bsrc + (size_t)(s << 4) * 128, true);
        CP_COMMIT();
    }
    __syncthreads();  // W1s/B1s visible
    // compute A stages 0..2
#pragma unroll
    for (int s = 0; s < S - 1; s++) {
        float4 v;
#pragma unroll
        for (int j = 0; j < 4; j++) {
            int k = (s << 4) + aseg + j;
            float tv = fmaf(x0, sm[W1O + k], fmaf(x1, sm[W1O + 128 + k], sm[B1O + k]));
            (&v.x)[j] = tv > 0.f ? tv : 0.f;
        }
        *(float4*)&AsF[s * ASTG + arow * 20 + aseg] = v;
    }

    float acc[2][4][4];
#pragma unroll
    for (int mi = 0; mi < 2; mi++)
#pragma unroll
        for (int ni = 0; ni < 4; ni++)
#pragma unroll
            for (int j = 0; j < 4; j++) acc[mi][ni][j] = 0.f;

    const int nIter = 8;
    for (int it = 0; it < nIter; it++) {
        CP_WAIT2();
        __syncthreads();
        const float* as = AsF + (it & 3) * ASTG;
        const float* bs = BsF + (it & 3) * BSTG;
#pragma unroll
        for (int ks = 0; ks < 2; ks++) {
            const int kbase = ks * 8;
            uint32_t a[2][4];
#pragma unroll
            for (int mi = 0; mi < 2; mi++) {
                const float* ap = as + (m0 + mi * 16 + qrow) * 20 + kbase + qk;
                a[mi][0] = __float_as_uint(to_tf32(ap[0]));
                a[mi][1] = __float_as_uint(to_tf32(ap[8 * 20]));
                a[mi][2] = __float_as_uint(to_tf32(ap[4]));
                a[mi][3] = __float_as_uint(to_tf32(ap[8 * 20 + 4]));
            }
            uint32_t b[4][2];
#pragma unroll
            for (int ni = 0; ni < 4; ni++) {
                const float* bp = bs + (kbase + qk) * 136 + n0 + ni * 8 + qrow;
                b[ni][0] = __float_as_uint(bp[0]);
                b[ni][1] = __float_as_uint(bp[4 * 136]);
            }
#pragma unroll
            for (int mi = 0; mi < 2; mi++)
#pragma unroll
                for (int ni = 0; ni < 4; ni++) MMA_TF32(acc[mi][ni], a[mi], b[ni]);
        }
        const int nx = it + S - 1;
        if (nx < nIter) {
            const int s = nx & 3;
            float4 v;
#pragma unroll
            for (int j = 0; j < 4; j++) {
                int k = (nx << 4) + aseg + j;
                float tv = fmaf(x0, sm[W1O + k], fmaf(x1, sm[W1O + 128 + k], sm[B1O + k]));
                (&v.x)[j] = tv > 0.f ? tv : 0.f;
            }
            *(float4*)&AsF[s * ASTG + arow * 20 + aseg] = v;
            cp16(bdst + (uint32_t)(s * BSTG) * 4u, Bsrc + (size_t)(nx << 4) * 128, true);
        }
        CP_COMMIT();
    }

    // epilogue: + x@Ws + bs + b2, store half
#pragma unroll
    for (int mi = 0; mi < 2; mi++) {
#pragma unroll
        for (int half = 0; half < 2; half++) {
            int r = bm + m0 + mi * 16 + qrow + half * 8;
            if (r >= Nn) continue;
            float x0r = x[(size_t)r * 2], x1r = x[(size_t)r * 2 + 1];
#pragma unroll
            for (int ni = 0; ni < 4; ni++) {
                int gc = n0 + ni * 8 + qk * 2;
                float v0 = acc[mi][ni][half * 2 + 0] +
                           fmaf(x0r, Ws[gc], fmaf(x1r, Ws[128 + gc], bs[gc] + b2[gc]));
                float v1 = acc[mi][ni][half * 2 + 1] +
                           fmaf(x0r, Ws[gc + 1], fmaf(x1r, Ws[128 + gc + 1], bs[gc + 1] + b2[gc + 1]));
                *(__half2*)(C + (size_t)r * ldc + gc) = __floats2half2_rn(v0, v1);
            }
        }
    }
}

// ---------------- generic fused tf32 tensor GEMM (512 thr, 2 CTAs/SM) ----------------
// AHALF: A is __half (lda in halfs). CHALF: C stored __half (ldc in halfs).
template <int RELU, int BIAS, int BN, int ELER, int AAFF, int DEC, int AHALF, int CHALF>
__global__ void __launch_bounds__(512, 2) k_tgemm(
    const float* __restrict__ A, int lda,
    const float* __restrict__ B,
    const float* __restrict__ bias,
    float* __restrict__ C, int ldc,
    int Nrows, int Mred, int Kcols, float* bnslot,
    const float* affA, const float* affAg, const float* affAb,
    const float* al, const float* ar) {
    constexpr int S = 4;
    constexpr int ASTG = 128 * 20;
    constexpr int BSTG = 16 * 136;
    constexpr int STGF = S * ASTG + S * BSTG;
    constexpr int SCA = STGF, SHA = SCA + 640;
    constexpr int ALO = SHA + 640, ARO = ALO + 128;
    extern __shared__ float sm[];
    float* AsF = sm;
    float* BsF = sm + S * ASTG;

    const int tid = threadIdx.x;
    const int lane = tid & 31;
    const int wid = tid >> 5;
    const int bm = blockIdx.x * 128;
    const int bn = blockIdx.y * 128;

    const int m0 = (wid & 3) * 32;
    const int n0 = (wid >> 2) * 32;
    const int qrow = lane >> 2;
    const int qk = lane & 3;

    const int arowF = tid >> 2;
    const int asegF = (tid & 3) * 4;
    const int arowH = tid >> 1;
    const int asegH = (tid & 1) * 8;
    const int brow = tid >> 5;
    const int bcol = (tid & 31) * 4;

    const bool aokF = (bm + arowF) < Nrows;
    const bool aokH = (tid < 256) && ((bm + arowH) < Nrows);
    const float* AsrcF = A + (size_t)(bm + arowF) * lda + asegF;
    const __half* AsrcH = (const __half*)A + (size_t)(bm + arowH) * lda + asegH;
    const float* Bsrc = B + (size_t)brow * Kcols + bn + bcol;
    const uint32_t asmb = smem_to_u32(AsF);
    const uint32_t bdst = smem_to_u32(BsF) + (uint32_t)(brow * 136 + bcol) * 4u;

    const int nIter = Mred >> 4;

#pragma unroll
    for (int s = 0; s < S - 1; s++) {
        if (s < nIter) {
            int kt = s << 4;
            if (AHALF) {
                if (tid < 256)
                    cp16(asmb + (uint32_t)s * (ASTG * 4u) + (uint32_t)(arowH * 24 + asegH) * 2u,
                         AsrcH + kt, aokH);
            } else {
                cp16(asmb + (uint32_t)s * (ASTG * 4u) + (uint32_t)(arowF * 20 + asegF) * 4u,
                     AsrcF + kt, aokF);
            }
            cp16(bdst + (uint32_t)(s * BSTG) * 4u, Bsrc + (size_t)kt * Kcols, true);
        }
        CP_COMMIT();
    }

    const float invN = 1.f / (float)Nn;
    if (AAFF) {
        for (int k = tid; k < Mred; k += 512) {
            float scv = 1.f, shv = 0.f;
            const float *slot = nullptr, *gg = nullptr, *bb = nullptr;
            int c = k;
            if (AAFF == 1) { slot = affA; gg = affAg; bb = affAb; }
            else {
                int blk = k >> 7;
                c = k & 127;
                if (blk > 0) {
                    slot = g_bnsum + (size_t)(2 * (blk - 1) + 1) * 256;
                    gg = affAg + (blk - 1) * 128;
                    bb = affAb + (blk - 1) * 128;
                }
            }
            if (slot) {
                float mu = slot[c] * invN;
                float var = slot[c + 128] * invN - mu * mu;
                float rs = rsqrtf(var + EPSBN);
                scv = gg[c] * rs;
                shv = bb[c] - mu * scv;
            }
            sm[SCA + k] = scv;
            sm[SHA + k] = shv;
        }
    }
    if (ELER) {
        if (tid < 128) sm[ALO + tid] = al[tid];
        else if (tid < 256) sm[ARO + tid - 128] = ar[tid - 128];
    }
    if (DEC) {
        if (tid < 128) sm[ALO + tid] = al[tid];
    }

    float acc[2][4][4];
#pragma unroll
    for (int mi = 0; mi < 2; mi++)
#pragma unroll
        for (int ni = 0; ni < 4; ni++)
#pragma unroll
            for (int j = 0; j < 4; j++) acc[mi][ni][j] = 0.f;

    for (int it = 0; it < nIter; it++) {
        CP_WAIT2();
        __syncthreads();

        const int stg = it & (S - 1);
        const float* as = AsF + stg * ASTG;
        const float* bs = BsF + stg * BSTG;
#pragma unroll
        for (int ks = 0; ks < 2; ks++) {
            const int kbase = ks * 8;
            float sc0 = 1.f, sc1 = 1.f, sh0 = 0.f, sh1 = 0.f;
            if (AAFF) {
                int kg = (it << 4) + kbase + qk;
                sc0 = sm[SCA + kg]; sh0 = sm[SHA + kg];
                sc1 = sm[SCA + kg + 4]; sh1 = sm[SHA + kg + 4];
            }
            uint32_t a[2][4];
#pragma unroll
            for (int mi = 0; mi < 2; mi++) {
                if (AHALF) {
                    const __half* ap = (const __half*)as + (m0 + mi * 16 + qrow) * 24 + kbase + qk;
                    float f0 = __half2float(ap[0]);
                    float f1 = __half2float(ap[8 * 24]);
                    float f2 = __half2float(ap[4]);
                    float f3 = __half2float(ap[8 * 24 + 4]);
                    if (AAFF) {
                        f0 = to_tf32(fmaf(f0, sc0, sh0));
                        f1 = to_tf32(fmaf(f1, sc0, sh0));
                        f2 = to_tf32(fmaf(f2, sc1, sh1));
                        f3 = to_tf32(fmaf(f3, sc1, sh1));
                    }
                    a[mi][0] = __float_as_uint(f0);
                    a[mi][1] = __float_as_uint(f1);
                    a[mi][2] = __float_as_uint(f2);
                    a[mi][3] = __float_as_uint(f3);
                } else {
                    const float* ap = as + (m0 + mi * 16 + qrow) * 20 + kbase + qk;
                    if (AAFF) {
                        a[mi][0] = __float_as_uint(to_tf32(fmaf(ap[0], sc0, sh0)));
                        a[mi][1] = __float_as_uint(to_tf32(fmaf(ap[8 * 20], sc0, sh0)));
                        a[mi][2] = __float_as_uint(to_tf32(fmaf(ap[4], sc1, sh1)));
                        a[mi][3] = __float_as_uint(to_tf32(fmaf(ap[8 * 20 + 4], sc1, sh1)));
                    } else {
                        a[mi][0] = __float_as_uint(to_tf32(ap[0]));
                        a[mi][1] = __float_as_uint(to_tf32(ap[8 * 20]));
                        a[mi][2] = __float_as_uint(to_tf32(ap[4]));
                        a[mi][3] = __float_as_uint(to_tf32(ap[8 * 20 + 4]));
                    }
                }
            }
            uint32_t b[4][2];
#pragma unroll
            for (int ni = 0; ni < 4; ni++) {
                const float* bp = bs + (kbase + qk) * 136 + n0 + ni * 8 + qrow;
                b[ni][0] = __float_as_uint(bp[0]);
                b[ni][1] = __float_as_uint(bp[4 * 136]);
            }
#pragma unroll
            for (int mi = 0; mi < 2; mi++)
#pragma unroll
                for (int ni = 0; ni < 4; ni++) MMA_TF32(acc[mi][ni], a[mi], b[ni]);
        }

        const int nx = it + S - 1;
        if (nx < nIter) {
            const int s = nx & (S - 1);
            const int kt = nx << 4;
            if (AHALF) {
                if (tid < 256)
                    cp16(asmb + (uint32_t)s * (ASTG * 4u) + (uint32_t)(arowH * 24 + asegH) * 2u,
                         AsrcH + kt, aokH);
            } else {
                cp16(asmb + (uint32_t)s * (ASTG * 4u) + (uint32_t)(arowF * 20 + asegF) * 4u,
                     AsrcF + kt, aokF);
            }
            cp16(bdst + (uint32_t)(s * BSTG) * 4u, Bsrc + (size_t)kt * Kcols, true);
        }
        CP_COMMIT();
    }

    // epilogue
    float s0[4], s1[4], q0[4], q1[4];
    if (BN) {
#pragma unroll
        for (int ni = 0; ni < 4; ni++) { s0[ni] = 0.f; s1[ni] = 0.f; q0[ni] = 0.f; q1[ni] = 0.f; }
    }
#pragma unroll
    for (int mi = 0; mi < 2; mi++) {
#pragma unroll
        for (int half = 0; half < 2; half++) {
            int r = bm + m0 + mi * 16 + qrow + half * 8;
            bool rok = r < Nrows;
            float pd = 0.f;
#pragma unroll
            for (int ni = 0; ni < 4; ni++) {
                int gcl = n0 + ni * 8 + qk * 2;
                int gc = bn + gcl;
                float v0 = acc[mi][ni][half * 2 + 0];
                float v1 = acc[mi][ni][half * 2 + 1];
                if (BIAS) {
                    v0 += bias[gc];
                    v1 += bias[gc + 1];
                }
                if (RELU) {
                    v0 = fmaxf(v0, 0.f);
                    v1 = fmaxf(v1, 0.f);
                }
                if (!DEC && rok) {
                    if (CHALF) {
                        *(__half2*)((__half*)C + (size_t)r * ldc + gc) = __floats2half2_rn(v0, v1);
                    } else {
                        *(float2*)(C + (size_t)r * ldc + gc) = make_float2(v0, v1);
                    }
                }
                if (BN && rok) {
                    s0[ni] += v0; q0[ni] += v0 * v0;
                    s1[ni] += v1; q1[ni] += v1 * v1;
                }
                if (DEC) pd = fmaf(v0, sm[ALO + gcl], fmaf(v1, sm[ALO + gcl + 1], pd));
                if (ELER) {
                    int h = (n0 >> 3) + ni;
                    float p = fmaf(v0, sm[ALO + h * 8 + qk * 2], v1 * sm[ALO + h * 8 + qk * 2 + 1]);
                    float q = fmaf(v0, sm[ARO + h * 8 + qk * 2], v1 * sm[ARO + h * 8 + qk * 2 + 1]);
                    p += __shfl_xor_sync(0xffffffffu, p, 1);
                    p += __shfl_xor_sync(0xffffffffu, p, 2);
                    q += __shfl_xor_sync(0xffffffffu, q, 1);
                    q += __shfl_xor_sync(0xffffffffu, q, 2);
                    if ((lane & 3) == 0 && rok) {
                        g_el[r * 16 + h] = p;
                        g_er[r * 16 + h] = q;
                    }
                }
            }
            if (DEC) {
                pd += __shfl_xor_sync(0xffffffffu, pd, 1);
                pd += __shfl_xor_sync(0xffffffffu, pd, 2);
                if ((lane & 3) == 0 && rok)
                    atomicAdd(C + r, pd + 0.25f * ar[0]);
            }
        }
    }

    if (BN) {
#pragma unroll
        for (int ni = 0; ni < 4; ni++) {
            s0[ni] += __shfl_xor_sync(0xffffffffu, s0[ni], 4);
            s0[ni] += __shfl_xor_sync(0xffffffffu, s0[ni], 8);
            s0[ni] += __shfl_xor_sync(0xffffffffu, s0[ni], 16);
            s1[ni] += __shfl_xor_sync(0xffffffffu, s1[ni], 4);
            s1[ni] += __shfl_xor_sync(0xffffffffu, s1[ni], 8);
            s1[ni] += __shfl_xor_sync(0xffffffffu, s1[ni], 16);
            q0[ni] += __shfl_xor_sync(0xffffffffu, q0[ni], 4);
            q0[ni] += __shfl_xor_sync(0xffffffffu, q0[ni], 8);
            q0[ni] += __shfl_xor_sync(0xffffffffu, q0[ni], 16);
            q1[ni] += __shfl_xor_sync(0xffffffffu, q1[ni], 4);
            q1[ni] += __shfl_xor_sync(0xffffffffu, q1[ni], 8);
            q1[ni] += __shfl_xor_sync(0xffffffffu, q1[ni], 16);
        }
        __syncthreads();
        if (lane < 4) {
            int mg = wid & 3;
#pragma unroll
            for (int ni = 0; ni < 4; ni++) {
                int c = n0 + ni * 8 + lane * 2;
                sm[mg * 128 + c] = s0[ni];
                sm[mg * 128 + c + 1] = s1[ni];
                sm[512 + mg * 128 + c] = q0[ni];
                sm[512 + mg * 128 + c + 1] = q1[ni];
            }
        }
        __syncthreads();
        if (tid < 256) {
            int c = tid & 127, st = tid >> 7;
            float v = sm[st * 512 + c] + sm[st * 512 + 128 + c] +
                      sm[st * 512 + 256 + c] + sm[st * 512 + 384 + c];
            atomicAdd(bnslot + st * 128 + c, v);
        }
    }
}

// ---------------- fused FF kernel (R10 layout; C stored fp16) ----------------
__global__ void __launch_bounds__(512, 1) k_ff(
    const float* __restrict__ y,
    const float* __restrict__ W1, const float* __restrict__ b1v,
    const float* __restrict__ W2, const float* __restrict__ b2v,
    __half* __restrict__ C, int ldc,
    const float* __restrict__ slot1, const float* __restrict__ g1, const float* __restrict__ bb1,
    float* __restrict__ bnslot) {
    constexpr int YOFF = 0;
    constexpr int TOFF = 16896;
    constexpr int WOFF = TOFF + 33280;
    constexpr int SCA = WOFF + 4352;
    constexpr int SHA = SCA + 128;
    constexpr int SB1 = SHA + 128;
    extern __shared__ float sm[];
    const int tid = threadIdx.x, lane = tid & 31, wid = tid >> 5;
    const int bm = blockIdx.x * 128;
    const int qrow = lane >> 2, qk = lane & 3;
    const uint32_t smb = smem_to_u32(sm);

    {
        int row = tid >> 2, cb = (tid & 3) * 32;
        bool ok = (bm + row) < Nn;
        const float* srcp = y + (size_t)(bm + row) * 128 + cb;
        uint32_t dst = smb + (uint32_t)(YOFF + row * 132 + cb) * 4u;
#pragma unroll
        for (int j = 0; j < 8; j++) cp16(dst + j * 16u, srcp + j * 4, ok);
    }
    {
        int r = tid >> 6, c = (tid & 63) * 4;
        cp16(smb + (uint32_t)(WOFF + r * 264 + c) * 4u, W1 + r * 256 + c, true);
    }
    CP_COMMIT();
    const float invN = 1.f / (float)Nn;
    if (tid < 128) {
        float mu = slot1[tid] * invN;
        float var = slot1[tid + 128] * invN - mu * mu;
        float sc = g1[tid] * rsqrtf(var + EPSBN);
        sm[SCA + tid] = sc;
        sm[SHA + tid] = bb1[tid] - mu * sc;
    } else if (tid < 384) {
        sm[SB1 + tid - 128] = b1v[tid - 128];
    }
    CP_WAIT0();
    __syncthreads();

    const int m0A = (wid & 3) * 32, n0A = (wid >> 2) * 64;
    float accA[2][8][4];
#pragma unroll
    for (int mi = 0; mi < 2; mi++)
#pragma unroll
        for (int ni = 0; ni < 8; ni++)
#pragma unroll
            for (int j = 0; j < 4; j++) accA[mi][ni][j] = 0.f;

    for (int it = 0; it < 16; it++) {
        if (it + 1 < 16) {
            int r = tid >> 6, c = (tid & 63) * 4;
            cp16(smb + (uint32_t)(WOFF + ((it + 1) & 1) * 2112 + r * 264 + c) * 4u,
                 W1 + (size_t)((it + 1) * 8 + r) * 256 + c, true);
        }
        CP_COMMIT();
        CP_WAIT1();
        __syncthreads();
        const float* bs = sm + WOFF + (it & 1) * 2112;
        int kg = it * 8 + qk;
        float sc0 = sm[SCA + kg], sh0 = sm[SHA + kg];
        float sc1 = sm[SCA + kg + 4], sh1 = sm[SHA + kg + 4];
        uint32_t a[2][4];
#pragma unroll
        for (int mi = 0; mi < 2; mi++) {
            const float* ap = sm + YOFF + (m0A + mi * 16 + qrow) * 132 + it * 8 + qk;
            a[mi][0] = __float_as_uint(to_tf32(fmaf(ap[0], sc0, sh0)));
            a[mi][1] = __float_as_uint(to_tf32(fmaf(ap[8 * 132], sc0, sh0)));
            a[mi][2] = __float_as_uint(to_tf32(fmaf(ap[4], sc1, sh1)));
            a[mi][3] = __float_as_uint(to_tf32(fmaf(ap[8 * 132 + 4], sc1, sh1)));
        }
#pragma unroll
        for (int ni = 0; ni < 8; ni++) {
            uint32_t b[2];
            const float* bp = bs + qk * 264 + n0A + ni * 8 + qrow;
            b[0] = __float_as_uint(bp[0]);
            b[1] = __float_as_uint(bp[4 * 264]);
#pragma unroll
            for (int mi = 0; mi < 2; mi++) MMA_TF32(accA[mi][ni], a[mi], b);
        }
        __syncthreads();
    }

#pragma unroll
    for (int mi = 0; mi < 2; mi++) {
#pragma unroll
        for (int half = 0; half < 2; half++) {
            int rl = m0A + mi * 16 + half * 8 + qrow;
#pragma unroll
            for (int ni = 0; ni < 8; ni++) {
                int c = n0A + ni * 8 + qk * 2;
                float v0 = fmaxf(accA[mi][ni][half * 2 + 0] + sm[SB1 + c], 0.f);
                float v1 = fmaxf(accA[mi][ni][half * 2 + 1] + sm[SB1 + c + 1], 0.f);
                *(float2*)&sm[TOFF + rl * 260 + c] = make_float2(v0, v1);
            }
        }
    }
    __syncthreads();

    const int m0B = (wid & 3) * 32, n0B = (wid >> 2) * 32;
    float accB[2][4][4];
#pragma unroll
    for (int mi = 0; mi < 2; mi++)
#pragma unroll
        for (int ni = 0; ni < 4; ni++)
#pragma unroll
            for (int j = 0; j < 4; j++) accB[mi][ni][j] = 0.f;

    {
        int r = tid >> 5, c = (tid & 31) * 4;
        cp16(smb + (uint32_t)(WOFF + r * 136 + c) * 4u, W2 + r * 128 + c, true);
    }
    CP_COMMIT();

    for (int it = 0; it < 16; it++) {
        if (it + 1 < 16) {
            int r = tid >> 5, c = (tid & 31) * 4;
            cp16(smb + (uint32_t)(WOFF + ((it + 1) & 1) * 2176 + r * 136 + c) * 4u,
                 W2 + (size_t)((it + 1) * 16 + r) * 128 + c, true);
        }
        CP_COMMIT();
        CP_WAIT1();
        __syncthreads();
        const float* bs = sm + WOFF + (it & 1) * 2176;
#pragma unroll
        for (int ks = 0; ks < 2; ks++) {
            int kb = it * 16 + ks * 8;
            uint32_t a[2][4];
#pragma unroll
            for (int mi = 0; mi < 2; mi++) {
                const float* ap = sm + TOFF + (m0B + mi * 16 + qrow) * 260 + kb + qk;
                a[mi][0] = __float_as_uint(to_tf32(ap[0]));
                a[mi][1] = __float_as_uint(to_tf32(ap[8 * 260]));
                a[mi][2] = __float_as_uint(to_tf32(ap[4]));
                a[mi][3] = __float_as_uint(to_tf32(ap[8 * 260 + 4]));
            }
#pragma unroll
            for (int ni = 0; ni < 4; ni++) {
                uint32_t b[2];
                const float* bp = bs + (ks * 8 + qk) * 136 + n0B + ni * 8 + qrow;
                b[0] = __float_as_uint(bp[0]);
                b[1] = __float_as_uint(bp[4 * 136]);
#pragma unroll
                for (int mi = 0; mi < 2; mi++) MMA_TF32(accB[mi][ni], a[mi], b);
            }
        }
        __syncthreads();
    }

    float s0[4], s1[4], q0[4], q1[4];
#pragma unroll
    for (int ni = 0; ni < 4; ni++) { s0[ni] = 0.f; s1[ni] = 0.f; q0[ni] = 0.f; q1[ni] = 0.f; }
#pragma unroll
    for (int mi = 0; mi < 2; mi++) {
#pragma unroll
        for (int half = 0; half < 2; half++) {
            int rl = m0B + mi * 16 + half * 8 + qrow;
            int r = bm + rl;
            bool rok = r < Nn;
#pragma unroll
            for (int ni = 0; ni < 4; ni++) {
                int gc = n0B + ni * 8 + qk * 2;
                float yv0 = fmaf(sm[YOFF + rl * 132 + gc], sm[SCA + gc], sm[SHA + gc]);
                float yv1 = fmaf(sm[YOFF + rl * 132 + gc + 1], sm[SCA + gc + 1], sm[SHA + gc + 1]);
                float v0 = accB[mi][ni][half * 2 + 0] + b2v[gc] + yv0;
                float v1 = accB[mi][ni][half * 2 + 1] + b2v[gc + 1] + yv1;
                if (rok) {
                    *(__half2*)(C + (size_t)r * ldc + gc) = __floats2half2_rn(v0, v1);
                    s0[ni] += v0; q0[ni] += v0 * v0;
                    s1[ni] += v1; q1[ni] += v1 * v1;
                }
            }
        }
    }
#pragma unroll
    for (int ni = 0; ni < 4; ni++) {
        s0[ni] += __shfl_xor_sync(0xffffffffu, s0[ni], 4);
        s0[ni] += __shfl_xor_sync(0xffffffffu, s0[ni], 8);
        s0[ni] += __shfl_xor_sync(0xffffffffu, s0[ni], 16);
        s1[ni] += __shfl_xor_sync(0xffffffffu, s1[ni], 4);
        s1[ni] += __shfl_xor_sync(0xffffffffu, s1[ni], 8);
        s1[ni] += __shfl_xor_sync(0xffffffffu, s1[ni], 16);
        q0[ni] += __shfl_xor_sync(0xffffffffu, q0[ni], 4);
        q0[ni] += __shfl_xor_sync(0xffffffffu, q0[ni], 8);
        q0[ni] += __shfl_xor_sync(0xffffffffu, q0[ni], 16);
        q1[ni] += __shfl_xor_sync(0xffffffffu, q1[ni], 4);
        q1[ni] += __shfl_xor_sync(0xffffffffu, q1[ni], 8);
        q1[ni] += __shfl_xor_sync(0xffffffffu, q1[ni], 16);
    }
    __syncthreads();
    if (lane < 4) {
        int mg = wid & 3;
#pragma unroll
        for (int ni = 0; ni < 4; ni++) {
            int c = n0B + ni * 8 + lane * 2;
            sm[mg * 128 + c] = s0[ni];
            sm[mg * 128 + c + 1] = s1[ni];
            sm[512 + mg * 128 + c] = q0[ni];
            sm[512 + mg * 128 + c + 1] = q1[ni];
        }
    }
    __syncthreads();
    if (tid < 256) {
        int c = tid & 127, st = tid >> 7;
        float v = sm[st * 512 + c] + sm[st * 512 + 128 + c] +
                  sm[st * 512 + 256 + c] + sm[st * 512 + 384 + c];
        atomicAdd(bnslot + st * 128 + c, v);
    }
}

// ---------------- GAT aggregate: half z + half hres, fused BN1 stats ----------------
__global__ void k_gat(const __half* __restrict__ z,
                      const __half* __restrict__ hres, int ldh,
                      const float* __restrict__ bias, float* __restrict__ y,
                      float* __restrict__ bnslot,
                      const float* __restrict__ slotPrev,
                      const float* __restrict__ gPrev, const float* __restrict__ bPrev) {
    __shared__ float sbn[2][8][128];
    int gw = (blockIdx.x * blockDim.x + threadIdx.x) >> 5;
    int lane = threadIdx.x & 31;
    int wid = threadIdx.x >> 5;
    float4 o = make_float4(0.f, 0.f, 0.f, 0.f);
    if (gw < Nn) {
        int head = lane >> 1;
        int beg = g_rowptr[gw], end = g_rowptr[gw + 1];
        float er_h = g_er[gw * 16 + head];
        const uint2* z2 = (const uint2*)z;

        float den = 0.f;
        float4 acc = make_float4(0.f, 0.f, 0.f, 0.f);
        int i = beg;
        for (; i + 1 < end; i += 2) {
            int sA = g_srcs[i];
            int sB = g_srcs[i + 1];
            float eA = g_el[sA * 16 + head];
            float eB = g_el[sB * 16 + head];
            uint2 rA = z2[(size_t)sA * 32 + lane];
            uint2 rB = z2[(size_t)sB * 32 + lane];
            eA += er_h;
            eB += er_h;
            eA = eA > 0.f ? eA : SLOPE * eA;
            eB = eB > 0.f ? eB : SLOPE * eB;
            float wA = __expf(eA);
            float wB = __expf(eB);
            den += wA + wB;
            float2 a0 = __half22float2(*(__half2*)&rA.x);
            float2 a1 = __half22float2(*(__half2*)&rA.y);
            float2 b0 = __half22float2(*(__half2*)&rB.x);
            float2 b1 = __half22float2(*(__half2*)&rB.y);
            acc.x += wA * a0.x + wB * b0.x;
            acc.y += wA * a0.y + wB * b0.y;
            acc.z += wA * a1.x + wB * b1.x;
            acc.w += wA * a1.y + wB * b1.y;
        }
        if (i < end) {
            int s = g_srcs[i];
            float e = g_el[s * 16 + head] + er_h;
            uint2 r = z2[(size_t)s * 32 + lane];
            e = e > 0.f ? e : SLOPE * e;
            float w = __expf(e);
            den += w;
            float2 a0 = __half22float2(*(__half2*)&r.x);
            float2 a1 = __half22float2(*(__half2*)&r.y);
            acc.x += w * a0.x; acc.y += w * a0.y;
            acc.z += w * a1.x; acc.w += w * a1.y;
        }
        float dinv = den > 0.f ? 1.f / den : 1.f;
        float4 b4 = ((const float4*)bias)[lane];
        uint2 hr = *(const uint2*)(hres + (size_t)gw * ldh + lane * 4);
        float2 h01 = __half22float2(*(__half2*)&hr.x);
        float2 h23 = __half22float2(*(__half2*)&hr.y);
        float4 h4 = make_float4(h01.x, h01.y, h23.x, h23.y);
        if (slotPrev != nullptr) {
            const float invN = 1.f / (float)Nn;
            int c = lane * 4;
#pragma unroll
            for (int j = 0; j < 4; j++) {
                float mu = slotPrev[c + j] * invN;
                float var = slotPrev[128 + c + j] * invN - mu * mu;
                float sc = gPrev[c + j] * rsqrtf(var + EPSBN);
                float sh = bPrev[c + j] - mu * sc;
                float* hp = (&h4.x) + j;
                *hp = fmaf(*hp, sc, sh);
            }
        }
        o.x = acc.x * dinv + b4.x + h4.x;
        o.y = acc.y * dinv + b4.y + h4.y;
        o.z = acc.z * dinv + b4.z + h4.z;
        o.w = acc.w * dinv + b4.w + h4.w;
        ((float4*)y)[(size_t)gw * 32 + lane] = o;
    }
    ((float4*)sbn[0][wid])[lane] = o;
    ((float4*)sbn[1][wid])[lane] = make_float4(o.x * o.x, o.y * o.y, o.z * o.z, o.w * o.w);
    __syncthreads();
    int c = threadIdx.x & 127, st = threadIdx.x >> 7;
    float v = 0.f;
#pragma unroll
    for (int w = 0; w < 8; w++) v += sbn[st][w][c];
    atomicAdd(bnslot + st * 128 + c, v);
}

// ---------------- launch ----------------
extern "C" void kernel_launch(void* const* d_in, const int* in_sizes, int n_in,
                              void* d_out, int out_size) {
    const float* x      = (const float*)d_in[0];
    const int*   src    = (const int*)d_in[1];
    const int*   dst    = (const int*)d_in[2];
    const float* emb_W1 = (const float*)d_in[3];
    const float* emb_b1 = (const float*)d_in[4];
    const float* emb_W2 = (const float*)d_in[5];
    const float* emb_b2 = (const float*)d_in[6];
    const float* emb_Ws = (const float*)d_in[7];
    const float* emb_bs = (const float*)d_in[8];
    const float* gat_W  = (const float*)d_in[9];
    const float* gat_al = (const float*)d_in[10];
    const float* gat_ar = (const float*)d_in[11];
    const float* gat_b  = (const float*)d_in[12];
    const float* bn1_g  = (const float*)d_in[13];
    const float* bn1_b  = (const float*)d_in[14];
    const float* ff_W1  = (const float*)d_in[15];
    const float* ff_b1  = (const float*)d_in[16];
    const float* ff_W2  = (const float*)d_in[17];
    const float* ff_b2  = (const float*)d_in[18];
    const float* bn2_g  = (const float*)d_in[19];
    const float* bn2_b  = (const float*)d_in[20];
    const float* dec_W1 = (const float*)d_in[21];
    const float* dec_b1 = (const float*)d_in[22];
    const float* dec_W2 = (const float*)d_in[23];
    const float* dec_b2 = (const float*)d_in[24];

    void* p;
    float *zb, *yb, *bns, *W;
    __half* HC;
    int* degp;
    cudaGetSymbolAddress(&p, g_HC);    HC = (__half*)p;
    cudaGetSymbolAddress(&p, g_z);     zb = (float*)p;
    cudaGetSymbolAddress(&p, g_y);     yb = (float*)p;
    cudaGetSymbolAddress(&p, g_bnsum); bns = (float*)p;
    cudaGetSymbolAddress(&p, g_deg);   degp = (int*)p;
    cudaGetSymbolAddress(&p, g_W);     W = (float*)p;

    float* Wg = W;
    float* Wf1 = W + 65536;
    float* Wf2 = W + 196608;
    float* Wd = W + 327680;
    float* We2 = W + 409600;

    const int SMEM = 20736 * 4;        // 82944 B
    const int SMEM_FF = 55040 * 4;     // 220160 B
    static bool attrDone = false;
    if (!attrDone) {
        cudaFuncSetAttribute(k_emb, cudaFuncAttributeMaxDynamicSharedMemorySize, SMEM);
        cudaFuncSetAttribute(k_tgemm<0, 0, 0, 1, 0, 0, 1, 1>, cudaFuncAttributeMaxDynamicSharedMemorySize, SMEM);
        cudaFuncSetAttribute(k_tgemm<0, 0, 0, 1, 1, 0, 1, 1>, cudaFuncAttributeMaxDynamicSharedMemorySize, SMEM);
        cudaFuncSetAttribute(k_tgemm<1, 1, 0, 0, 2, 1, 1, 0>, cudaFuncAttributeMaxDynamicSharedMemorySize, SMEM);
        cudaFuncSetAttribute(k_ff, cudaFuncAttributeMaxDynamicSharedMemorySize, SMEM_FF);
        attrDone = true;
    }

    cudaMemsetAsync(bns, 0, 8 * 256 * sizeof(float));
    cudaMemsetAsync(degp, 0, Nn * sizeof(int));
    cudaMemsetAsync(d_out, 0, (size_t)out_size * sizeof(float));

    k_cvt_all<<<(425984 + 255) / 256, 256>>>(gat_W, ff_W1, ff_W2, dec_W1, emb_W2);
    k_count<<<(Ee + 255) / 256, 256>>>(dst);

    const int gx = (Nn + 127) / 128;  // 782
    dim3 grid1(gx, 1);
    const int warpBlocks = (Nn * 32 + 255) / 256;

    // fused embed -> HC block 0 (fp16)
    k_emb<<<grid1, 512, SMEM>>>(x, We2, emb_W1, emb_b1, emb_Ws, emb_bs, emb_b2, HC, 640);

    const int nb = (Nn + 1023) / 1024;
    k_scan1<<<nb, 1024>>>();
    k_scan2<<<1, 128>>>(nb);
    k_finalize<<<(Nn + 255) / 256, 256>>>();
    k_fill<<<(Ee + 255) / 256, 256>>>(dst, src);

    for (int l = 0; l < 4; l++) {
        const __half* h = HC + (size_t)l * 128;
        float* slot1 = bns + (size_t)(2 * l) * 256;
        float* slot2 = bns + (size_t)(2 * l + 1) * 256;
        const float* slotP = (l > 0) ? (bns + (size_t)(2 * (l - 1) + 1) * 256) : nullptr;
        const float* gP = (l > 0) ? (bn2_g + (l - 1) * 128) : nullptr;
        const float* bP = (l > 0) ? (bn2_b + (l - 1) * 128) : nullptr;

        // z(half) = BN2prev(h:half) @ gat_W[l]  (+ fused el/er)
        if (l == 0) {
            k_tgemm<0, 0, 0, 1, 0, 0, 1, 1><<<grid1, 512, SMEM>>>(
                (const float*)h, 640, Wg, nullptr, zb, 128, Nn, 128, 128, nullptr,
                nullptr, nullptr, nullptr, gat_al, gat_ar);
        } else {
            k_tgemm<0, 0, 0, 1, 1, 0, 1, 1><<<grid1, 512, SMEM>>>(
                (const float*)h, 640, Wg + (size_t)l * 16384, nullptr, zb, 128, Nn, 128, 128, nullptr,
                slotP, gP, bP, gat_al + l * 128, gat_ar + l * 128);
        }
        k_gat<<<warpBlocks, 256>>>((const __half*)zb, h, 640, gat_b + l * 128, yb, slot1,
                                   slotP, gP, bP);
        k_ff<<<grid1, 512, SMEM_FF>>>(
            yb, Wf1 + (size_t)l * 32768, ff_b1 + l * 256,
            Wf2 + (size_t)l * 32768, ff_b2 + l * 128,
            HC + (size_t)(l + 1) * 128, 640,
            slot1, bn1_g + l * 128, bn1_b + l * 128, slot2);
    }

    // decoder: relu(affine_concat(HC:half) @ Wd + b1) . W2 + b2
    k_tgemm<1, 1, 0, 0, 2, 1, 1, 0><<<grid1, 512, SMEM>>>(
        (const float*)HC, 640, Wd, dec_b1, (float*)d_out, 1, Nn, 640, 128, nullptr,
        nullptr, bn2_g, bn2_b, dec_W2, dec_b2);
}

// round 16
// speedup vs baseline: 1.0885x; 1.0159x over previous
#include <cuda_runtime.h>
#include <cuda_fp16.h>
#include <cstdint>

#define Nn 100000
#define Ee 600000
#define EPSBN 1e-5f
#define SLOPE 0.2f

// ---------------- scratch ----------------
__device__ __half g_HC[(size_t)Nn * 640];
__device__ float g_z[(size_t)Nn * 128];    // used as __half[Nn*128]
__device__ float g_y[(size_t)Nn * 128];
__device__ float g_el[(size_t)Nn * 16];
__device__ float g_er[(size_t)Nn * 16];
__device__ float g_bnsum[8 * 256];
__device__ int   g_deg[Nn];
__device__ int   g_scan[Nn];
__device__ int   g_bsum[128];
__device__ int   g_rowptr[Nn + 1];
__device__ int   g_cursor[Nn];
__device__ int   g_srcs[Ee];
__device__ float g_W[425984];

__device__ __forceinline__ float to_tf32(float x) {
    float r;
    asm("cvt.rna.tf32.f32 %0, %1;" : "=f"(r) : "f"(x));
    return r;
}
__device__ __forceinline__ uint32_t smem_to_u32(const void* p) {
    uint32_t a;
    asm("{ .reg .u64 t; cvta.to.shared.u64 t, %1; cvt.u32.u64 %0, t; }" : "=r"(a) : "l"(p));
    return a;
}
__device__ __forceinline__ void cp16(uint32_t dst, const void* src, bool ok) {
    int sz = ok ? 16 : 0;
    asm volatile("cp.async.cg.shared.global [%0], [%1], 16, %2;"
                 :: "r"(dst), "l"(src), "r"(sz) : "memory");
}
#define CP_COMMIT() asm volatile("cp.async.commit_group;" ::: "memory")
#define CP_WAIT2() asm volatile("cp.async.wait_group 2;" ::: "memory")
#define CP_WAIT1() asm volatile("cp.async.wait_group 1;" ::: "memory")
#define CP_WAIT0() asm volatile("cp.async.wait_group 0;" ::: "memory")

#define MMA_TF32(d, av, bv)                                               \
    asm volatile(                                                         \
        "mma.sync.aligned.m16n8k8.row.col.f32.tf32.tf32.f32 "             \
        "{%0,%1,%2,%3},{%4,%5,%6,%7},{%8,%9},{%0,%1,%2,%3};"              \
        : "+f"((d)[0]), "+f"((d)[1]), "+f"((d)[2]), "+f"((d)[3])          \
        : "r"((av)[0]), "r"((av)[1]), "r"((av)[2]), "r"((av)[3]),         \
          "r"((bv)[0]), "r"((bv)[1]))

// ---------------- CSR build ----------------
__global__ void k_count(const int* __restrict__ dst) {
    int e = blockIdx.x * blockDim.x + threadIdx.x;
    if (e < Ee) atomicAdd(&g_deg[dst[e]], 1);
}
__global__ void k_scan1() {
    __shared__ int s[1024];
    int i = blockIdx.x * 1024 + threadIdx.x;
    int v = (i < Nn) ? g_deg[i] : 0;
    s[threadIdx.x] = v;
    __syncthreads();
    for (int off = 1; off < 1024; off <<= 1) {
        int t = (threadIdx.x >= off) ? s[threadIdx.x - off] : 0;
        __syncthreads();
        s[threadIdx.x] += t;
        __syncthreads();
    }
    if (i < Nn) g_scan[i] = s[threadIdx.x];
    if (threadIdx.x == 1023) g_bsum[blockIdx.x] = s[1023];
}
__global__ void k_scan2(int nb) {
    __shared__ int s[128];
    int v = (threadIdx.x < nb) ? g_bsum[threadIdx.x] : 0;
    s[threadIdx.x] = v;
    __syncthreads();
    for (int off = 1; off < 128; off <<= 1) {
        int t = (threadIdx.x >= off) ? s[threadIdx.x - off] : 0;
        __syncthreads();
        s[threadIdx.x] += t;
        __syncthreads();
    }
    g_bsum[threadIdx.x] = (threadIdx.x == 0) ? 0 : s[threadIdx.x - 1];
}
__global__ void k_finalize() {
    int i = blockIdx.x * blockDim.x + threadIdx.x;
    if (i >= Nn) return;
    int incl = g_scan[i] + g_bsum[i >> 10];
    g_rowptr[i + 1] = incl;
    g_cursor[i] = incl - g_deg[i];
    if (i == 0) g_rowptr[0] = 0;
}
__global__ void k_fill(const int* __restrict__ dst, const int* __restrict__ src) {
    int e = blockIdx.x * blockDim.x + threadIdx.x;
    if (e < Ee) {
        int d = dst[e];
        int p = atomicAdd(&g_cursor[d], 1);
        g_srcs[p] = src[e];
    }
}

// ---------------- all-weight cvt ----------------
__global__ void k_cvt_all(const float* __restrict__ gat_W, const float* __restrict__ ff_W1,
                          const float* __restrict__ ff_W2, const float* __restrict__ dec_W1,
                          const float* __restrict__ emb_W2) {
    int i = blockIdx.x * blockDim.x + threadIdx.x;
    if (i >= 425984) return;
    float v;
    if (i < 65536) v = gat_W[i];
    else if (i < 196608) v = ff_W1[i - 65536];
    else if (i < 327680) v = ff_W2[i - 196608];
    else if (i < 409600) v = dec_W1[i - 327680];
    else v = emb_W2[i - 409600];
    g_W[i] = to_tf32(v);
}

// ---------------- fused embed kernel ----------------
__global__ void __launch_bounds__(512, 2) k_emb(
    const float* __restrict__ x, const float* __restrict__ B,
    const float* __restrict__ W1, const float* __restrict__ b1,
    const float* __restrict__ Ws, const float* __restrict__ bs,
    const float* __restrict__ b2,
    __half* __restrict__ C, int ldc) {
    constexpr int S = 4;
    constexpr int ASTG = 128 * 20;
    constexpr int BSTG = 16 * 136;
    constexpr int W1O = S * ASTG + S * BSTG;
    constexpr int B1O = W1O + 256;
    extern __shared__ float sm[];
    float* AsF = sm;
    float* BsF = sm + S * ASTG;
    const int tid = threadIdx.x, lane = tid & 31, wid = tid >> 5;
    const int bm = blockIdx.x * 128;
    const int m0 = (wid & 3) * 32, n0 = (wid >> 2) * 32;
    const int qrow = lane >> 2, qk = lane & 3;
    const int arow = tid >> 2, aseg = (tid & 3) * 4;
    const int brow = tid >> 5, bcol = (tid & 31) * 4;
    const bool aok = (bm + arow) < Nn;
    float x0 = 0.f, x1 = 0.f;
    if (aok) {
        x0 = x[(size_t)(bm + arow) * 2];
        x1 = x[(size_t)(bm + arow) * 2 + 1];
    }
    if (tid < 256) sm[W1O + tid] = W1[tid];
    else if (tid < 384) sm[B1O + tid - 256] = b1[tid - 256];

    const float* Bsrc = B + (size_t)brow * 128 + bcol;
    const uint32_t bdst = smem_to_u32(BsF) + (uint32_t)(brow * 136 + bcol) * 4u;
#pragma unroll
    for (int s = 0; s < S - 1; s++) {
        cp16(bdst + (uint32_t)(s * BSTG) * 4u, Bsrc + (size_t)(s << 4) * 128, true);
        CP_COMMIT();
    }
    __syncthreads();
#pragma unroll
    for (int s = 0; s < S - 1; s++) {
        float4 v;
#pragma unroll
        for (int j = 0; j < 4; j++) {
            int k = (s << 4) + aseg + j;
            float tv = fmaf(x0, sm[W1O + k], fmaf(x1, sm[W1O + 128 + k], sm[B1O + k]));
            (&v.x)[j] = tv > 0.f ? tv : 0.f;
        }
        *(float4*)&AsF[s * ASTG + arow * 20 + aseg] = v;
    }

    float acc[2][4][4];
#pragma unroll
    for (int mi = 0; mi < 2; mi++)
#pragma unroll
        for (int ni = 0; ni < 4; ni++)
#pragma unroll
            for (int j = 0; j < 4; j++) acc[mi][ni][j] = 0.f;

    const int nIter = 8;
    for (int it = 0; it < nIter; it++) {
        CP_WAIT2();
        __syncthreads();
        const float* as = AsF + (it & 3) * ASTG;
        const float* bs = BsF + (it & 3) * BSTG;
#pragma unroll
        for (int ks = 0; ks < 2; ks++) {
            const int kbase = ks * 8;
            uint32_t a[2][4];
#pragma unroll
            for (int mi = 0; mi < 2; mi++) {
                const float* ap = as + (m0 + mi * 16 + qrow) * 20 + kbase + qk;
                a[mi][0] = __float_as_uint(to_tf32(ap[0]));
                a[mi][1] = __float_as_uint(to_tf32(ap[8 * 20]));
                a[mi][2] = __float_as_uint(to_tf32(ap[4]));
                a[mi][3] = __float_as_uint(to_tf32(ap[8 * 20 + 4]));
            }
            uint32_t b[4][2];
#pragma unroll
            for (int ni = 0; ni < 4; ni++) {
                const float* bp = bs + (kbase + qk) * 136 + n0 + ni * 8 + qrow;
                b[ni][0] = __float_as_uint(bp[0]);
                b[ni][1] = __float_as_uint(bp[4 * 136]);
            }
#pragma unroll
            for (int mi = 0; mi < 2; mi++)
#pragma unroll
                for (int ni = 0; ni < 4; ni++) MMA_TF32(acc[mi][ni], a[mi], b[ni]);
        }
        const int nx = it + S - 1;
        if (nx < nIter) {
            const int s = nx & 3;
            float4 v;
#pragma unroll
            for (int j = 0; j < 4; j++) {
                int k = (nx << 4) + aseg + j;
                float tv = fmaf(x0, sm[W1O + k], fmaf(x1, sm[W1O + 128 + k], sm[B1O + k]));
                (&v.x)[j] = tv > 0.f ? tv : 0.f;
            }
            *(float4*)&AsF[s * ASTG + arow * 20 + aseg] = v;
            cp16(bdst + (uint32_t)(s * BSTG) * 4u, Bsrc + (size_t)(nx << 4) * 128, true);
        }
        CP_COMMIT();
    }

#pragma unroll
    for (int mi = 0; mi < 2; mi++) {
#pragma unroll
        for (int half = 0; half < 2; half++) {
            int r = bm + m0 + mi * 16 + qrow + half * 8;
            if (r >= Nn) continue;
            float x0r = x[(size_t)r * 2], x1r = x[(size_t)r * 2 + 1];
#pragma unroll
            for (int ni = 0; ni < 4; ni++) {
                int gc = n0 + ni * 8 + qk * 2;
                float v0 = acc[mi][ni][half * 2 + 0] +
                           fmaf(x0r, Ws[gc], fmaf(x1r, Ws[128 + gc], bs[gc] + b2[gc]));
                float v1 = acc[mi][ni][half * 2 + 1] +
                           fmaf(x0r, Ws[gc + 1], fmaf(x1r, Ws[128 + gc + 1], bs[gc + 1] + b2[gc + 1]));
                *(__half2*)(C + (size_t)r * ldc + gc) = __floats2half2_rn(v0, v1);
            }
        }
    }
}

// ---------------- generic fused tf32 tensor GEMM ----------------
template <int RELU, int BIAS, int BN, int ELER, int AAFF, int DEC, int AHALF, int CHALF>
__global__ void __launch_bounds__(512, 2) k_tgemm(
    const float* __restrict__ A, int lda,
    const float* __restrict__ B,
    const float* __restrict__ bias,
    float* __restrict__ C, int ldc,
    int Nrows, int Mred, int Kcols, float* bnslot,
    const float* affA, const float* affAg, const float* affAb,
    const float* al, const float* ar) {
    constexpr int S = 4;
    constexpr int ASTG = 128 * 20;
    constexpr int BSTG = 16 * 136;
    constexpr int STGF = S * ASTG + S * BSTG;
    constexpr int SCA = STGF, SHA = SCA + 640;
    constexpr int ALO = SHA + 640, ARO = ALO + 128;
    extern __shared__ float sm[];
    float* AsF = sm;
    float* BsF = sm + S * ASTG;

    const int tid = threadIdx.x;
    const int lane = tid & 31;
    const int wid = tid >> 5;
    const int bm = blockIdx.x * 128;
    const int bn = blockIdx.y * 128;

    const int m0 = (wid & 3) * 32;
    const int n0 = (wid >> 2) * 32;
    const int qrow = lane >> 2;
    const int qk = lane & 3;

    const int arowF = tid >> 2;
    const int asegF = (tid & 3) * 4;
    const int arowH = tid >> 1;
    const int asegH = (tid & 1) * 8;
    const int brow = tid >> 5;
    const int bcol = (tid & 31) * 4;

    const bool aokF = (bm + arowF) < Nrows;
    const bool aokH = (tid < 256) && ((bm + arowH) < Nrows);
    const float* AsrcF = A + (size_t)(bm + arowF) * lda + asegF;
    const __half* AsrcH = (const __half*)A + (size_t)(bm + arowH) * lda + asegH;
    const float* Bsrc = B + (size_t)brow * Kcols + bn + bcol;
    const uint32_t asmb = smem_to_u32(AsF);
    const uint32_t bdst = smem_to_u32(BsF) + (uint32_t)(brow * 136 + bcol) * 4u;

    const int nIter = Mred >> 4;

#pragma unroll
    for (int s = 0; s < S - 1; s++) {
        if (s < nIter) {
            int kt = s << 4;
            if (AHALF) {
                if (tid < 256)
                    cp16(asmb + (uint32_t)s * (ASTG * 4u) + (uint32_t)(arowH * 24 + asegH) * 2u,
                         AsrcH + kt, aokH);
            } else {
                cp16(asmb + (uint32_t)s * (ASTG * 4u) + (uint32_t)(arowF * 20 + asegF) * 4u,
                     AsrcF + kt, aokF);
            }
            cp16(bdst + (uint32_t)(s * BSTG) * 4u, Bsrc + (size_t)kt * Kcols, true);
        }
        CP_COMMIT();
    }

    const float invN = 1.f / (float)Nn;
    if (AAFF) {
        for (int k = tid; k < Mred; k += 512) {
            float scv = 1.f, shv = 0.f;
            const float *slot = nullptr, *gg = nullptr, *bb = nullptr;
            int c = k;
            if (AAFF == 1) { slot = affA; gg = affAg; bb = affAb; }
            else {
                int blk = k >> 7;
                c = k & 127;
                if (blk > 0) {
                    slot = g_bnsum + (size_t)(2 * (blk - 1) + 1) * 256;
                    gg = affAg + (blk - 1) * 128;
                    bb = affAb + (blk - 1) * 128;
                }
            }
            if (slot) {
                float mu = slot[c] * invN;
                float var = slot[c + 128] * invN - mu * mu;
                float rs = rsqrtf(var + EPSBN);
                scv = gg[c] * rs;
                shv = bb[c] - mu * scv;
            }
            sm[SCA + k] = scv;
            sm[SHA + k] = shv;
        }
    }
    if (ELER) {
        if (tid < 128) sm[ALO + tid] = al[tid];
        else if (tid < 256) sm[ARO + tid - 128] = ar[tid - 128];
    }
    if (DEC) {
        if (tid < 128) sm[ALO + tid] = al[tid];
    }

    float acc[2][4][4];
#pragma unroll
    for (int mi = 0; mi < 2; mi++)
#pragma unroll
        for (int ni = 0; ni < 4; ni++)
#pragma unroll
            for (int j = 0; j < 4; j++) acc[mi][ni][j] = 0.f;

    for (int it = 0; it < nIter; it++) {
        CP_WAIT2();
        __syncthreads();

        const int stg = it & (S - 1);
        const float* as = AsF + stg * ASTG;
        const float* bs = BsF + stg * BSTG;
#pragma unroll
        for (int ks = 0; ks < 2; ks++) {
            const int kbase = ks * 8;
            float sc0 = 1.f, sc1 = 1.f, sh0 = 0.f, sh1 = 0.f;
            if (AAFF) {
                int kg = (it << 4) + kbase + qk;
                sc0 = sm[SCA + kg]; sh0 = sm[SHA + kg];
                sc1 = sm[SCA + kg + 4]; sh1 = sm[SHA + kg + 4];
            }
            uint32_t a[2][4];
#pragma unroll
            for (int mi = 0; mi < 2; mi++) {
                if (AHALF) {
                    const __half* ap = (const __half*)as + (m0 + mi * 16 + qrow) * 24 + kbase + qk;
                    float f0 = __half2float(ap[0]);
                    float f1 = __half2float(ap[8 * 24]);
                    float f2 = __half2float(ap[4]);
                    float f3 = __half2float(ap[8 * 24 + 4]);
                    if (AAFF) {
                        f0 = to_tf32(fmaf(f0, sc0, sh0));
                        f1 = to_tf32(fmaf(f1, sc0, sh0));
                        f2 = to_tf32(fmaf(f2, sc1, sh1));
                        f3 = to_tf32(fmaf(f3, sc1, sh1));
                    }
                    a[mi][0] = __float_as_uint(f0);
                    a[mi][1] = __float_as_uint(f1);
                    a[mi][2] = __float_as_uint(f2);
                    a[mi][3] = __float_as_uint(f3);
                } else {
                    const float* ap = as + (m0 + mi * 16 + qrow) * 20 + kbase + qk;
                    if (AAFF) {
                        a[mi][0] = __float_as_uint(to_tf32(fmaf(ap[0], sc0, sh0)));
                        a[mi][1] = __float_as_uint(to_tf32(fmaf(ap[8 * 20], sc0, sh0)));
                        a[mi][2] = __float_as_uint(to_tf32(fmaf(ap[4], sc1, sh1)));
                        a[mi][3] = __float_as_uint(to_tf32(fmaf(ap[8 * 20 + 4], sc1, sh1)));
                    } else {
                        a[mi][0] = __float_as_uint(to_tf32(ap[0]));
                        a[mi][1] = __float_as_uint(to_tf32(ap[8 * 20]));
                        a[mi][2] = __float_as_uint(to_tf32(ap[4]));
                        a[mi][3] = __float_as_uint(to_tf32(ap[8 * 20 + 4]));
                    }
                }
            }
            uint32_t b[4][2];
#pragma unroll
            for (int ni = 0; ni < 4; ni++) {
                const float* bp = bs + (kbase + qk) * 136 + n0 + ni * 8 + qrow;
                b[ni][0] = __float_as_uint(bp[0]);
                b[ni][1] = __float_as_uint(bp[4 * 136]);
            }
#pragma unroll
            for (int mi = 0; mi < 2; mi++)
#pragma unroll
                for (int ni = 0; ni < 4; ni++) MMA_TF32(acc[mi][ni], a[mi], b[ni]);
        }

        const int nx = it + S - 1;
        if (nx < nIter) {
            const int s = nx & (S - 1);
            const int kt = nx << 4;
            if (AHALF) {
                if (tid < 256)
                    cp16(asmb + (uint32_t)s * (ASTG * 4u) + (uint32_t)(arowH * 24 + asegH) * 2u,
                         AsrcH + kt, aokH);
            } else {
                cp16(asmb + (uint32_t)s * (ASTG * 4u) + (uint32_t)(arowF * 20 + asegF) * 4u,
                     AsrcF + kt, aokF);
            }
            cp16(bdst + (uint32_t)(s * BSTG) * 4u, Bsrc + (size_t)kt * Kcols, true);
        }
        CP_COMMIT();
    }

    // epilogue
    float s0[4], s1[4], q0[4], q1[4];
    if (BN) {
#pragma unroll
        for (int ni = 0; ni < 4; ni++) { s0[ni] = 0.f; s1[ni] = 0.f; q0[ni] = 0.f; q1[ni] = 0.f; }
    }
#pragma unroll
    for (int mi = 0; mi < 2; mi++) {
#pragma unroll
        for (int half = 0; half < 2; half++) {
            int r = bm + m0 + mi * 16 + qrow + half * 8;
            bool rok = r < Nrows;
            float pd = 0.f;
#pragma unroll
            for (int ni = 0; ni < 4; ni++) {
                int gcl = n0 + ni * 8 + qk * 2;
                int gc = bn + gcl;
                float v0 = acc[mi][ni][half * 2 + 0];
                float v1 = acc[mi][ni][half * 2 + 1];
                if (BIAS) {
                    v0 += bias[gc];
                    v1 += bias[gc + 1];
                }
                if (RELU) {
                    v0 = fmaxf(v0, 0.f);
                    v1 = fmaxf(v1, 0.f);
                }
                if (!DEC && rok) {
                    if (CHALF) {
                        *(__half2*)((__half*)C + (size_t)r * ldc + gc) = __floats2half2_rn(v0, v1);
                    } else {
                        *(float2*)(C + (size_t)r * ldc + gc) = make_float2(v0, v1);
                    }
                }
                if (BN && rok) {
                    s0[ni] += v0; q0[ni] += v0 * v0;
                    s1[ni] += v1; q1[ni] += v1 * v1;
                }
                if (DEC) pd = fmaf(v0, sm[ALO + gcl], fmaf(v1, sm[ALO + gcl + 1], pd));
                if (ELER) {
                    int h = (n0 >> 3) + ni;
                    float p = fmaf(v0, sm[ALO + h * 8 + qk * 2], v1 * sm[ALO + h * 8 + qk * 2 + 1]);
                    float q = fmaf(v0, sm[ARO + h * 8 + qk * 2], v1 * sm[ARO + h * 8 + qk * 2 + 1]);
                    p += __shfl_xor_sync(0xffffffffu, p, 1);
                    p += __shfl_xor_sync(0xffffffffu, p, 2);
                    q += __shfl_xor_sync(0xffffffffu, q, 1);
                    q += __shfl_xor_sync(0xffffffffu, q, 2);
                    if ((lane & 3) == 0 && rok) {
                        g_el[r * 16 + h] = p;
                        g_er[r * 16 + h] = q;
                    }
                }
            }
            if (DEC) {
                pd += __shfl_xor_sync(0xffffffffu, pd, 1);
                pd += __shfl_xor_sync(0xffffffffu, pd, 2);
                if ((lane & 3) == 0 && rok)
                    atomicAdd(C + r, pd + 0.25f * ar[0]);
            }
        }
    }

    if (BN) {
#pragma unroll
        for (int ni = 0; ni < 4; ni++) {
            s0[ni] += __shfl_xor_sync(0xffffffffu, s0[ni], 4);
            s0[ni] += __shfl_xor_sync(0xffffffffu, s0[ni], 8);
            s0[ni] += __shfl_xor_sync(0xffffffffu, s0[ni], 16);
            s1[ni] += __shfl_xor_sync(0xffffffffu, s1[ni], 4);
            s1[ni] += __shfl_xor_sync(0xffffffffu, s1[ni], 8);
            s1[ni] += __shfl_xor_sync(0xffffffffu, s1[ni], 16);
            q0[ni] += __shfl_xor_sync(0xffffffffu, q0[ni], 4);
            q0[ni] += __shfl_xor_sync(0xffffffffu, q0[ni], 8);
            q0[ni] += __shfl_xor_sync(0xffffffffu, q0[ni], 16);
            q1[ni] += __shfl_xor_sync(0xffffffffu, q1[ni], 4);
            q1[ni] += __shfl_xor_sync(0xffffffffu, q1[ni], 8);
            q1[ni] += __shfl_xor_sync(0xffffffffu, q1[ni], 16);
        }
        __syncthreads();
        if (lane < 4) {
            int mg = wid & 3;
#pragma unroll
            for (int ni = 0; ni < 4; ni++) {
                int c = n0 + ni * 8 + lane * 2;
                sm[mg * 128 + c] = s0[ni];
                sm[mg * 128 + c + 1] = s1[ni];
                sm[512 + mg * 128 + c] = q0[ni];
                sm[512 + mg * 128 + c + 1] = q1[ni];
            }
        }
        __syncthreads();
        if (tid < 256) {
            int c = tid & 127, st = tid >> 7;
            float v = sm[st * 512 + c] + sm[st * 512 + 128 + c] +
                      sm[st * 512 + 256 + c] + sm[st * 512 + 384 + c];
            atomicAdd(bnslot + st * 128 + c, v);
        }
    }
}

// ---------------- fused FF kernel, M=64 tiles, T in fp16 smem, 2 CTAs/SM ----------------
// smem floats: Y[64][132]=8448 | Th[64][264] (8448 floats) | W 4352 | SCA 128 | SHA 128 | SB1 256
__global__ void __launch_bounds__(512, 2) k_ff(
    const float* __restrict__ y,
    const float* __restrict__ W1, const float* __restrict__ b1v,
    const float* __restrict__ W2, const float* __restrict__ b2v,
    __half* __restrict__ C, int ldc,
    const float* __restrict__ slot1, const float* __restrict__ g1, const float* __restrict__ bb1,
    float* __restrict__ bnslot) {
    constexpr int YOFF = 0;
    constexpr int TOFF = 8448;            // halfs base (as float idx)
    constexpr int WOFF = TOFF + 8448;     // 16896
    constexpr int SCA = WOFF + 4352;      // 21248
    constexpr int SHA = SCA + 128;
    constexpr int SB1 = SHA + 128;        // ..21760 floats = 87040 B
    extern __shared__ float sm[];
    __half* Th = (__half*)(sm + TOFF);
    const int tid = threadIdx.x, lane = tid & 31, wid = tid >> 5;
    const int bm = blockIdx.x * 64;
    const int qrow = lane >> 2, qk = lane & 3;
    const uint32_t smb = smem_to_u32(sm);

    // Y tile 64x128
    {
        int row = tid >> 3, cb = (tid & 7) * 16;
        bool ok = (bm + row) < Nn;
        const float* srcp = y + (size_t)(bm + row) * 128 + cb;
        uint32_t dst = smb + (uint32_t)(YOFF + row * 132 + cb) * 4u;
#pragma unroll
        for (int j = 0; j < 4; j++) cp16(dst + j * 16u, srcp + j * 4, ok);
    }
    // W1 chunk 0
    {
        int r = tid >> 6, c = (tid & 63) * 4;
        cp16(smb + (uint32_t)(WOFF + r * 264 + c) * 4u, W1 + r * 256 + c, true);
    }
    CP_COMMIT();
    const float invN = 1.f / (float)Nn;
    if (tid < 128) {
        float mu = slot1[tid] * invN;
        float var = slot1[tid + 128] * invN - mu * mu;
        float sc = g1[tid] * rsqrtf(var + EPSBN);
        sm[SCA + tid] = sc;
        sm[SHA + tid] = bb1[tid] - mu * sc;
    } else if (tid < 384) {
        sm[SB1 + tid - 128] = b1v[tid - 128];
    }
    CP_WAIT0();
    __syncthreads();

    // ---- stage A: T(half) = relu(BN1(Y) @ W1 + b1); warp tile 32x32 over 64x256 ----
    const int m0A = (wid & 1) * 32, n0A = (wid >> 1) * 32;
    float accA[2][4][4];
#pragma unroll
    for (int mi = 0; mi < 2; mi++)
#pragma unroll
        for (int ni = 0; ni < 4; ni++)
#pragma unroll
            for (int j = 0; j < 4; j++) accA[mi][ni][j] = 0.f;

    for (int it = 0; it < 16; it++) {
        if (it + 1 < 16) {
            int r = tid >> 6, c = (tid & 63) * 4;
            cp16(smb + (uint32_t)(WOFF + ((it + 1) & 1) * 2112 + r * 264 + c) * 4u,
                 W1 + (size_t)((it + 1) * 8 + r) * 256 + c, true);
        }
        CP_COMMIT();
        CP_WAIT1();
        __syncthreads();
        const float* bs = sm + WOFF + (it & 1) * 2112;
        int kg = it * 8 + qk;
        float sc0 = sm[SCA + kg], sh0 = sm[SHA + kg];
        float sc1 = sm[SCA + kg + 4], sh1 = sm[SHA + kg + 4];
        uint32_t a[2][4];
#pragma unroll
        for (int mi = 0; mi < 2; mi++) {
            const float* ap = sm + YOFF + (m0A + mi * 16 + qrow) * 132 + it * 8 + qk;
            a[mi][0] = __float_as_uint(to_tf32(fmaf(ap[0], sc0, sh0)));
            a[mi][1] = __float_as_uint(to_tf32(fmaf(ap[8 * 132], sc0, sh0)));
            a[mi][2] = __float_as_uint(to_tf32(fmaf(ap[4], sc1, sh1)));
            a[mi][3] = __float_as_uint(to_tf32(fmaf(ap[8 * 132 + 4], sc1, sh1)));
        }
#pragma unroll
        for (int ni = 0; ni < 4; ni++) {
            uint32_t b[2];
            const float* bp = bs + qk * 264 + n0A + ni * 8 + qrow;
            b[0] = __float_as_uint(bp[0]);
            b[1] = __float_as_uint(bp[4 * 264]);
#pragma unroll
            for (int mi = 0; mi < 2; mi++) MMA_TF32(accA[mi][ni], a[mi], b);
        }
        __syncthreads();
    }

    // write T = relu(acc + b1) as half
#pragma unroll
    for (int mi = 0; mi < 2; mi++) {
#pragma unroll
        for (int half = 0; half < 2; half++) {
            int rl = m0A + mi * 16 + half * 8 + qrow;
#pragma unroll
            for (int ni = 0; ni < 4; ni++) {
                int c = n0A + ni * 8 + qk * 2;
                float v0 = fmaxf(accA[mi][ni][half * 2 + 0] + sm[SB1 + c], 0.f);
                float v1 = fmaxf(accA[mi][ni][half * 2 + 1] + sm[SB1 + c + 1], 0.f);
                *(__half2*)&Th[rl * 264 + c] = __floats2half2_rn(v0, v1);
            }
        }
    }
    __syncthreads();

    // ---- stage B: HC = T @ W2 + b2 + BN1(Y); warp tile 32x16 over 64x128 ----
    const int m0B = (wid & 1) * 32, n0B = (wid >> 1) * 16;
    float accB[2][2][4];
#pragma unroll
    for (int mi = 0; mi < 2; mi++)
#pragma unroll
        for (int ni = 0; ni < 2; ni++)
#pragma unroll
            for (int j = 0; j < 4; j++) accB[mi][ni][j] = 0.f;

    {
        int r = tid >> 5, c = (tid & 31) * 4;
        cp16(smb + (uint32_t)(WOFF + r * 136 + c) * 4u, W2 + r * 128 + c, true);
    }
    CP_COMMIT();

    for (int it = 0; it < 16; it++) {
        if (it + 1 < 16) {
            int r = tid >> 5, c = (tid & 31) * 4;
            cp16(smb + (uint32_t)(WOFF + ((it + 1) & 1) * 2176 + r * 136 + c) * 4u,
                 W2 + (size_t)((it + 1) * 16 + r) * 128 + c, true);
        }
        CP_COMMIT();
        CP_WAIT1();
        __syncthreads();
        const float* bs = sm + WOFF + (it & 1) * 2176;
#pragma unroll
        for (int ks = 0; ks < 2; ks++) {
            int kb = it * 16 + ks * 8;
            uint32_t a[2][4];
#pragma unroll
            for (int mi = 0; mi < 2; mi++) {
                const __half* ap = Th + (m0B + mi * 16 + qrow) * 264 + kb + qk;
                a[mi][0] = __float_as_uint(__half2float(ap[0]));
                a[mi][1] = __float_as_uint(__half2float(ap[8 * 264]));
                a[mi][2] = __float_as_uint(__half2float(ap[4]));
                a[mi][3] = __float_as_uint(__half2float(ap[8 * 264 + 4]));
            }
#pragma unroll
            for (int ni = 0; ni < 2; ni++) {
                uint32_t b[2];
                const float* bp = bs + (ks * 8 + qk) * 136 + n0B + ni * 8 + qrow;
                b[0] = __float_as_uint(bp[0]);
                b[1] = __float_as_uint(bp[4 * 136]);
#pragma unroll
                for (int mi = 0; mi < 2; mi++) MMA_TF32(accB[mi][ni], a[mi], b);
            }
        }
        __syncthreads();
    }

    // epilogue: + b2 + BN1(Y) residual, write HC (half), BN2 stats
    float s0[2], s1[2], q0[2], q1[2];
#pragma unroll
    for (int ni = 0; ni < 2; ni++) { s0[ni] = 0.f; s1[ni] = 0.f; q0[ni] = 0.f; q1[ni] = 0.f; }
#pragma unroll
    for (int mi = 0; mi < 2; mi++) {
#pragma unroll
        for (int half = 0; half < 2; half++) {
            int rl = m0B + mi * 16 + half * 8 + qrow;
            int r = bm + rl;
            bool rok = r < Nn;
#pragma unroll
            for (int ni = 0; ni < 2; ni++) {
                int gc = n0B + ni * 8 + qk * 2;
                float yv0 = fmaf(sm[YOFF + rl * 132 + gc], sm[SCA + gc], sm[SHA + gc]);
                float yv1 = fmaf(sm[YOFF + rl * 132 + gc + 1], sm[SCA + gc + 1], sm[SHA + gc + 1]);
                float v0 = accB[mi][ni][half * 2 + 0] + b2v[gc] + yv0;
                float v1 = accB[mi][ni][half * 2 + 1] + b2v[gc + 1] + yv1;
                if (rok) {
                    *(__half2*)(C + (size_t)r * ldc + gc) = __floats2half2_rn(v0, v1);
                    s0[ni] += v0; q0[ni] += v0 * v0;
                    s1[ni] += v1; q1[ni] += v1 * v1;
                }
            }
        }
    }
#pragma unroll
    for (int ni = 0; ni < 2; ni++) {
        s0[ni] += __shfl_xor_sync(0xffffffffu, s0[ni], 4);
        s0[ni] += __shfl_xor_sync(0xffffffffu, s0[ni], 8);
        s0[ni] += __shfl_xor_sync(0xffffffffu, s0[ni], 16);
        s1[ni] += __shfl_xor_sync(0xffffffffu, s1[ni], 4);
        s1[ni] += __shfl_xor_sync(0xffffffffu, s1[ni], 8);
        s1[ni] += __shfl_xor_sync(0xffffffffu, s1[ni], 16);
        q0[ni] += __shfl_xor_sync(0xffffffffu, q0[ni], 4);
        q0[ni] += __shfl_xor_sync(0xffffffffu, q0[ni], 8);
        q0[ni] += __shfl_xor_sync(0xffffffffu, q0[ni], 16);
        q1[ni] += __shfl_xor_sync(0xffffffffu, q1[ni], 4);
        q1[ni] += __shfl_xor_sync(0xffffffffu, q1[ni], 8);
        q1[ni] += __shfl_xor_sync(0xffffffffu, q1[ni], 16);
    }
    __syncthreads();
    if (lane < 4) {
        int mg = wid & 1;
#pragma unroll
        for (int ni = 0; ni < 2; ni++) {
            int c = n0B + ni * 8 + lane * 2;
            sm[mg * 128 + c] = s0[ni];
            sm[mg * 128 + c + 1] = s1[ni];
            sm[256 + mg * 128 + c] = q0[ni];
            sm[256 + mg * 128 + c + 1] = q1[ni];
        }
    }
    __syncthreads();
    if (tid < 256) {
        int st = tid >> 7, c = tid & 127;
        float v = sm[st * 256 + c] + sm[st * 256 + 128 + c];
        atomicAdd(bnslot + st * 128 + c, v);
    }
}

// ---------------- GAT aggregate ----------------
__global__ void k_gat(const __half* __restrict__ z,
                      const __half* __restrict__ hres, int ldh,
                      const float* __restrict__ bias, float* __restrict__ y,
                      float* __restrict__ bnslot,
                      const float* __restrict__ slotPrev,
                      const float* __restrict__ gPrev, const float* __restrict__ bPrev) {
    __shared__ float sbn[2][8][128];
    int gw = (blockIdx.x * blockDim.x + threadIdx.x) >> 5;
    int lane = threadIdx.x & 31;
    int wid = threadIdx.x >> 5;
    float4 o = make_float4(0.f, 0.f, 0.f, 0.f);
    if (gw < Nn) {
        int head = lane >> 1;
        int beg = g_rowptr[gw], end = g_rowptr[gw + 1];
        float er_h = g_er[gw * 16 + head];
        const uint2* z2 = (const uint2*)z;

        float den = 0.f;
        float4 acc = make_float4(0.f, 0.f, 0.f, 0.f);
        int i = beg;
        for (; i + 1 < end; i += 2) {
            int sA = g_srcs[i];
            int sB = g_srcs[i + 1];
            float eA = g_el[sA * 16 + head];
            float eB = g_el[sB * 16 + head];
            uint2 rA = z2[(size_t)sA * 32 + lane];
            uint2 rB = z2[(size_t)sB * 32 + lane];
            eA += er_h;
            eB += er_h;
            eA = eA > 0.f ? eA : SLOPE * eA;
            eB = eB > 0.f ? eB : SLOPE * eB;
            float wA = __expf(eA);
            float wB = __expf(eB);
            den += wA + wB;
            float2 a0 = __half22float2(*(__half2*)&rA.x);
            float2 a1 = __half22float2(*(__half2*)&rA.y);
            float2 b0 = __half22float2(*(__half2*)&rB.x);
            float2 b1 = __half22float2(*(__half2*)&rB.y);
            acc.x += wA * a0.x + wB * b0.x;
            acc.y += wA * a0.y + wB * b0.y;
            acc.z += wA * a1.x + wB * b1.x;
            acc.w += wA * a1.y + wB * b1.y;
        }
        if (i < end) {
            int s = g_srcs[i];
            float e = g_el[s * 16 + head] + er_h;
            uint2 r = z2[(size_t)s * 32 + lane];
            e = e > 0.f ? e : SLOPE * e;
            float w = __expf(e);
            den += w;
            float2 a0 = __half22float2(*(__half2*)&r.x);
            float2 a1 = __half22float2(*(__half2*)&r.y);
            acc.x += w * a0.x; acc.y += w * a0.y;
            acc.z += w * a1.x; acc.w += w * a1.y;
        }
        float dinv = den > 0.f ? 1.f / den : 1.f;
        float4 b4 = ((const float4*)bias)[lane];
        uint2 hr = *(const uint2*)(hres + (size_t)gw * ldh + lane * 4);
        float2 h01 = __half22float2(*(__half2*)&hr.x);
        float2 h23 = __half22float2(*(__half2*)&hr.y);
        float4 h4 = make_float4(h01.x, h01.y, h23.x, h23.y);
        if (slotPrev != nullptr) {
            const float invN = 1.f / (float)Nn;
            int c = lane * 4;
#pragma unroll
            for (int j = 0; j < 4; j++) {
                float mu = slotPrev[c + j] * invN;
                float var = slotPrev[128 + c + j] * invN - mu * mu;
                float sc = gPrev[c + j] * rsqrtf(var + EPSBN);
                float sh = bPrev[c + j] - mu * sc;
                float* hp = (&h4.x) + j;
                *hp = fmaf(*hp, sc, sh);
            }
        }
        o.x = acc.x * dinv + b4.x + h4.x;
        o.y = acc.y * dinv + b4.y + h4.y;
        o.z = acc.z * dinv + b4.z + h4.z;
        o.w = acc.w * dinv + b4.w + h4.w;
        ((float4*)y)[(size_t)gw * 32 + lane] = o;
    }
    ((float4*)sbn[0][wid])[lane] = o;
    ((float4*)sbn[1][wid])[lane] = make_float4(o.x * o.x, o.y * o.y, o.z * o.z, o.w * o.w);
    __syncthreads();
    int c = threadIdx.x & 127, st = threadIdx.x >> 7;
    float v = 0.f;
#pragma unroll
    for (int w = 0; w < 8; w++) v += sbn[st][w][c];
    atomicAdd(bnslot + st * 128 + c, v);
}

// ---------------- launch ----------------
extern "C" void kernel_launch(void* const* d_in, const int* in_sizes, int n_in,
                              void* d_out, int out_size) {
    const float* x      = (const float*)d_in[0];
    const int*   src    = (const int*)d_in[1];
    const int*   dst    = (const int*)d_in[2];
    const float* emb_W1 = (const float*)d_in[3];
    const float* emb_b1 = (const float*)d_in[4];
    const float* emb_W2 = (const float*)d_in[5];
    const float* emb_b2 = (const float*)d_in[6];
    const float* emb_Ws = (const float*)d_in[7];
    const float* emb_bs = (const float*)d_in[8];
    const float* gat_W  = (const float*)d_in[9];
    const float* gat_al = (const float*)d_in[10];
    const float* gat_ar = (const float*)d_in[11];
    const float* gat_b  = (const float*)d_in[12];
    const float* bn1_g  = (const float*)d_in[13];
    const float* bn1_b  = (const float*)d_in[14];
    const float* ff_W1  = (const float*)d_in[15];
    const float* ff_b1  = (const float*)d_in[16];
    const float* ff_W2  = (const float*)d_in[17];
    const float* ff_b2  = (const float*)d_in[18];
    const float* bn2_g  = (const float*)d_in[19];
    const float* bn2_b  = (const float*)d_in[20];
    const float* dec_W1 = (const float*)d_in[21];
    const float* dec_b1 = (const float*)d_in[22];
    const float* dec_W2 = (const float*)d_in[23];
    const float* dec_b2 = (const float*)d_in[24];

    void* p;
    float *zb, *yb, *bns, *W;
    __half* HC;
    int* degp;
    cudaGetSymbolAddress(&p, g_HC);    HC = (__half*)p;
    cudaGetSymbolAddress(&p, g_z);     zb = (float*)p;
    cudaGetSymbolAddress(&p, g_y);     yb = (float*)p;
    cudaGetSymbolAddress(&p, g_bnsum); bns = (float*)p;
    cudaGetSymbolAddress(&p, g_deg);   degp = (int*)p;
    cudaGetSymbolAddress(&p, g_W);     W = (float*)p;

    float* Wg = W;
    float* Wf1 = W + 65536;
    float* Wf2 = W + 196608;
    float* Wd = W + 327680;
    float* We2 = W + 409600;

    const int SMEM = 20736 * 4;        // 82944 B
    const int SMEM_FF = 21760 * 4;     // 87040 B (2 CTAs/SM)
    static bool attrDone = false;
    if (!attrDone) {
        cudaFuncSetAttribute(k_emb, cudaFuncAttributeMaxDynamicSharedMemorySize, SMEM);
        cudaFuncSetAttribute(k_tgemm<0, 0, 0, 1, 0, 0, 1, 1>, cudaFuncAttributeMaxDynamicSharedMemorySize, SMEM);
        cudaFuncSetAttribute(k_tgemm<0, 0, 0, 1, 1, 0, 1, 1>, cudaFuncAttributeMaxDynamicSharedMemorySize, SMEM);
        cudaFuncSetAttribute(k_tgemm<1, 1, 0, 0, 2, 1, 1, 0>, cudaFuncAttributeMaxDynamicSharedMemorySize, SMEM);
        cudaFuncSetAttribute(k_ff, cudaFuncAttributeMaxDynamicSharedMemorySize, SMEM_FF);
        attrDone = true;
    }

    cudaMemsetAsync(bns, 0, 8 * 256 * sizeof(float));
    cudaMemsetAsync(degp, 0, Nn * sizeof(int));
    cudaMemsetAsync(d_out, 0, (size_t)out_size * sizeof(float));

    const int gx = (Nn + 127) / 128;   // 782
    const int gx64 = (Nn + 63) / 64;   // 1563
    dim3 grid1(gx, 1);
    const int warpBlocks = (Nn * 32 + 255) / 256;

    k_cvt_all<<<(425984 + 255) / 256, 256>>>(gat_W, ff_W1, ff_W2, dec_W1, emb_W2);
    k_count<<<(Ee + 255) / 256, 256>>>(dst);
    // fused embed -> HC block 0 (fp16)
    k_emb<<<grid1, 512, SMEM>>>(x, We2, emb_W1, emb_b1, emb_Ws, emb_bs, emb_b2, HC, 640);
    // layer-0 z GEMM (4th launch -> ncu target)
    k_tgemm<0, 0, 0, 1, 0, 0, 1, 1><<<grid1, 512, SMEM>>>(
        (const float*)HC, 640, Wg, nullptr, zb, 128, Nn, 128, 128, nullptr,
        nullptr, nullptr, nullptr, gat_al, gat_ar);

    const int nb = (Nn + 1023) / 1024;
    k_scan1<<<nb, 1024>>>();
    k_scan2<<<1, 128>>>(nb);
    k_finalize<<<(Nn + 255) / 256, 256>>>();
    k_fill<<<(Ee + 255) / 256, 256>>>(dst, src);

    for (int l = 0; l < 4; l++) {
        const __half* h = HC + (size_t)l * 128;
        float* slot1 = bns + (size_t)(2 * l) * 256;
        float* slot2 = bns + (size_t)(2 * l + 1) * 256;
        const float* slotP = (l > 0) ? (bns + (size_t)(2 * (l - 1) + 1) * 256) : nullptr;
        const float* gP = (l > 0) ? (bn2_g + (l - 1) * 128) : nullptr;
        const float* bP = (l > 0) ? (bn2_b + (l - 1) * 128) : nullptr;

        if (l > 0) {
            k_tgemm<0, 0, 0, 1, 1, 0, 1, 1><<<grid1, 512, SMEM>>>(
                (const float*)h, 640, Wg + (size_t)l * 16384, nullptr, zb, 128, Nn, 128, 128, nullptr,
                slotP, gP, bP, gat_al + l * 128, gat_ar + l * 128);
        }
        k_gat<<<warpBlocks, 256>>>((const __half*)zb, h, 640, gat_b + l * 128, yb, slot1,
                                   slotP, gP, bP);
        k_ff<<<gx64, 512, SMEM_FF>>>(
            yb, Wf1 + (size_t)l * 32768, ff_b1 + l * 256,
            Wf2 + (size_t)l * 32768, ff_b2 + l * 128,
            HC + (size_t)(l + 1) * 128, 640,
            slot1, bn1_g + l * 128, bn1_b + l * 128, slot2);
    }

    // decoder
    k_tgemm<1, 1, 0, 0, 2, 1, 1, 0><<<grid1, 512, SMEM>>>(
        (const float*)HC, 640, Wd, dec_b1, (float*)d_out, 1, Nn, 640, 128, nullptr,
        nullptr, bn2_g, bn2_b, dec_W2, dec_b2);
}

// round 17
// speedup vs baseline: 1.1828x; 1.0866x over previous
#include <cuda_runtime.h>
#include <cuda_fp16.h>
#include <cstdint>

#define Nn 100000
#define Ee 600000
#define EPSBN 1e-5f
#define SLOPE 0.2f

// ---------------- scratch ----------------
__device__ __half g_HC[(size_t)Nn * 640];
__device__ float g_z[(size_t)Nn * 128];    // used as __half[Nn*128]
__device__ float g_y[(size_t)Nn * 128];
__device__ float g_el[(size_t)Nn * 16];
__device__ float g_er[(size_t)Nn * 16];
__device__ float g_bnsum[8 * 256];
__device__ int   g_deg[Nn];
__device__ int   g_scan[Nn];
__device__ int   g_bsum[128];
__device__ int   g_rowptr[Nn + 1];
__device__ int   g_cursor[Nn];
__device__ int   g_srcs[Ee];
__device__ float g_W[262144];              // tf32 ff weights: W1[4*32768] W2[4*32768]
__device__ __half g_Wgt[4][128 * 136];     // transposed half gat weights (affine-folded)
__device__ __half g_We2t[128 * 136];       // transposed half emb W2
__device__ __half g_Wdt[128 * 648];        // transposed half dec W1 (affine-folded)
__device__ float g_biasz[4 * 128];
__device__ float g_biasd[128];

__device__ __forceinline__ float to_tf32(float x) {
    float r;
    asm("cvt.rna.tf32.f32 %0, %1;" : "=f"(r) : "f"(x));
    return r;
}
__device__ __forceinline__ uint32_t smem_to_u32(const void* p) {
    uint32_t a;
    asm("{ .reg .u64 t; cvta.to.shared.u64 t, %1; cvt.u32.u64 %0, t; }" : "=r"(a) : "l"(p));
    return a;
}
__device__ __forceinline__ void cp16(uint32_t dst, const void* src, bool ok) {
    int sz = ok ? 16 : 0;
    asm volatile("cp.async.cg.shared.global [%0], [%1], 16, %2;"
                 :: "r"(dst), "l"(src), "r"(sz) : "memory");
}
#define CP_COMMIT() asm volatile("cp.async.commit_group;" ::: "memory")
#define CP_WAIT2() asm volatile("cp.async.wait_group 2;" ::: "memory")
#define CP_WAIT1() asm volatile("cp.async.wait_group 1;" ::: "memory")
#define CP_WAIT0() asm volatile("cp.async.wait_group 0;" ::: "memory")

#define MMA_TF32(d, av, bv)                                               \
    asm volatile(                                                         \
        "mma.sync.aligned.m16n8k8.row.col.f32.tf32.tf32.f32 "             \
        "{%0,%1,%2,%3},{%4,%5,%6,%7},{%8,%9},{%0,%1,%2,%3};"              \
        : "+f"((d)[0]), "+f"((d)[1]), "+f"((d)[2]), "+f"((d)[3])          \
        : "r"((av)[0]), "r"((av)[1]), "r"((av)[2]), "r"((av)[3]),         \
          "r"((bv)[0]), "r"((bv)[1]))

#define MMA_F16(d, av, bv)                                                \
    asm volatile(                                                         \
        "mma.sync.aligned.m16n8k16.row.col.f32.f16.f16.f32 "              \
        "{%0,%1,%2,%3},{%4,%5,%6,%7},{%8,%9},{%0,%1,%2,%3};"              \
        : "+f"((d)[0]), "+f"((d)[1]), "+f"((d)[2]), "+f"((d)[3])          \
        : "r"((av)[0]), "r"((av)[1]), "r"((av)[2]), "r"((av)[3]),         \
          "r"((bv)[0]), "r"((bv)[1]))

// ---------------- CSR build ----------------
__global__ void k_count(const int* __restrict__ dst) {
    int e = blockIdx.x * blockDim.x + threadIdx.x;
    if (e < Ee) atomicAdd(&g_deg[dst[e]], 1);
}
__global__ void k_scan1() {
    __shared__ int s[1024];
    int i = blockIdx.x * 1024 + threadIdx.x;
    int v = (i < Nn) ? g_deg[i] : 0;
    s[threadIdx.x] = v;
    __syncthreads();
    for (int off = 1; off < 1024; off <<= 1) {
        int t = (threadIdx.x >= off) ? s[threadIdx.x - off] : 0;
        __syncthreads();
        s[threadIdx.x] += t;
        __syncthreads();
    }
    if (i < Nn) g_scan[i] = s[threadIdx.x];
    if (threadIdx.x == 1023) g_bsum[blockIdx.x] = s[1023];
}
__global__ void k_scan2(int nb) {
    __shared__ int s[128];
    int v = (threadIdx.x < nb) ? g_bsum[threadIdx.x] : 0;
    s[threadIdx.x] = v;
    __syncthreads();
    for (int off = 1; off < 128; off <<= 1) {
        int t = (threadIdx.x >= off) ? s[threadIdx.x - off] : 0;
        __syncthreads();
        s[threadIdx.x] += t;
        __syncthreads();
    }
    g_bsum[threadIdx.x] = (threadIdx.x == 0) ? 0 : s[threadIdx.x - 1];
}
__global__ void k_finalize() {
    int i = blockIdx.x * blockDim.x + threadIdx.x;
    if (i >= Nn) return;
    int incl = g_scan[i] + g_bsum[i >> 10];
    g_rowptr[i + 1] = incl;
    g_cursor[i] = incl - g_deg[i];
    if (i == 0) g_rowptr[0] = 0;
}
__global__ void k_fill(const int* __restrict__ dst, const int* __restrict__ src) {
    int e = blockIdx.x * blockDim.x + threadIdx.x;
    if (e < Ee) {
        int d = dst[e];
        int p = atomicAdd(&g_cursor[d], 1);
        g_srcs[p] = src[e];
    }
}

// ---------------- ff weight cvt (tf32) ----------------
__global__ void k_cvt_ff(const float* __restrict__ ff_W1, const float* __restrict__ ff_W2) {
    int i = blockIdx.x * blockDim.x + threadIdx.x;
    if (i >= 262144) return;
    float v = (i < 131072) ? ff_W1[i] : ff_W2[i - 131072];
    g_W[i] = to_tf32(v);
}

// ---------------- weight prep: Wt[n][k] = half(sc[k]*W[k][n]); bias[n] = sum_k sh[k]*W[k][n] ----------------
__global__ void k_prep128(const float* __restrict__ W, const float* __restrict__ slot,
                          const float* __restrict__ g, const float* __restrict__ b,
                          __half* __restrict__ Wt, float* __restrict__ bias) {
    int n = blockIdx.x, k = threadIdx.x;
    float sc = 1.f, sh = 0.f;
    if (slot != nullptr) {
        const float invN = 1.f / (float)Nn;
        float mu = slot[k] * invN;
        float var = slot[k + 128] * invN - mu * mu;
        float rs = rsqrtf(var + EPSBN);
        sc = g[k] * rs;
        sh = b[k] - mu * sc;
    }
    float w = W[k * 128 + n];
    Wt[n * 136 + k] = __float2half(sc * w);
    __shared__ float red[128];
    red[k] = sh * w;
    __syncthreads();
    for (int o = 64; o; o >>= 1) {
        if (k < o) red[k] += red[k + o];
        __syncthreads();
    }
    if (k == 0) bias[n] = red[0];
}

// decoder prep: 640-k concat affine fold
__global__ void k_prepdec(const float* __restrict__ W, const float* __restrict__ g2,
                          const float* __restrict__ b2a, const float* __restrict__ db1,
                          __half* __restrict__ Wt, float* __restrict__ bias) {
    int n = blockIdx.x, k = threadIdx.x;  // 640 threads
    int blk = k >> 7, c = k & 127;
    float sc = 1.f, sh = 0.f;
    if (blk > 0) {
        const float* slot = g_bnsum + (size_t)(2 * (blk - 1) + 1) * 256;
        const float invN = 1.f / (float)Nn;
        float mu = slot[c] * invN;
        float var = slot[c + 128] * invN - mu * mu;
        float rs = rsqrtf(var + EPSBN);
        sc = g2[(blk - 1) * 128 + c] * rs;
        sh = b2a[(blk - 1) * 128 + c] - mu * sc;
    }
    float w = W[k * 128 + n];
    Wt[n * 648 + k] = __float2half(sc * w);
    __shared__ float red[1024];
    red[k] = sh * w;
    if (k < 384) red[640 + k] = 0.f;
    __syncthreads();
    for (int o = 512; o; o >>= 1) {
        if (k < o) red[k] += red[k + o];
        __syncthreads();
    }
    if (k == 0) bias[n] = red[0] + db1[n];
}

// ---------------- fp16 HMMA GEMM: C = A(half)[N,Mred] @ Bt(half)[128][Mred] (+bias)(relu)(+el/er)(dec) ----------------
template <int RELU, int BIAS, int ELER, int DEC, int CHALF>
__global__ void __launch_bounds__(512, 2) k_hgemm(
    const __half* __restrict__ A, int lda,
    const __half* __restrict__ Bt, int bpad,
    const float* __restrict__ bias,
    float* __restrict__ C, int ldc,
    int Nrows, int Mred,
    const float* al, const float* ar) {
    constexpr int STGH = 3072;  // halfs per stage per matrix (128 rows x 24)
    constexpr int ALO = 12288, ARO = ALO + 128;  // float indices
    extern __shared__ float sm[];
    __half* Ah = (__half*)sm;
    __half* Bh = Ah + 4 * STGH;

    const int tid = threadIdx.x, lane = tid & 31, wid = tid >> 5;
    const int bm = blockIdx.x * 128;
    const int m0 = (wid & 3) * 32, n0 = (wid >> 2) * 32;
    const int qrow = lane >> 2, qk = lane & 3;

    const int arowH = (tid & 255) >> 1;
    const int asegH = (tid & 1) * 8;
    const bool isA = tid < 256;
    const bool aok = isA && ((bm + arowH) < Nrows);
    const __half* Asrc = A + (size_t)(bm + arowH) * lda + asegH;
    const __half* Bsrc = Bt + (size_t)arowH * bpad + asegH;  // arowH reused as n for loaders
    const uint32_t abase = smem_to_u32(Ah);
    const uint32_t bbase = smem_to_u32(Bh);
    const uint32_t ldst = (isA ? abase : bbase) + (uint32_t)(arowH * 24 + asegH) * 2u;
    const __half* lsrc = isA ? Asrc : Bsrc;
    const bool lok = isA ? aok : true;

    const int nIter = Mred >> 4;
#pragma unroll
    for (int s = 0; s < 3; s++) {
        if (s < nIter) cp16(ldst + (uint32_t)s * (STGH * 2u), lsrc + s * 16, lok);
        CP_COMMIT();
    }
    if (ELER) {
        if (tid < 128) sm[ALO + tid] = al[tid];
        else if (tid < 256) sm[ARO + tid - 128] = ar[tid - 128];
    }
    if (DEC) {
        if (tid < 128) sm[ALO + tid] = al[tid];
    }

    float acc[2][4][4];
#pragma unroll
    for (int mi = 0; mi < 2; mi++)
#pragma unroll
        for (int ni = 0; ni < 4; ni++)
#pragma unroll
            for (int j = 0; j < 4; j++) acc[mi][ni][j] = 0.f;

    for (int it = 0; it < nIter; it++) {
        CP_WAIT2();
        __syncthreads();
        const __half* as = Ah + (it & 3) * STGH;
        const __half* bs = Bh + (it & 3) * STGH;
        uint32_t a[2][4], b[4][2];
#pragma unroll
        for (int mi = 0; mi < 2; mi++) {
            const __half* ap = as + (m0 + mi * 16 + qrow) * 24 + 2 * qk;
            a[mi][0] = *(const uint32_t*)(ap);
            a[mi][1] = *(const uint32_t*)(ap + 8 * 24);
            a[mi][2] = *(const uint32_t*)(ap + 8);
            a[mi][3] = *(const uint32_t*)(ap + 8 * 24 + 8);
        }
#pragma unroll
        for (int ni = 0; ni < 4; ni++) {
            const __half* bp = bs + (n0 + ni * 8 + qrow) * 24 + 2 * qk;
            b[ni][0] = *(const uint32_t*)(bp);
            b[ni][1] = *(const uint32_t*)(bp + 8);
        }
#pragma unroll
        for (int mi = 0; mi < 2; mi++)
#pragma unroll
            for (int ni = 0; ni < 4; ni++) MMA_F16(acc[mi][ni], a[mi], b[ni]);

        const int nx = it + 3;
        if (nx < nIter) cp16(ldst + (uint32_t)(nx & 3) * (STGH * 2u), lsrc + nx * 16, lok);
        CP_COMMIT();
    }

    // epilogue
#pragma unroll
    for (int mi = 0; mi < 2; mi++) {
#pragma unroll
        for (int half = 0; half < 2; half++) {
            int r = bm + m0 + mi * 16 + qrow + half * 8;
            bool rok = r < Nrows;
            float pd = 0.f;
#pragma unroll
            for (int ni = 0; ni < 4; ni++) {
                int gc = n0 + ni * 8 + qk * 2;
                float v0 = acc[mi][ni][half * 2 + 0];
                float v1 = acc[mi][ni][half * 2 + 1];
                if (BIAS) {
                    v0 += bias[gc];
                    v1 += bias[gc + 1];
                }
                if (RELU) {
                    v0 = fmaxf(v0, 0.f);
                    v1 = fmaxf(v1, 0.f);
                }
                if (!DEC && rok) {
                    if (CHALF) {
                        *(__half2*)((__half*)C + (size_t)r * ldc + gc) = __floats2half2_rn(v0, v1);
                    } else {
                        *(float2*)(C + (size_t)r * ldc + gc) = make_float2(v0, v1);
                    }
                }
                if (DEC) pd = fmaf(v0, sm[ALO + gc], fmaf(v1, sm[ALO + gc + 1], pd));
                if (ELER) {
                    int h = (n0 >> 3) + ni;
                    float p = fmaf(v0, sm[ALO + h * 8 + qk * 2], v1 * sm[ALO + h * 8 + qk * 2 + 1]);
                    float q = fmaf(v0, sm[ARO + h * 8 + qk * 2], v1 * sm[ARO + h * 8 + qk * 2 + 1]);
                    p += __shfl_xor_sync(0xffffffffu, p, 1);
                    p += __shfl_xor_sync(0xffffffffu, p, 2);
                    q += __shfl_xor_sync(0xffffffffu, q, 1);
                    q += __shfl_xor_sync(0xffffffffu, q, 2);
                    if ((lane & 3) == 0 && rok) {
                        g_el[r * 16 + h] = p;
                        g_er[r * 16 + h] = q;
                    }
                }
            }
            if (DEC) {
                pd += __shfl_xor_sync(0xffffffffu, pd, 1);
                pd += __shfl_xor_sync(0xffffffffu, pd, 2);
                if ((lane & 3) == 0 && rok)
                    atomicAdd(C + r, pd + 0.25f * ar[0]);
            }
        }
    }
}

// ---------------- fused embed kernel (fp16 HMMA): HC0(half) = relu(x@W1+b1)@We2 + skip ----------------
__global__ void __launch_bounds__(512, 2) k_emb(
    const float* __restrict__ x, const __half* __restrict__ Bt,
    const float* __restrict__ W1, const float* __restrict__ b1,
    const float* __restrict__ Ws, const float* __restrict__ bs,
    const float* __restrict__ b2,
    __half* __restrict__ C, int ldc) {
    constexpr int STGH = 3072;
    constexpr int W1O = 12288, B1O = W1O + 256;  // float indices
    extern __shared__ float sm[];
    __half* Ah = (__half*)sm;
    __half* Bh = Ah + 4 * STGH;
    const int tid = threadIdx.x, lane = tid & 31, wid = tid >> 5;
    const int bm = blockIdx.x * 128;
    const int m0 = (wid & 3) * 32, n0 = (wid >> 2) * 32;
    const int qrow = lane >> 2, qk = lane & 3;
    const int arow = tid >> 2, aseg = (tid & 3) * 4;
    const bool aok = (bm + arow) < Nn;
    float x0 = 0.f, x1 = 0.f;
    if (aok) {
        x0 = x[(size_t)(bm + arow) * 2];
        x1 = x[(size_t)(bm + arow) * 2 + 1];
    }
    if (tid < 256) sm[W1O + tid] = W1[tid];
    else if (tid < 384) sm[B1O + tid - 256] = b1[tid - 256];

    const int bn_ = (tid & 255) >> 1, bkk = (tid & 1) * 8;
    const uint32_t bdst = smem_to_u32(Bh) + (uint32_t)(bn_ * 24 + bkk) * 2u;
    const __half* Bsrc = Bt + (size_t)bn_ * 136 + bkk;
#pragma unroll
    for (int s = 0; s < 3; s++) {
        if (tid < 256) cp16(bdst + (uint32_t)s * (STGH * 2u), Bsrc + s * 16, true);
        CP_COMMIT();
    }
    __syncthreads();  // W1s/B1s visible
    // compute A stages 0..2 (half)
#pragma unroll
    for (int s = 0; s < 3; s++) {
        float v[4];
#pragma unroll
        for (int j = 0; j < 4; j++) {
            int k = (s << 4) + aseg + j;
            float tv = fmaf(x0, sm[W1O + k], fmaf(x1, sm[W1O + 128 + k], sm[B1O + k]));
            v[j] = tv > 0.f ? tv : 0.f;
        }
        __half* dst = Ah + s * STGH + arow * 24 + aseg;
        *(__half2*)(dst) = __floats2half2_rn(v[0], v[1]);
        *(__half2*)(dst + 2) = __floats2half2_rn(v[2], v[3]);
    }

    float acc[2][4][4];
#pragma unroll
    for (int mi = 0; mi < 2; mi++)
#pragma unroll
        for (int ni = 0; ni < 4; ni++)
#pragma unroll
            for (int j = 0; j < 4; j++) acc[mi][ni][j] = 0.f;

    for (int it = 0; it < 8; it++) {
        CP_WAIT2();
        __syncthreads();
        const __half* as = Ah + (it & 3) * STGH;
        const __half* bs = Bh + (it & 3) * STGH;
        uint32_t a[2][4], b[4][2];
#pragma unroll
        for (int mi = 0; mi < 2; mi++) {
            const __half* ap = as + (m0 + mi * 16 + qrow) * 24 + 2 * qk;
            a[mi][0] = *(const uint32_t*)(ap);
            a[mi][1] = *(const uint32_t*)(ap + 8 * 24);
            a[mi][2] = *(const uint32_t*)(ap + 8);
            a[mi][3] = *(const uint32_t*)(ap + 8 * 24 + 8);
        }
#pragma unroll
        for (int ni = 0; ni < 4; ni++) {
            const __half* bp = bs + (n0 + ni * 8 + qrow) * 24 + 2 * qk;
            b[ni][0] = *(const uint32_t*)(bp);
            b[ni][1] = *(const uint32_t*)(bp + 8);
        }
#pragma unroll
        for (int mi = 0; mi < 2; mi++)
#pragma unroll
            for (int ni = 0; ni < 4; ni++) MMA_F16(acc[mi][ni], a[mi], b[ni]);

        const int nx = it + 3;
        if (nx < 8) {
            float v[4];
#pragma unroll
            for (int j = 0; j < 4; j++) {
                int k = (nx << 4) + aseg + j;
                float tv = fmaf(x0, sm[W1O + k], fmaf(x1, sm[W1O + 128 + k], sm[B1O + k]));
                v[j] = tv > 0.f ? tv : 0.f;
            }
            __half* dst = Ah + (nx & 3) * STGH + arow * 24 + aseg;
            *(__half2*)(dst) = __floats2half2_rn(v[0], v[1]);
            *(__half2*)(dst + 2) = __floats2half2_rn(v[2], v[3]);
            if (tid < 256) cp16(bdst + (uint32_t)(nx & 3) * (STGH * 2u), Bsrc + nx * 16, true);
        }
        CP_COMMIT();
    }

#pragma unroll
    for (int mi = 0; mi < 2; mi++) {
#pragma unroll
        for (int half = 0; half < 2; half++) {
            int r = bm + m0 + mi * 16 + qrow + half * 8;
            if (r >= Nn) continue;
            float x0r = x[(size_t)r * 2], x1r = x[(size_t)r * 2 + 1];
#pragma unroll
            for (int ni = 0; ni < 4; ni++) {
                int gc = n0 + ni * 8 + qk * 2;
                float v0 = acc[mi][ni][half * 2 + 0] +
                           fmaf(x0r, Ws[gc], fmaf(x1r, Ws[128 + gc], bs[gc] + b2[gc]));
                float v1 = acc[mi][ni][half * 2 + 1] +
                           fmaf(x0r, Ws[gc + 1], fmaf(x1r, Ws[128 + gc + 1], bs[gc + 1] + b2[gc + 1]));
                *(__half2*)(C + (size_t)r * ldc + gc) = __floats2half2_rn(v0, v1);
            }
        }
    }
}

// ---------------- fused FF kernel, M=64 tiles, T in fp16 smem, 2 CTAs/SM (R16 version) ----------------
__global__ void __launch_bounds__(512, 2) k_ff(
    const float* __restrict__ y,
    const float* __restrict__ W1, const float* __restrict__ b1v,
    const float* __restrict__ W2, const float* __restrict__ b2v,
    __half* __restrict__ C, int ldc,
    const float* __restrict__ slot1, const float* __restrict__ g1, const float* __restrict__ bb1,
    float* __restrict__ bnslot) {
    constexpr int YOFF = 0;
    constexpr int TOFF = 8448;
    constexpr int WOFF = TOFF + 8448;
    constexpr int SCA = WOFF + 4352;
    constexpr int SHA = SCA + 128;
    constexpr int SB1 = SHA + 128;
    extern __shared__ float sm[];
    __half* Th = (__half*)(sm + TOFF);
    const int tid = threadIdx.x, lane = tid & 31, wid = tid >> 5;
    const int bm = blockIdx.x * 64;
    const int qrow = lane >> 2, qk = lane & 3;
    const uint32_t smb = smem_to_u32(sm);

    {
        int row = tid >> 3, cb = (tid & 7) * 16;
        bool ok = (bm + row) < Nn;
        const float* srcp = y + (size_t)(bm + row) * 128 + cb;
        uint32_t dst = smb + (uint32_t)(YOFF + row * 132 + cb) * 4u;
#pragma unroll
        for (int j = 0; j < 4; j++) cp16(dst + j * 16u, srcp + j * 4, ok);
    }
    {
        int r = tid >> 6, c = (tid & 63) * 4;
        cp16(smb + (uint32_t)(WOFF + r * 264 + c) * 4u, W1 + r * 256 + c, true);
    }
    CP_COMMIT();
    const float invN = 1.f / (float)Nn;
    if (tid < 128) {
        float mu = slot1[tid] * invN;
        float var = slot1[tid + 128] * invN - mu * mu;
        float sc = g1[tid] * rsqrtf(var + EPSBN);
        sm[SCA + tid] = sc;
        sm[SHA + tid] = bb1[tid] - mu * sc;
    } else if (tid < 384) {
        sm[SB1 + tid - 128] = b1v[tid - 128];
    }
    CP_WAIT0();
    __syncthreads();

    const int m0A = (wid & 1) * 32, n0A = (wid >> 1) * 32;
    float accA[2][4][4];
#pragma unroll
    for (int mi = 0; mi < 2; mi++)
#pragma unroll
        for (int ni = 0; ni < 4; ni++)
#pragma unroll
            for (int j = 0; j < 4; j++) accA[mi][ni][j] = 0.f;

    for (int it = 0; it < 16; it++) {
        if (it + 1 < 16) {
            int r = tid >> 6, c = (tid & 63) * 4;
            cp16(smb + (uint32_t)(WOFF + ((it + 1) & 1) * 2112 + r * 264 + c) * 4u,
                 W1 + (size_t)((it + 1) * 8 + r) * 256 + c, true);
        }
        CP_COMMIT();
        CP_WAIT1();
        __syncthreads();
        const float* bs = sm + WOFF + (it & 1) * 2112;
        int kg = it * 8 + qk;
        float sc0 = sm[SCA + kg], sh0 = sm[SHA + kg];
        float sc1 = sm[SCA + kg + 4], sh1 = sm[SHA + kg + 4];
        uint32_t a[2][4];
#pragma unroll
        for (int mi = 0; mi < 2; mi++) {
            const float* ap = sm + YOFF + (m0A + mi * 16 + qrow) * 132 + it * 8 + qk;
            a[mi][0] = __float_as_uint(to_tf32(fmaf(ap[0], sc0, sh0)));
            a[mi][1] = __float_as_uint(to_tf32(fmaf(ap[8 * 132], sc0, sh0)));
            a[mi][2] = __float_as_uint(to_tf32(fmaf(ap[4], sc1, sh1)));
            a[mi][3] = __float_as_uint(to_tf32(fmaf(ap[8 * 132 + 4], sc1, sh1)));
        }
#pragma unroll
        for (int ni = 0; ni < 4; ni++) {
            uint32_t b[2];
            const float* bp = bs + qk * 264 + n0A + ni * 8 + qrow;
            b[0] = __float_as_uint(bp[0]);
            b[1] = __float_as_uint(bp[4 * 264]);
#pragma unroll
            for (int mi = 0; mi < 2; mi++) MMA_TF32(accA[mi][ni], a[mi], b);
        }
        __syncthreads();
    }

#pragma unroll
    for (int mi = 0; mi < 2; mi++) {
#pragma unroll
        for (int half = 0; half < 2; half++) {
            int rl = m0A + mi * 16 + half * 8 + qrow;
#pragma unroll
            for (int ni = 0; ni < 4; ni++) {
                int c = n0A + ni * 8 + qk * 2;
                float v0 = fmaxf(accA[mi][ni][half * 2 + 0] + sm[SB1 + c], 0.f);
                float v1 = fmaxf(accA[mi][ni][half * 2 + 1] + sm[SB1 + c + 1], 0.f);
                *(__half2*)&Th[rl * 264 + c] = __floats2half2_rn(v0, v1);
            }
        }
    }
    __syncthreads();

    const int m0B = (wid & 1) * 32, n0B = (wid >> 1) * 16;
    float accB[2][2][4];
#pragma unroll
    for (int mi = 0; mi < 2; mi++)
#pragma unroll
        for (int ni = 0; ni < 2; ni++)
#pragma unroll
            for (int j = 0; j < 4; j++) accB[mi][ni][j] = 0.f;

    {
        int r = tid >> 5, c = (tid & 31) * 4;
        cp16(smb + (uint32_t)(WOFF + r * 136 + c) * 4u, W2 + r * 128 + c, true);
    }
    CP_COMMIT();

    for (int it = 0; it < 16; it++) {
        if (it + 1 < 16) {
            int r = tid >> 5, c = (tid & 31) * 4;
            cp16(smb + (uint32_t)(WOFF + ((it + 1) & 1) * 2176 + r * 136 + c) * 4u,
                 W2 + (size_t)((it + 1) * 16 + r) * 128 + c, true);
        }
        CP_COMMIT();
        CP_WAIT1();
        __syncthreads();
        const float* bs = sm + WOFF + (it & 1) * 2176;
#pragma unroll
        for (int ks = 0; ks < 2; ks++) {
            int kb = it * 16 + ks * 8;
            uint32_t a[2][4];
#pragma unroll
            for (int mi = 0; mi < 2; mi++) {
                const __half* ap = Th + (m0B + mi * 16 + qrow) * 264 + kb + qk;
                a[mi][0] = __float_as_uint(__half2float(ap[0]));
                a[mi][1] = __float_as_uint(__half2float(ap[8 * 264]));
                a[mi][2] = __float_as_uint(__half2float(ap[4]));
                a[mi][3] = __float_as_uint(__half2float(ap[8 * 264 + 4]));
            }
#pragma unroll
            for (int ni = 0; ni < 2; ni++) {
                uint32_t b[2];
                const float* bp = bs + (ks * 8 + qk) * 136 + n0B + ni * 8 + qrow;
                b[0] = __float_as_uint(bp[0]);
                b[1] = __float_as_uint(bp[4 * 136]);
#pragma unroll
                for (int mi = 0; mi < 2; mi++) MMA_TF32(accB[mi][ni], a[mi], b);
            }
        }
        __syncthreads();
    }

    float s0[2], s1[2], q0[2], q1[2];
#pragma unroll
    for (int ni = 0; ni < 2; ni++) { s0[ni] = 0.f; s1[ni] = 0.f; q0[ni] = 0.f; q1[ni] = 0.f; }
#pragma unroll
    for (int mi = 0; mi < 2; mi++) {
#pragma unroll
        for (int half = 0; half < 2; half++) {
            int rl = m0B + mi * 16 + half * 8 + qrow;
            int r = bm + rl;
            bool rok = r < Nn;
#pragma unroll
            for (int ni = 0; ni < 2; ni++) {
                int gc = n0B + ni * 8 + qk * 2;
                float yv0 = fmaf(sm[YOFF + rl * 132 + gc], sm[SCA + gc], sm[SHA + gc]);
                float yv1 = fmaf(sm[YOFF + rl * 132 + gc + 1], sm[SCA + gc + 1], sm[SHA + gc + 1]);
                float v0 = accB[mi][ni][half * 2 + 0] + b2v[gc] + yv0;
                float v1 = accB[mi][ni][half * 2 + 1] + b2v[gc + 1] + yv1;
                if (rok) {
                    *(__half2*)(C + (size_t)r * ldc + gc) = __floats2half2_rn(v0, v1);
                    s0[ni] += v0; q0[ni] += v0 * v0;
                    s1[ni] += v1; q1[ni] += v1 * v1;
                }
            }
        }
    }
#pragma unroll
    for (int ni = 0; ni < 2; ni++) {
        s0[ni] += __shfl_xor_sync(0xffffffffu, s0[ni], 4);
        s0[ni] += __shfl_xor_sync(0xffffffffu, s0[ni], 8);
        s0[ni] += __shfl_xor_sync(0xffffffffu, s0[ni], 16);
        s1[ni] += __shfl_xor_sync(0xffffffffu, s1[ni], 4);
        s1[ni] += __shfl_xor_sync(0xffffffffu, s1[ni], 8);
        s1[ni] += __shfl_xor_sync(0xffffffffu, s1[ni], 16);
        q0[ni] += __shfl_xor_sync(0xffffffffu, q0[ni], 4);
        q0[ni] += __shfl_xor_sync(0xffffffffu, q0[ni], 8);
        q0[ni] += __shfl_xor_sync(0xffffffffu, q0[ni], 16);
        q1[ni] += __shfl_xor_sync(0xffffffffu, q1[ni], 4);
        q1[ni] += __shfl_xor_sync(0xffffffffu, q1[ni], 8);
        q1[ni] += __shfl_xor_sync(0xffffffffu, q1[ni], 16);
    }
    __syncthreads();
    if (lane < 4) {
        int mg = wid & 1;
#pragma unroll
        for (int ni = 0; ni < 2; ni++) {
            int c = n0B + ni * 8 + lane * 2;
            sm[mg * 128 + c] = s0[ni];
            sm[mg * 128 + c + 1] = s1[ni];
            sm[256 + mg * 128 + c] = q0[ni];
            sm[256 + mg * 128 + c + 1] = q1[ni];
        }
    }
    __syncthreads();
    if (tid < 256) {
        int st = tid >> 7, c = tid & 127;
        float v = sm[st * 256 + c] + sm[st * 256 + 128 + c];
        atomicAdd(bnslot + st * 128 + c, v);
    }
}

// ---------------- GAT aggregate (R16 version) ----------------
__global__ void k_gat(const __half* __restrict__ z,
                      const __half* __restrict__ hres, int ldh,
                      const float* __restrict__ bias, float* __restrict__ y,
                      float* __restrict__ bnslot,
                      const float* __restrict__ slotPrev,
                      const float* __restrict__ gPrev, const float* __restrict__ bPrev) {
    __shared__ float sbn[2][8][128];
    int gw = (blockIdx.x * blockDim.x + threadIdx.x) >> 5;
    int lane = threadIdx.x & 31;
    int wid = threadIdx.x >> 5;
    float4 o = make_float4(0.f, 0.f, 0.f, 0.f);
    if (gw < Nn) {
        int head = lane >> 1;
        int beg = g_rowptr[gw], end = g_rowptr[gw + 1];
        float er_h = g_er[gw * 16 + head];
        const uint2* z2 = (const uint2*)z;

        float den = 0.f;
        float4 acc = make_float4(0.f, 0.f, 0.f, 0.f);
        int i = beg;
        for (; i + 1 < end; i += 2) {
            int sA = g_srcs[i];
            int sB = g_srcs[i + 1];
            float eA = g_el[sA * 16 + head];
            float eB = g_el[sB * 16 + head];
            uint2 rA = z2[(size_t)sA * 32 + lane];
            uint2 rB = z2[(size_t)sB * 32 + lane];
            eA += er_h;
            eB += er_h;
            eA = eA > 0.f ? eA : SLOPE * eA;
            eB = eB > 0.f ? eB : SLOPE * eB;
            float wA = __expf(eA);
            float wB = __expf(eB);
            den += wA + wB;
            float2 a0 = __half22float2(*(__half2*)&rA.x);
            float2 a1 = __half22float2(*(__half2*)&rA.y);
            float2 b0 = __half22float2(*(__half2*)&rB.x);
            float2 b1 = __half22float2(*(__half2*)&rB.y);
            acc.x += wA * a0.x + wB * b0.x;
            acc.y += wA * a0.y + wB * b0.y;
            acc.z += wA * a1.x + wB * b1.x;
            acc.w += wA * a1.y + wB * b1.y;
        }
        if (i < end) {
            int s = g_srcs[i];
            float e = g_el[s * 16 + head] + er_h;
            uint2 r = z2[(size_t)s * 32 + lane];
            e = e > 0.f ? e : SLOPE * e;
            float w = __expf(e);
            den += w;
            float2 a0 = __half22float2(*(__half2*)&r.x);
            float2 a1 = __half22float2(*(__half2*)&r.y);
            acc.x += w * a0.x; acc.y += w * a0.y;
            acc.z += w * a1.x; acc.w += w * a1.y;
        }
        float dinv = den > 0.f ? 1.f / den : 1.f;
        float4 b4 = ((const float4*)bias)[lane];
        uint2 hr = *(const uint2*)(hres + (size_t)gw * ldh + lane * 4);
        float2 h01 = __half22float2(*(__half2*)&hr.x);
        float2 h23 = __half22float2(*(__half2*)&hr.y);
        float4 h4 = make_float4(h01.x, h01.y, h23.x, h23.y);
        if (slotPrev != nullptr) {
            const float invN = 1.f / (float)Nn;
            int c = lane * 4;
#pragma unroll
            for (int j = 0; j < 4; j++) {
                float mu = slotPrev[c + j] * invN;
                float var = slotPrev[128 + c + j] * invN - mu * mu;
                float sc = gPrev[c + j] * rsqrtf(var + EPSBN);
                float sh = bPrev[c + j] - mu * sc;
                float* hp = (&h4.x) + j;
                *hp = fmaf(*hp, sc, sh);
            }
        }
        o.x = acc.x * dinv + b4.x + h4.x;
        o.y = acc.y * dinv + b4.y + h4.y;
        o.z = acc.z * dinv + b4.z + h4.z;
        o.w = acc.w * dinv + b4.w + h4.w;
        ((float4*)y)[(size_t)gw * 32 + lane] = o;
    }
    ((float4*)sbn[0][wid])[lane] = o;
    ((float4*)sbn[1][wid])[lane] = make_float4(o.x * o.x, o.y * o.y, o.z * o.z, o.w * o.w);
    __syncthreads();
    int c = threadIdx.x & 127, st = threadIdx.x >> 7;
    float v = 0.f;
#pragma unroll
    for (int w = 0; w < 8; w++) v += sbn[st][w][c];
    atomicAdd(bnslot + st * 128 + c, v);
}

// ---------------- launch ----------------
extern "C" void kernel_launch(void* const* d_in, const int* in_sizes, int n_in,
                              void* d_out, int out_size) {
    const float* x      = (const float*)d_in[0];
    const int*   src    = (const int*)d_in[1];
    const int*   dst    = (const int*)d_in[2];
    const float* emb_W1 = (const float*)d_in[3];
    const float* emb_b1 = (const float*)d_in[4];
    const float* emb_W2 = (const float*)d_in[5];
    const float* emb_b2 = (const float*)d_in[6];
    const float* emb_Ws = (const float*)d_in[7];
    const float* emb_bs = (const float*)d_in[8];
    const float* gat_W  = (const float*)d_in[9];
    const float* gat_al = (const float*)d_in[10];
    const float* gat_ar = (const float*)d_in[11];
    const float* gat_b  = (const float*)d_in[12];
    const float* bn1_g  = (const float*)d_in[13];
    const float* bn1_b  = (const float*)d_in[14];
    const float* ff_W1  = (const float*)d_in[15];
    const float* ff_b1  = (const float*)d_in[16];
    const float* ff_W2  = (const float*)d_in[17];
    const float* ff_b2  = (const float*)d_in[18];
    const float* bn2_g  = (const float*)d_in[19];
    const float* bn2_b  = (const float*)d_in[20];
    const float* dec_W1 = (const float*)d_in[21];
    const float* dec_b1 = (const float*)d_in[22];
    const float* dec_W2 = (const float*)d_in[23];
    const float* dec_b2 = (const float*)d_in[24];

    void* p;
    float *zb, *yb, *bns, *W, *biasz, *biasd;
    __half *HC, *Wgt, *We2t, *Wdt;
    int* degp;
    cudaGetSymbolAddress(&p, g_HC);    HC = (__half*)p;
    cudaGetSymbolAddress(&p, g_z);     zb = (float*)p;
    cudaGetSymbolAddress(&p, g_y);     yb = (float*)p;
    cudaGetSymbolAddress(&p, g_bnsum); bns = (float*)p;
    cudaGetSymbolAddress(&p, g_deg);   degp = (int*)p;
    cudaGetSymbolAddress(&p, g_W);     W = (float*)p;
    cudaGetSymbolAddress(&p, g_Wgt);   Wgt = (__half*)p;
    cudaGetSymbolAddress(&p, g_We2t);  We2t = (__half*)p;
    cudaGetSymbolAddress(&p, g_Wdt);   Wdt = (__half*)p;
    cudaGetSymbolAddress(&p, g_biasz); biasz = (float*)p;
    cudaGetSymbolAddress(&p, g_biasd); biasd = (float*)p;

    float* Wf1 = W;
    float* Wf2 = W + 131072;

    const int SMEM_H = 12672 * 4;      // 50688 B (hgemm/emb)
    const int SMEM_FF = 21760 * 4;     // 87040 B
    static bool attrDone = false;
    if (!attrDone) {
        cudaFuncSetAttribute(k_emb, cudaFuncAttributeMaxDynamicSharedMemorySize, SMEM_H);
        cudaFuncSetAttribute(k_hgemm<0, 1, 1, 0, 1>, cudaFuncAttributeMaxDynamicSharedMemorySize, SMEM_H);
        cudaFuncSetAttribute(k_hgemm<1, 1, 0, 1, 0>, cudaFuncAttributeMaxDynamicSharedMemorySize, SMEM_H);
        cudaFuncSetAttribute(k_ff, cudaFuncAttributeMaxDynamicSharedMemorySize, SMEM_FF);
        attrDone = true;
    }

    cudaMemsetAsync(bns, 0, 8 * 256 * sizeof(float));
    cudaMemsetAsync(degp, 0, Nn * sizeof(int));
    cudaMemsetAsync(d_out, 0, (size_t)out_size * sizeof(float));

    const int gx = (Nn + 127) / 128;   // 782
    const int gx64 = (Nn + 63) / 64;   // 1563
    dim3 grid1(gx, 1);
    const int warpBlocks = (Nn * 32 + 255) / 256;

    k_cvt_ff<<<(262144 + 255) / 256, 256>>>(ff_W1, ff_W2);
    k_prep128<<<128, 128>>>(emb_W2, nullptr, nullptr, nullptr, We2t, biasd);  // biasd = dummy
    k_prep128<<<128, 128>>>(gat_W, nullptr, nullptr, nullptr, Wgt, biasz);
    // fused embed -> HC block 0 (fp16)   [4th kernel: ncu target]
    k_emb<<<grid1, 512, SMEM_H>>>(x, We2t, emb_W1, emb_b1, emb_Ws, emb_bs, emb_b2, HC, 640);
    // layer-0 z GEMM
    k_hgemm<0, 1, 1, 0, 1><<<grid1, 512, SMEM_H>>>(
        HC, 640, Wgt, 136, biasz, zb, 128, Nn, 128, gat_al, gat_ar);

    k_count<<<(Ee + 255) / 256, 256>>>(dst);
    const int nb = (Nn + 1023) / 1024;
    k_scan1<<<nb, 1024>>>();
    k_scan2<<<1, 128>>>(nb);
    k_finalize<<<(Nn + 255) / 256, 256>>>();
    k_fill<<<(Ee + 255) / 256, 256>>>(dst, src);

    for (int l = 0; l < 4; l++) {
        const __half* h = HC + (size_t)l * 128;
        float* slot1 = bns + (size_t)(2 * l) * 256;
        const float* slotP = (l > 0) ? (bns + (size_t)(2 * (l - 1) + 1) * 256) : nullptr;
        const float* gP = (l > 0) ? (bn2_g + (l - 1) * 128) : nullptr;
        const float* bP = (l > 0) ? (bn2_b + (l - 1) * 128) : nullptr;

        if (l > 0) {
            // fold BN2(prev) affine into gat weights + bias, then z GEMM
            k_prep128<<<128, 128>>>(gat_W + (size_t)l * 16384, slotP, gP, bP,
                                    Wgt + (size_t)l * 128 * 136, biasz + l * 128);
            k_hgemm<0, 1, 1, 0, 1><<<grid1, 512, SMEM_H>>>(
                h, 640, Wgt + (size_t)l * 128 * 136, 136, biasz + l * 128,
                zb, 128, Nn, 128, gat_al + l * 128, gat_ar + l * 128);
        }
        k_gat<<<warpBlocks, 256>>>((const __half*)zb, h, 640, gat_b + l * 128, yb, slot1,
                                   slotP, gP, bP);
        k_ff<<<gx64, 512, SMEM_FF>>>(
            yb, Wf1 + (size_t)l * 32768, ff_b1 + l * 256,
            Wf2 + (size_t)l * 32768, ff_b2 + l * 128,
            HC + (size_t)(l + 1) * 128, 640,
            slot1, bn1_g + l * 128, bn1_b + l * 128,
            bns + (size_t)(2 * l + 1) * 256);
    }

    // decoder: fold concat affine into Wd, then GEMM + fused dot
    k_prepdec<<<128, 640>>>(dec_W1, bn2_g, bn2_b, dec_b1, Wdt, biasd);
    k_hgemm<1, 1, 0, 1, 0><<<grid1, 512, SMEM_H>>>(
        HC, 640, Wdt, 648, biasd, (float*)d_out, 1, Nn, 640, dec_W2, dec_b2);
}